// round 1
// baseline (speedup 1.0000x reference)
#include <cuda_runtime.h>
#include <math.h>

#define B_   2
#define T_   1024
#define C_   1024
#define H_   16
#define HD_  64
#define L_   2
#define E_   8
#define FF_  4096
#define V_   32000
#define NTOK (B_ * T_)
#define CAP  320   // ceil(1.25 * 2048 / 8)

// ---------------- scratch (static device globals; no allocations) ----------------
__device__ float g_x[NTOK * C_];
__device__ float g_ln[NTOK * C_];
__device__ float g_qkv[NTOK * 3 * C_];
__device__ float g_scores[(size_t)B_ * H_ * T_ * T_];   // 134 MB
__device__ float g_attn[NTOK * C_];
__device__ float g_gates[NTOK * E_];
__device__ int   g_top[NTOK * 2];
__device__ int   g_slot[NTOK * 2];
__device__ float g_buf [E_ * CAP * C_];
__device__ float g_hbuf[E_ * CAP * FF_];
__device__ float g_ybuf[E_ * CAP * C_];

// ---------------- helpers ----------------
__device__ __forceinline__ float warp_sum(float v) {
#pragma unroll
    for (int o = 16; o; o >>= 1) v += __shfl_xor_sync(0xffffffffu, v, o);
    return v;
}
__device__ __forceinline__ float warp_max(float v) {
#pragma unroll
    for (int o = 16; o; o >>= 1) v = fmaxf(v, __shfl_xor_sync(0xffffffffu, v, o));
    return v;
}
__device__ __forceinline__ float gelu_exact(float v) {
    return 0.5f * v * (1.0f + erff(v * 0.70710678118654752f));
}

// ---------------- embedding gather ----------------
__global__ void embed_kernel(const int* __restrict__ idx, const float* __restrict__ emb,
                             float* __restrict__ x) {
    int i = blockIdx.x * 256 + threadIdx.x;        // over NTOK*C
    int n = i >> 10, c = i & 1023;
    x[i] = emb[(size_t)idx[n] * C_ + c];
}

// ---------------- layernorm (one block per row) ----------------
__global__ void ln_kernel(const float* __restrict__ x, const float* __restrict__ g,
                          const float* __restrict__ b, float* __restrict__ out) {
    int row = blockIdx.x;
    const float* xr = x + (size_t)row * C_;
    float s = 0.f, s2 = 0.f;
    for (int c = threadIdx.x; c < C_; c += 256) { float v = xr[c]; s += v; s2 += v * v; }
    __shared__ float sh1[8], sh2[8], shm[2];
    int lane = threadIdx.x & 31, w = threadIdx.x >> 5;
    s = warp_sum(s); s2 = warp_sum(s2);
    if (!lane) { sh1[w] = s; sh2[w] = s2; }
    __syncthreads();
    if (threadIdx.x == 0) {
        float S = 0.f, S2 = 0.f;
        for (int i = 0; i < 8; i++) { S += sh1[i]; S2 += sh2[i]; }
        float mean = S * (1.0f / C_);
        float var  = S2 * (1.0f / C_) - mean * mean;
        shm[0] = mean; shm[1] = rsqrtf(var + 1e-5f);
    }
    __syncthreads();
    float mean = shm[0], inv = shm[1];
    float* orow = out + (size_t)row * C_;
    for (int c = threadIdx.x; c < C_; c += 256)
        orow[c] = (xr[c] - mean) * inv * g[c] + b[c];
}

// ---------------- generic tiled GEMM: C[M,N] = A[M,K] @ B[K,N]; batched over z ----
// epilogue: 0=store, 1=add into C (residual), 2=bias+gelu, 3=bias
__global__ void gemm_kernel(const float* __restrict__ A, const float* __restrict__ B,
                            float* __restrict__ C, const float* __restrict__ bias,
                            int N, int K,
                            long sA, long sB, long sC, long sBias, int epilogue) {
    int z = blockIdx.z;
    A += (long)z * sA; B += (long)z * sB; C += (long)z * sC;
    const float* bp = bias ? bias + (long)z * sBias : nullptr;
    __shared__ float As[16][68];
    __shared__ float Bs[16][68];
    int tid = threadIdx.x;
    int tx = tid & 15, ty = tid >> 4;
    int m0 = blockIdx.y * 64, n0 = blockIdx.x * 64;
    const float* Ab = A + (size_t)m0 * K;
    const float* Bb = B + n0;
    float acc[4][4] = {};
    for (int k0 = 0; k0 < K; k0 += 16) {
#pragma unroll
        for (int r = 0; r < 4; r++) {
            int idx = tid + r * 256;
            As[idx & 15][idx >> 4] = Ab[(size_t)(idx >> 4) * K + k0 + (idx & 15)];
        }
#pragma unroll
        for (int r = 0; r < 4; r++) {
            int idx = tid + r * 256;
            Bs[idx >> 6][idx & 63] = Bb[(size_t)(k0 + (idx >> 6)) * N + (idx & 63)];
        }
        __syncthreads();
#pragma unroll
        for (int kk = 0; kk < 16; kk++) {
            float a[4], bb[4];
#pragma unroll
            for (int i = 0; i < 4; i++) a[i]  = As[kk][ty * 4 + i];
#pragma unroll
            for (int j = 0; j < 4; j++) bb[j] = Bs[kk][tx * 4 + j];
#pragma unroll
            for (int i = 0; i < 4; i++)
#pragma unroll
                for (int j = 0; j < 4; j++) acc[i][j] += a[i] * bb[j];
        }
        __syncthreads();
    }
#pragma unroll
    for (int i = 0; i < 4; i++) {
        float* crow = C + (size_t)(m0 + ty * 4 + i) * N + n0;
#pragma unroll
        for (int j = 0; j < 4; j++) {
            int nn = tx * 4 + j;
            float v = acc[i][j];
            if (epilogue == 2)      v = gelu_exact(v + bp[n0 + nn]);
            else if (epilogue == 3) v = v + bp[n0 + nn];
            if (epilogue == 1) crow[nn] += v; else crow[nn] = v;
        }
    }
}

// ---------------- RoPE in-place on q,k of qkv ----------------
__global__ void rope_kernel(float* __restrict__ qkv) {
    int i = blockIdx.x * 256 + threadIdx.x;          // NTOK*H*(HD/2)
    if (i >= NTOK * H_ * (HD_ / 2)) return;
    int j = i & 31;
    int h = (i >> 5) & 15;
    int n = i >> 9;
    int t = n & (T_ - 1);
    float e = (float)(2 * j) / (float)HD_;
    float invf = 1.0f / powf(10000.0f, e);
    float ang = (float)t * invf;
    float s = sinf(ang), c = cosf(ang);
    float* base = qkv + (size_t)n * (3 * C_) + h * (3 * HD_);
    float q1 = base[j],      q2 = base[j + 32];
    base[j]      = q1 * c - q2 * s;
    base[j + 32] = q1 * s + q2 * c;
    float k1 = base[64 + j], k2 = base[64 + j + 32];
    base[64 + j]      = k1 * c - k2 * s;
    base[64 + j + 32] = k1 * s + k2 * c;
}

// ---------------- causal scores: S[bh,q,k] = q.k * 0.125 or -FLT_MAX ----------------
__global__ void attn_scores_kernel(const float* __restrict__ qkv, float* __restrict__ sc) {
    int bh = blockIdx.z; int b = bh >> 4, h = bh & 15;
    int q0 = blockIdx.y * 16, k0 = blockIdx.x * 16;
    int tx = threadIdx.x, ty = threadIdx.y;
    float* S = sc + (size_t)bh * T_ * T_;
    const float NEG = -3.4028234663852886e38f;
    if (k0 > q0 + 15) { S[(size_t)(q0 + ty) * T_ + k0 + tx] = NEG; return; }
    __shared__ float Qs[16][65], Ks[16][65];
    int tid = ty * 16 + tx;
    const float* qb = qkv + (size_t)(b * T_ + q0) * (3 * C_) + h * (3 * HD_);
    const float* kb = qkv + (size_t)(b * T_ + k0) * (3 * C_) + h * (3 * HD_) + HD_;
#pragma unroll
    for (int r = 0; r < 4; r++) {
        int idx = tid + r * 256;
        int row = idx >> 6, col = idx & 63;
        Qs[row][col] = qb[(size_t)row * (3 * C_) + col];
        Ks[row][col] = kb[(size_t)row * (3 * C_) + col];
    }
    __syncthreads();
    float acc = 0.f;
#pragma unroll
    for (int d = 0; d < 64; d++) acc += Qs[ty][d] * Ks[tx][d];
    int q = q0 + ty, k = k0 + tx;
    S[(size_t)q * T_ + k] = (k <= q) ? acc * 0.125f : NEG;
}

// ---------------- row softmax over T ----------------
__global__ void softmax_kernel(float* __restrict__ sc) {
    size_t row = blockIdx.x;
    float* r = sc + row * T_;
    __shared__ float sh[8], shv[1];
    int lane = threadIdx.x & 31, w = threadIdx.x >> 5;
    float mx = -INFINITY;
    for (int k = threadIdx.x; k < T_; k += 256) mx = fmaxf(mx, r[k]);
    mx = warp_max(mx);
    if (!lane) sh[w] = mx;
    __syncthreads();
    if (threadIdx.x == 0) {
        float m = sh[0];
        for (int i = 1; i < 8; i++) m = fmaxf(m, sh[i]);
        shv[0] = m;
    }
    __syncthreads();
    float M = shv[0];
    float s = 0.f;
    for (int k = threadIdx.x; k < T_; k += 256) { float e = expf(r[k] - M); r[k] = e; s += e; }
    s = warp_sum(s);
    if (!lane) sh[w] = s;
    __syncthreads();
    if (threadIdx.x == 0) {
        float S = 0.f;
        for (int i = 0; i < 8; i++) S += sh[i];
        shv[0] = 1.0f / S;
    }
    __syncthreads();
    float inv = shv[0];
    for (int k = threadIdx.x; k < T_; k += 256) r[k] *= inv;
}

// ---------------- P @ V (per b,h; strided V inside qkv) ----------------
__global__ void attn_pv_kernel(const float* __restrict__ sc, const float* __restrict__ qkv,
                               float* __restrict__ out) {
    int z = blockIdx.z; int b = z >> 4, h = z & 15;
    const float* A  = sc + (size_t)z * T_ * T_;
    const float* Bp = qkv + (size_t)b * T_ * (3 * C_) + h * (3 * HD_) + 2 * HD_;  // ldb=3072
    float* Cp = out + (size_t)b * T_ * C_ + h * HD_;                               // ldc=1024
    __shared__ float As[16][68];
    __shared__ float Bs[16][68];
    int tid = threadIdx.x;
    int tx = tid & 15, ty = tid >> 4;
    int m0 = blockIdx.y * 64;
    float acc[4][4] = {};
    for (int k0 = 0; k0 < T_; k0 += 16) {
#pragma unroll
        for (int r = 0; r < 4; r++) {
            int idx = tid + r * 256;
            As[idx & 15][idx >> 4] = A[(size_t)(m0 + (idx >> 4)) * T_ + k0 + (idx & 15)];
        }
#pragma unroll
        for (int r = 0; r < 4; r++) {
            int idx = tid + r * 256;
            Bs[idx >> 6][idx & 63] = Bp[(size_t)(k0 + (idx >> 6)) * (3 * C_) + (idx & 63)];
        }
        __syncthreads();
#pragma unroll
        for (int kk = 0; kk < 16; kk++) {
            float a[4], bb[4];
#pragma unroll
            for (int i = 0; i < 4; i++) a[i]  = As[kk][ty * 4 + i];
#pragma unroll
            for (int j = 0; j < 4; j++) bb[j] = Bs[kk][tx * 4 + j];
#pragma unroll
            for (int i = 0; i < 4; i++)
#pragma unroll
                for (int j = 0; j < 4; j++) acc[i][j] += a[i] * bb[j];
        }
        __syncthreads();
    }
#pragma unroll
    for (int i = 0; i < 4; i++)
#pragma unroll
        for (int j = 0; j < 4; j++)
            Cp[(size_t)(m0 + ty * 4 + i) * C_ + tx * 4 + j] = acc[i][j];
}

// ---------------- gating: softmax(x @ gate_w) + top2 ----------------
__global__ void gate_kernel(const float* __restrict__ x, const float* __restrict__ gw,
                            float* __restrict__ gates, int* __restrict__ top) {
    int n = blockIdx.x;
    int lane = threadIdx.x & 31, w = threadIdx.x >> 5;   // warp w -> expert w
    const float* xr = x + (size_t)n * C_;
    float acc = 0.f;
    for (int c = lane; c < C_; c += 32) acc += xr[c] * gw[(size_t)c * E_ + w];
    acc = warp_sum(acc);
    __shared__ float sl[E_];
    if (!lane) sl[w] = acc;
    __syncthreads();
    if (threadIdx.x == 0) {
        float p[E_];
        float m = sl[0];
        for (int e = 1; e < E_; e++) m = fmaxf(m, sl[e]);
        float s = 0.f;
        for (int e = 0; e < E_; e++) { p[e] = expf(sl[e] - m); s += p[e]; }
        float inv = 1.0f / s;
        for (int e = 0; e < E_; e++) { p[e] *= inv; gates[(size_t)n * E_ + e] = p[e]; }
        int i0 = 0;
        for (int e = 1; e < E_; e++) if (p[e] > p[i0]) i0 = e;
        int i1 = -1;
        for (int e = 0; e < E_; e++) {
            if (e == i0) continue;
            if (i1 < 0 || p[e] > p[i1]) i1 = e;
        }
        top[2 * n] = i0; top[2 * n + 1] = i1;
    }
}

// ---------------- routing: per-expert token-order cumsum with capacity ----------------
__global__ void route_kernel(const int* __restrict__ top, int* __restrict__ slot) {
    int e = threadIdx.x;
    if (e >= E_) return;
    int cnt = 0;
    for (int n = 0; n < NTOK; n++) {
        if (top[2 * n] == e)     { slot[2 * n]     = (cnt < CAP) ? cnt : -1; cnt++; }
        if (top[2 * n + 1] == e) { slot[2 * n + 1] = (cnt < CAP) ? cnt : -1; cnt++; }
    }
}

// ---------------- scatter kept tokens into expert buffers ----------------
__global__ void scatter_kernel(const float* __restrict__ ln, const int* __restrict__ top,
                               const int* __restrict__ slot, float* __restrict__ buf) {
    int n = blockIdx.x;
    const float4* src = (const float4*)(ln + (size_t)n * C_);
#pragma unroll
    for (int kk = 0; kk < 2; kk++) {
        int s = slot[2 * n + kk];
        if (s < 0) continue;
        int e = top[2 * n + kk];
        float4* dst = (float4*)(buf + ((size_t)e * CAP + s) * C_);
        for (int i = threadIdx.x; i < C_ / 4; i += 256) dst[i] = src[i];
    }
}

// ---------------- weighted combine + residual ----------------
__global__ void combine_kernel(const float* __restrict__ y, const float* __restrict__ gates,
                               const int* __restrict__ top, const int* __restrict__ slot,
                               float* __restrict__ x) {
    int n = blockIdx.x;
    int e0 = top[2 * n], e1 = top[2 * n + 1];
    int s0 = slot[2 * n], s1 = slot[2 * n + 1];
    float w0 = (s0 >= 0) ? gates[(size_t)n * E_ + e0] : 0.f;
    float w1 = (s1 >= 0) ? gates[(size_t)n * E_ + e1] : 0.f;
    const float* y0 = y + ((size_t)e0 * CAP + (s0 >= 0 ? s0 : 0)) * C_;
    const float* y1 = y + ((size_t)e1 * CAP + (s1 >= 0 ? s1 : 0)) * C_;
    float* xr = x + (size_t)n * C_;
    for (int c = threadIdx.x; c < C_; c += 256)
        xr[c] += w0 * y0[c] + w1 * y1[c];
}

// ---------------- launch ----------------
extern "C" void kernel_launch(void* const* d_in, const int* in_sizes, int n_in,
                              void* d_out, int out_size) {
    const int*   idx     = (const int*)  d_in[0];
    const float* tok_emb = (const float*)d_in[1];
    const float* ln1_g   = (const float*)d_in[2];
    const float* ln1_b   = (const float*)d_in[3];
    const float* qkv_w   = (const float*)d_in[4];
    const float* proj_w  = (const float*)d_in[5];
    const float* ln2_g   = (const float*)d_in[6];
    const float* ln2_b   = (const float*)d_in[7];
    const float* gate_w  = (const float*)d_in[8];
    const float* w1      = (const float*)d_in[9];
    const float* b1      = (const float*)d_in[10];
    const float* w2      = (const float*)d_in[11];
    const float* b2      = (const float*)d_in[12];
    const float* lnf_g   = (const float*)d_in[13];
    const float* lnf_b   = (const float*)d_in[14];
    const float* lm_head = (const float*)d_in[15];
    float* out = (float*)d_out;

    float *x, *ln, *qkv, *sc, *attn, *gates, *buf, *hbuf, *ybuf;
    int *top, *slot;
    cudaGetSymbolAddress((void**)&x,     g_x);
    cudaGetSymbolAddress((void**)&ln,    g_ln);
    cudaGetSymbolAddress((void**)&qkv,   g_qkv);
    cudaGetSymbolAddress((void**)&sc,    g_scores);
    cudaGetSymbolAddress((void**)&attn,  g_attn);
    cudaGetSymbolAddress((void**)&gates, g_gates);
    cudaGetSymbolAddress((void**)&top,   g_top);
    cudaGetSymbolAddress((void**)&slot,  g_slot);
    cudaGetSymbolAddress((void**)&buf,   g_buf);
    cudaGetSymbolAddress((void**)&hbuf,  g_hbuf);
    cudaGetSymbolAddress((void**)&ybuf,  g_ybuf);

    embed_kernel<<<NTOK * C_ / 256, 256>>>(idx, tok_emb, x);

    for (int l = 0; l < L_; l++) {
        // --- attention ---
        ln_kernel<<<NTOK, 256>>>(x, ln1_g + (size_t)l * C_, ln1_b + (size_t)l * C_, ln);
        gemm_kernel<<<dim3(3 * C_ / 64, NTOK / 64, 1), 256>>>(
            ln, qkv_w + (size_t)l * C_ * 3 * C_, qkv, nullptr, 3 * C_, C_, 0, 0, 0, 0, 0);
        rope_kernel<<<(NTOK * H_ * (HD_ / 2) + 255) / 256, 256>>>(qkv);
        attn_scores_kernel<<<dim3(T_ / 16, T_ / 16, B_ * H_), dim3(16, 16)>>>(qkv, sc);
        softmax_kernel<<<B_ * H_ * T_, 256>>>(sc);
        attn_pv_kernel<<<dim3(1, T_ / 64, B_ * H_), 256>>>(sc, qkv, attn);
        gemm_kernel<<<dim3(C_ / 64, NTOK / 64, 1), 256>>>(
            attn, proj_w + (size_t)l * C_ * C_, x, nullptr, C_, C_, 0, 0, 0, 0, 1);  // += residual

        // --- MoE ---
        ln_kernel<<<NTOK, 256>>>(x, ln2_g + (size_t)l * C_, ln2_b + (size_t)l * C_, ln);
        gate_kernel<<<NTOK, 256>>>(ln, gate_w + (size_t)l * C_ * E_, gates, top);
        route_kernel<<<1, 32>>>(top, slot);
        scatter_kernel<<<NTOK, 256>>>(ln, top, slot, buf);
        gemm_kernel<<<dim3(FF_ / 64, CAP / 64, E_), 256>>>(
            buf, w1 + (size_t)l * E_ * C_ * FF_, hbuf, b1 + (size_t)l * E_ * FF_,
            FF_, C_, (long)CAP * C_, (long)C_ * FF_, (long)CAP * FF_, (long)FF_, 2);  // gelu
        gemm_kernel<<<dim3(C_ / 64, CAP / 64, E_), 256>>>(
            hbuf, w2 + (size_t)l * E_ * FF_ * C_, ybuf, b2 + (size_t)l * E_ * C_,
            C_, FF_, (long)CAP * FF_, (long)FF_ * C_, (long)CAP * C_, (long)C_, 3);   // bias
        combine_kernel<<<NTOK, 256>>>(ybuf, gates, top, slot, x);
    }

    ln_kernel<<<NTOK, 256>>>(x, lnf_g, lnf_b, ln);
    gemm_kernel<<<dim3(V_ / 64, NTOK / 64, 1), 256>>>(
        ln, lm_head, out, nullptr, V_, C_, 0, 0, 0, 0, 0);
}

// round 4
// speedup vs baseline: 1.3233x; 1.3233x over previous
#include <cuda_runtime.h>
#include <math.h>
#include <stdint.h>

#define B_   2
#define T_   1024
#define C_   1024
#define H_   16
#define HD_  64
#define L_   2
#define E_   8
#define FF_  4096
#define V_   32000
#define NTOK (B_ * T_)
#define CAP  320   // ceil(1.25 * 2048 / 8)
#define CAPP 384   // padded to multiple of 128

// ---------------- scratch (static device globals; no allocations) ----------------
__device__ float g_x[NTOK * C_];
__device__ float g_ln[NTOK * C_];
__device__ float g_qkv[NTOK * 3 * C_];
__device__ float g_scores[(size_t)B_ * H_ * T_ * T_];
__device__ float g_attn[NTOK * C_];
__device__ float g_gates[NTOK * E_];
__device__ int   g_top[NTOK * 2];
__device__ int   g_slot[NTOK * 2];
__device__ float g_buf [E_ * CAPP * C_];
__device__ float g_hbuf[E_ * CAPP * FF_];
__device__ float g_ybuf[E_ * CAPP * C_];

// ---------------- helpers ----------------
__device__ __forceinline__ float warp_sum(float v) {
#pragma unroll
    for (int o = 16; o; o >>= 1) v += __shfl_xor_sync(0xffffffffu, v, o);
    return v;
}
__device__ __forceinline__ float warp_max(float v) {
#pragma unroll
    for (int o = 16; o; o >>= 1) v = fmaxf(v, __shfl_xor_sync(0xffffffffu, v, o));
    return v;
}
__device__ __forceinline__ float gelu_exact(float v) {
    return 0.5f * v * (1.0f + erff(v * 0.70710678118654752f));
}
__device__ __forceinline__ float to_tf32(float v) {
    float o; asm("cvt.rna.tf32.f32 %0, %1;" : "=f"(o) : "f"(v)); return o;
}

// ======== 3xTF32 tensor-core GEMM via mma.sync (base-PTX, compute_103-safe) ========
// C[Mv,N] = A[M,K] @ B[K,N], batched over blockIdx.z.
// 128x128 tile per CTA, 256 threads (8 warps as 2x4), K-chunks of 32.
// Raw fp32 in smem; hi/lo tf32 split at fragment load; 3 mma passes (hh, h*lo, lo*h).
// ep: 0=store, 1=add into C (residual), 2=bias+gelu, 3=bias
#define LDA_ 36    // banks (4r+c) -> conflict-free A frag reads
#define LDB_ 136   // banks (8k+n) -> conflict-free B frag reads
#define MM_SMEM ((128 * LDA_ + 32 * LDB_) * 4)

__global__ void __launch_bounds__(256, 2)
mm_mma_kernel(const float* __restrict__ A, const float* __restrict__ B,
              float* __restrict__ C, const float* __restrict__ bias,
              int Mv, int N, int K,
              long sA, long sB, long sC, long sBias, int ep)
{
    extern __shared__ float sm[];
    float* smA = sm;                    // [128][LDA_] raw fp32
    float* smB = sm + 128 * LDA_;       // [32][LDB_]  raw fp32
    int tid = threadIdx.x, lane = tid & 31, wid = tid >> 5;
    int wm = wid & 1, wn = wid >> 1;    // warp tile: rows wm*64..+63, cols wn*32..+31
    int z = blockIdx.z;
    A += (long)z * sA; B += (long)z * sB; C += (long)z * sC;
    const float* bp = bias ? bias + (long)z * sBias : nullptr;
    int m0 = blockIdx.x * 128, n0 = blockIdx.y * 128;

    float acc[4][4][4];
#pragma unroll
    for (int i = 0; i < 4; i++)
#pragma unroll
        for (int j = 0; j < 4; j++)
#pragma unroll
            for (int k = 0; k < 4; k++) acc[i][j][k] = 0.f;

    for (int k0 = 0; k0 < K; k0 += 32) {
        if (k0) __syncthreads();
        // A chunk: 128 rows x 32 k (raw)
#pragma unroll
        for (int r = 0; r < 4; r++) {
            int idx = tid + r * 256;
            int m = idx >> 3, f4 = idx & 7;
            *(float4*)(smA + m * LDA_ + f4 * 4) =
                *(const float4*)(A + (size_t)(m0 + m) * K + k0 + f4 * 4);
        }
        // B chunk: 32 k-rows x 128 n (raw)
#pragma unroll
        for (int r = 0; r < 4; r++) {
            int idx = tid + r * 256;
            int k = idx >> 5, f4 = idx & 31;
            *(float4*)(smB + k * LDB_ + f4 * 4) =
                *(const float4*)(B + (size_t)(k0 + k) * N + n0 + f4 * 4);
        }
        __syncthreads();
        int r_lo = lane >> 2, c_lo = lane & 3;
#pragma unroll
        for (int ks = 0; ks < 4; ks++) {
            float ar[4][4], br[4][2];
            uint32_t ah[4][4], bh[4][2];
#pragma unroll
            for (int mt = 0; mt < 4; mt++) {
                const float* ab = smA + (wm * 64 + mt * 16 + r_lo) * LDA_ + ks * 8 + c_lo;
                ar[mt][0] = ab[0];
                ar[mt][1] = ab[8 * LDA_];
                ar[mt][2] = ab[4];
                ar[mt][3] = ab[8 * LDA_ + 4];
#pragma unroll
                for (int q = 0; q < 4; q++) ah[mt][q] = __float_as_uint(to_tf32(ar[mt][q]));
            }
#pragma unroll
            for (int nt = 0; nt < 4; nt++) {
                const float* bb = smB + (ks * 8 + c_lo) * LDB_ + wn * 32 + nt * 8 + r_lo;
                br[nt][0] = bb[0];
                br[nt][1] = bb[4 * LDB_];
                bh[nt][0] = __float_as_uint(to_tf32(br[nt][0]));
                bh[nt][1] = __float_as_uint(to_tf32(br[nt][1]));
            }
            // pass 1: hi x hi
#pragma unroll
            for (int mt = 0; mt < 4; mt++)
#pragma unroll
                for (int nt = 0; nt < 4; nt++)
                    asm volatile(
                        "mma.sync.aligned.m16n8k8.row.col.f32.tf32.tf32.f32 "
                        "{%0,%1,%2,%3}, {%4,%5,%6,%7}, {%8,%9}, {%0,%1,%2,%3};"
                        : "+f"(acc[mt][nt][0]), "+f"(acc[mt][nt][1]),
                          "+f"(acc[mt][nt][2]), "+f"(acc[mt][nt][3])
                        : "r"(ah[mt][0]), "r"(ah[mt][1]), "r"(ah[mt][2]), "r"(ah[mt][3]),
                          "r"(bh[nt][0]), "r"(bh[nt][1]));
            // b_lo into br; pass 2: hi x b_lo
#pragma unroll
            for (int nt = 0; nt < 4; nt++) {
                br[nt][0] = to_tf32(br[nt][0] - __uint_as_float(bh[nt][0]));
                br[nt][1] = to_tf32(br[nt][1] - __uint_as_float(bh[nt][1]));
            }
#pragma unroll
            for (int mt = 0; mt < 4; mt++)
#pragma unroll
                for (int nt = 0; nt < 4; nt++)
                    asm volatile(
                        "mma.sync.aligned.m16n8k8.row.col.f32.tf32.tf32.f32 "
                        "{%0,%1,%2,%3}, {%4,%5,%6,%7}, {%8,%9}, {%0,%1,%2,%3};"
                        : "+f"(acc[mt][nt][0]), "+f"(acc[mt][nt][1]),
                          "+f"(acc[mt][nt][2]), "+f"(acc[mt][nt][3])
                        : "r"(ah[mt][0]), "r"(ah[mt][1]), "r"(ah[mt][2]), "r"(ah[mt][3]),
                          "r"(__float_as_uint(br[nt][0])), "r"(__float_as_uint(br[nt][1])));
            // a_lo into ar; pass 3: a_lo x hi
#pragma unroll
            for (int mt = 0; mt < 4; mt++)
#pragma unroll
                for (int q = 0; q < 4; q++)
                    ar[mt][q] = to_tf32(ar[mt][q] - __uint_as_float(ah[mt][q]));
#pragma unroll
            for (int mt = 0; mt < 4; mt++)
#pragma unroll
                for (int nt = 0; nt < 4; nt++)
                    asm volatile(
                        "mma.sync.aligned.m16n8k8.row.col.f32.tf32.tf32.f32 "
                        "{%0,%1,%2,%3}, {%4,%5,%6,%7}, {%8,%9}, {%0,%1,%2,%3};"
                        : "+f"(acc[mt][nt][0]), "+f"(acc[mt][nt][1]),
                          "+f"(acc[mt][nt][2]), "+f"(acc[mt][nt][3])
                        : "r"(__float_as_uint(ar[mt][0])), "r"(__float_as_uint(ar[mt][1])),
                          "r"(__float_as_uint(ar[mt][2])), "r"(__float_as_uint(ar[mt][3])),
                          "r"(bh[nt][0]), "r"(bh[nt][1]));
        }
    }
    // epilogue
    int rbase = m0 + wm * 64 + (lane >> 2);
    int cbase = n0 + wn * 32 + (lane & 3) * 2;
#pragma unroll
    for (int mt = 0; mt < 4; mt++) {
#pragma unroll
        for (int half = 0; half < 2; half++) {
            int row = rbase + mt * 16 + half * 8;
            if (row >= Mv) continue;
#pragma unroll
            for (int nt = 0; nt < 4; nt++) {
                int col = cbase + nt * 8;
                float x0 = acc[mt][nt][half * 2 + 0];
                float x1 = acc[mt][nt][half * 2 + 1];
                if (ep == 2)      { x0 = gelu_exact(x0 + bp[col]); x1 = gelu_exact(x1 + bp[col + 1]); }
                else if (ep == 3) { x0 += bp[col]; x1 += bp[col + 1]; }
                float* cp = C + (size_t)row * N + col;
                if (ep == 1) { x0 += cp[0]; x1 += cp[1]; }
                float2 o; o.x = x0; o.y = x1;
                *(float2*)cp = o;
            }
        }
    }
}

// ---------------- embedding gather ----------------
__global__ void embed_kernel(const int* __restrict__ idx, const float* __restrict__ emb,
                             float* __restrict__ x) {
    int i = blockIdx.x * 256 + threadIdx.x;
    int n = i >> 10, c = i & 1023;
    x[i] = emb[(size_t)idx[n] * C_ + c];
}

// ---------------- layernorm ----------------
__global__ void ln_kernel(const float* __restrict__ x, const float* __restrict__ g,
                          const float* __restrict__ b, float* __restrict__ out) {
    int row = blockIdx.x;
    const float* xr = x + (size_t)row * C_;
    float s = 0.f, s2 = 0.f;
    for (int c = threadIdx.x; c < C_; c += 256) { float v = xr[c]; s += v; s2 += v * v; }
    __shared__ float sh1[8], sh2[8], shm[2];
    int lane = threadIdx.x & 31, w = threadIdx.x >> 5;
    s = warp_sum(s); s2 = warp_sum(s2);
    if (!lane) { sh1[w] = s; sh2[w] = s2; }
    __syncthreads();
    if (threadIdx.x == 0) {
        float S = 0.f, S2 = 0.f;
        for (int i = 0; i < 8; i++) { S += sh1[i]; S2 += sh2[i]; }
        float mean = S * (1.0f / C_);
        float var  = S2 * (1.0f / C_) - mean * mean;
        shm[0] = mean; shm[1] = rsqrtf(var + 1e-5f);
    }
    __syncthreads();
    float mean = shm[0], inv = shm[1];
    float* orow = out + (size_t)row * C_;
    for (int c = threadIdx.x; c < C_; c += 256)
        orow[c] = (xr[c] - mean) * inv * g[c] + b[c];
}

// ---------------- RoPE ----------------
__global__ void rope_kernel(float* __restrict__ qkv) {
    int i = blockIdx.x * 256 + threadIdx.x;
    if (i >= NTOK * H_ * (HD_ / 2)) return;
    int j = i & 31;
    int h = (i >> 5) & 15;
    int n = i >> 9;
    int t = n & (T_ - 1);
    float e = (float)(2 * j) / (float)HD_;
    float invf = 1.0f / powf(10000.0f, e);
    float ang = (float)t * invf;
    float s = sinf(ang), c = cosf(ang);
    float* base = qkv + (size_t)n * (3 * C_) + h * (3 * HD_);
    float q1 = base[j],      q2 = base[j + 32];
    base[j]      = q1 * c - q2 * s;
    base[j + 32] = q1 * s + q2 * c;
    float k1 = base[64 + j], k2 = base[64 + j + 32];
    base[64 + j]      = k1 * c - k2 * s;
    base[64 + j + 32] = k1 * s + k2 * c;
}

// ---------------- causal scores ----------------
__global__ void attn_scores_kernel(const float* __restrict__ qkv, float* __restrict__ sc) {
    int bh = blockIdx.z; int b = bh >> 4, h = bh & 15;
    int q0 = blockIdx.y * 16, k0 = blockIdx.x * 16;
    int tx = threadIdx.x, ty = threadIdx.y;
    float* S = sc + (size_t)bh * T_ * T_;
    const float NEG = -3.4028234663852886e38f;
    if (k0 > q0 + 15) { S[(size_t)(q0 + ty) * T_ + k0 + tx] = NEG; return; }
    __shared__ float Qs[16][65], Ks[16][65];
    int tid = ty * 16 + tx;
    const float* qb = qkv + (size_t)(b * T_ + q0) * (3 * C_) + h * (3 * HD_);
    const float* kb = qkv + (size_t)(b * T_ + k0) * (3 * C_) + h * (3 * HD_) + HD_;
#pragma unroll
    for (int r = 0; r < 4; r++) {
        int idx = tid + r * 256;
        int row = idx >> 6, col = idx & 63;
        Qs[row][col] = qb[(size_t)row * (3 * C_) + col];
        Ks[row][col] = kb[(size_t)row * (3 * C_) + col];
    }
    __syncthreads();
    float acc = 0.f;
#pragma unroll
    for (int d = 0; d < 64; d++) acc += Qs[ty][d] * Ks[tx][d];
    int q = q0 + ty, k = k0 + tx;
    S[(size_t)q * T_ + k] = (k <= q) ? acc * 0.125f : NEG;
}

// ---------------- row softmax ----------------
__global__ void softmax_kernel(float* __restrict__ sc) {
    size_t row = blockIdx.x;
    float* r = sc + row * T_;
    __shared__ float sh[8], shv[1];
    int lane = threadIdx.x & 31, w = threadIdx.x >> 5;
    float mx = -INFINITY;
    for (int k = threadIdx.x; k < T_; k += 256) mx = fmaxf(mx, r[k]);
    mx = warp_max(mx);
    if (!lane) sh[w] = mx;
    __syncthreads();
    if (threadIdx.x == 0) {
        float m = sh[0];
        for (int i = 1; i < 8; i++) m = fmaxf(m, sh[i]);
        shv[0] = m;
    }
    __syncthreads();
    float M = shv[0];
    float s = 0.f;
    for (int k = threadIdx.x; k < T_; k += 256) { float e = expf(r[k] - M); r[k] = e; s += e; }
    s = warp_sum(s);
    if (!lane) sh[w] = s;
    __syncthreads();
    if (threadIdx.x == 0) {
        float S = 0.f;
        for (int i = 0; i < 8; i++) S += sh[i];
        shv[0] = 1.0f / S;
    }
    __syncthreads();
    float inv = shv[0];
    for (int k = threadIdx.x; k < T_; k += 256) r[k] *= inv;
}

// ---------------- P @ V ----------------
__global__ void attn_pv_kernel(const float* __restrict__ sc, const float* __restrict__ qkv,
                               float* __restrict__ out) {
    int z = blockIdx.z; int b = z >> 4, h = z & 15;
    const float* A  = sc + (size_t)z * T_ * T_;
    const float* Bp = qkv + (size_t)b * T_ * (3 * C_) + h * (3 * HD_) + 2 * HD_;
    float* Cp = out + (size_t)b * T_ * C_ + h * HD_;
    __shared__ float As[16][68];
    __shared__ float Bs[16][68];
    int tid = threadIdx.x;
    int tx = tid & 15, ty = tid >> 4;
    int m0 = blockIdx.y * 64;
    float acc[4][4] = {};
    for (int k0 = 0; k0 < T_; k0 += 16) {
#pragma unroll
        for (int r = 0; r < 4; r++) {
            int idx = tid + r * 256;
            As[idx & 15][idx >> 4] = A[(size_t)(m0 + (idx >> 4)) * T_ + k0 + (idx & 15)];
        }
#pragma unroll
        for (int r = 0; r < 4; r++) {
            int idx = tid + r * 256;
            Bs[idx >> 6][idx & 63] = Bp[(size_t)(k0 + (idx >> 6)) * (3 * C_) + (idx & 63)];
        }
        __syncthreads();
#pragma unroll
        for (int kk = 0; kk < 16; kk++) {
            float a[4], bb[4];
#pragma unroll
            for (int i = 0; i < 4; i++) a[i]  = As[kk][ty * 4 + i];
#pragma unroll
            for (int j = 0; j < 4; j++) bb[j] = Bs[kk][tx * 4 + j];
#pragma unroll
            for (int i = 0; i < 4; i++)
#pragma unroll
                for (int j = 0; j < 4; j++) acc[i][j] += a[i] * bb[j];
        }
        __syncthreads();
    }
#pragma unroll
    for (int i = 0; i < 4; i++)
#pragma unroll
        for (int j = 0; j < 4; j++)
            Cp[(size_t)(m0 + ty * 4 + i) * C_ + tx * 4 + j] = acc[i][j];
}

// ---------------- gating ----------------
__global__ void gate_kernel(const float* __restrict__ x, const float* __restrict__ gw,
                            float* __restrict__ gates, int* __restrict__ top) {
    int n = blockIdx.x;
    int lane = threadIdx.x & 31, w = threadIdx.x >> 5;
    const float* xr = x + (size_t)n * C_;
    float acc = 0.f;
    for (int c = lane; c < C_; c += 32) acc += xr[c] * gw[(size_t)c * E_ + w];
    acc = warp_sum(acc);
    __shared__ float sl[E_];
    if (!lane) sl[w] = acc;
    __syncthreads();
    if (threadIdx.x == 0) {
        float p[E_];
        float m = sl[0];
        for (int e = 1; e < E_; e++) m = fmaxf(m, sl[e]);
        float s = 0.f;
        for (int e = 0; e < E_; e++) { p[e] = expf(sl[e] - m); s += p[e]; }
        float inv = 1.0f / s;
        for (int e = 0; e < E_; e++) { p[e] *= inv; gates[(size_t)n * E_ + e] = p[e]; }
        int i0 = 0;
        for (int e = 1; e < E_; e++) if (p[e] > p[i0]) i0 = e;
        int i1 = -1;
        for (int e = 0; e < E_; e++) {
            if (e == i0) continue;
            if (i1 < 0 || p[e] > p[i1]) i1 = e;
        }
        top[2 * n] = i0; top[2 * n + 1] = i1;
    }
}

// ---------------- routing ----------------
__global__ void route_kernel(const int* __restrict__ top, int* __restrict__ slot) {
    int e = threadIdx.x;
    if (e >= E_) return;
    int cnt = 0;
    for (int n = 0; n < NTOK; n++) {
        if (top[2 * n] == e)     { slot[2 * n]     = (cnt < CAP) ? cnt : -1; cnt++; }
        if (top[2 * n + 1] == e) { slot[2 * n + 1] = (cnt < CAP) ? cnt : -1; cnt++; }
    }
}

// ---------------- scatter ----------------
__global__ void scatter_kernel(const float* __restrict__ ln, const int* __restrict__ top,
                               const int* __restrict__ slot, float* __restrict__ buf) {
    int n = blockIdx.x;
    const float4* src = (const float4*)(ln + (size_t)n * C_);
#pragma unroll
    for (int kk = 0; kk < 2; kk++) {
        int s = slot[2 * n + kk];
        if (s < 0) continue;
        int e = top[2 * n + kk];
        float4* dst = (float4*)(buf + ((size_t)e * CAPP + s) * C_);
        for (int i = threadIdx.x; i < C_ / 4; i += 256) dst[i] = src[i];
    }
}

// ---------------- combine + residual ----------------
__global__ void combine_kernel(const float* __restrict__ y, const float* __restrict__ gates,
                               const int* __restrict__ top, const int* __restrict__ slot,
                               float* __restrict__ x) {
    int n = blockIdx.x;
    int e0 = top[2 * n], e1 = top[2 * n + 1];
    int s0 = slot[2 * n], s1 = slot[2 * n + 1];
    float w0 = (s0 >= 0) ? gates[(size_t)n * E_ + e0] : 0.f;
    float w1 = (s1 >= 0) ? gates[(size_t)n * E_ + e1] : 0.f;
    const float* y0 = y + ((size_t)e0 * CAPP + (s0 >= 0 ? s0 : 0)) * C_;
    const float* y1 = y + ((size_t)e1 * CAPP + (s1 >= 0 ? s1 : 0)) * C_;
    float* xr = x + (size_t)n * C_;
    for (int c = threadIdx.x; c < C_; c += 256)
        xr[c] += w0 * y0[c] + w1 * y1[c];
}

// ---------------- launch ----------------
extern "C" void kernel_launch(void* const* d_in, const int* in_sizes, int n_in,
                              void* d_out, int out_size) {
    const int*   idx     = (const int*)  d_in[0];
    const float* tok_emb = (const float*)d_in[1];
    const float* ln1_g   = (const float*)d_in[2];
    const float* ln1_b   = (const float*)d_in[3];
    const float* qkv_w   = (const float*)d_in[4];
    const float* proj_w  = (const float*)d_in[5];
    const float* ln2_g   = (const float*)d_in[6];
    const float* ln2_b   = (const float*)d_in[7];
    const float* gate_w  = (const float*)d_in[8];
    const float* w1      = (const float*)d_in[9];
    const float* b1      = (const float*)d_in[10];
    const float* w2      = (const float*)d_in[11];
    const float* b2      = (const float*)d_in[12];
    const float* lnf_g   = (const float*)d_in[13];
    const float* lnf_b   = (const float*)d_in[14];
    const float* lm_head = (const float*)d_in[15];
    float* out = (float*)d_out;

    float *x, *ln, *qkv, *sc, *attn, *gates, *buf, *hbuf, *ybuf;
    int *top, *slot;
    cudaGetSymbolAddress((void**)&x,     g_x);
    cudaGetSymbolAddress((void**)&ln,    g_ln);
    cudaGetSymbolAddress((void**)&qkv,   g_qkv);
    cudaGetSymbolAddress((void**)&sc,    g_scores);
    cudaGetSymbolAddress((void**)&attn,  g_attn);
    cudaGetSymbolAddress((void**)&gates, g_gates);
    cudaGetSymbolAddress((void**)&top,   g_top);
    cudaGetSymbolAddress((void**)&slot,  g_slot);
    cudaGetSymbolAddress((void**)&buf,   g_buf);
    cudaGetSymbolAddress((void**)&hbuf,  g_hbuf);
    cudaGetSymbolAddress((void**)&ybuf,  g_ybuf);

    cudaFuncSetAttribute(mm_mma_kernel, cudaFuncAttributeMaxDynamicSharedMemorySize, MM_SMEM);

    embed_kernel<<<NTOK * C_ / 256, 256>>>(idx, tok_emb, x);

    for (int l = 0; l < L_; l++) {
        // --- attention ---
        ln_kernel<<<NTOK, 256>>>(x, ln1_g + (size_t)l * C_, ln1_b + (size_t)l * C_, ln);
        mm_mma_kernel<<<dim3(NTOK / 128, 3 * C_ / 128, 1), 256, MM_SMEM>>>(
            ln, qkv_w + (size_t)l * C_ * 3 * C_, qkv, nullptr,
            NTOK, 3 * C_, C_, 0, 0, 0, 0, 0);
        rope_kernel<<<(NTOK * H_ * (HD_ / 2) + 255) / 256, 256>>>(qkv);
        attn_scores_kernel<<<dim3(T_ / 16, T_ / 16, B_ * H_), dim3(16, 16)>>>(qkv, sc);
        softmax_kernel<<<B_ * H_ * T_, 256>>>(sc);
        attn_pv_kernel<<<dim3(1, T_ / 64, B_ * H_), 256>>>(sc, qkv, attn);
        mm_mma_kernel<<<dim3(NTOK / 128, C_ / 128, 1), 256, MM_SMEM>>>(
            attn, proj_w + (size_t)l * C_ * C_, x, nullptr,
            NTOK, C_, C_, 0, 0, 0, 0, 1);  // += residual

        // --- MoE ---
        ln_kernel<<<NTOK, 256>>>(x, ln2_g + (size_t)l * C_, ln2_b + (size_t)l * C_, ln);
        gate_kernel<<<NTOK, 256>>>(ln, gate_w + (size_t)l * C_ * E_, gates, top);
        route_kernel<<<1, 32>>>(top, slot);
        scatter_kernel<<<NTOK, 256>>>(ln, top, slot, buf);
        mm_mma_kernel<<<dim3(CAPP / 128, FF_ / 128, E_), 256, MM_SMEM>>>(
            buf, w1 + (size_t)l * E_ * C_ * FF_, hbuf, b1 + (size_t)l * E_ * FF_,
            CAP, FF_, C_, (long)CAPP * C_, (long)C_ * FF_, (long)CAPP * FF_, (long)FF_, 2);
        mm_mma_kernel<<<dim3(CAPP / 128, C_ / 128, E_), 256, MM_SMEM>>>(
            hbuf, w2 + (size_t)l * E_ * FF_ * C_, ybuf, b2 + (size_t)l * E_ * C_,
            CAP, C_, FF_, (long)CAPP * FF_, (long)FF_ * C_, (long)CAPP * C_, (long)C_, 3);
        combine_kernel<<<NTOK, 256>>>(ybuf, gates, top, slot, x);
    }

    ln_kernel<<<NTOK, 256>>>(x, lnf_g, lnf_b, ln);
    mm_mma_kernel<<<dim3(NTOK / 128, V_ / 128, 1), 256, MM_SMEM>>>(
        ln, lm_head, out, nullptr, NTOK, V_, C_, 0, 0, 0, 0, 0);
}

// round 6
// speedup vs baseline: 1.3666x; 1.0327x over previous
#include <cuda_runtime.h>
#include <math.h>
#include <stdint.h>

#define B_   2
#define T_   1024
#define C_   1024
#define H_   16
#define HD_  64
#define L_   2
#define E_   8
#define FF_  4096
#define V_   32000
#define NTOK (B_ * T_)
#define CAP  320   // ceil(1.25 * 2048 / 8)
#define CAPP 384   // padded to multiple of 128

// ---------------- scratch (static device globals; no allocations) ----------------
__device__ float g_x[NTOK * C_];
__device__ float g_ln[NTOK * C_];
__device__ float g_qkv[NTOK * 3 * C_];
__device__ float g_scores[(size_t)B_ * H_ * T_ * T_];
__device__ float g_attn[NTOK * C_];
__device__ float g_gates[NTOK * E_];
__device__ int   g_top[NTOK * 2];
__device__ int   g_slot[NTOK * 2];
__device__ float g_buf [E_ * CAPP * C_];
__device__ float g_hbuf[E_ * CAPP * FF_];
__device__ float g_ybuf[E_ * CAPP * C_];

// ---------------- helpers ----------------
__device__ __forceinline__ float warp_sum(float v) {
#pragma unroll
    for (int o = 16; o; o >>= 1) v += __shfl_xor_sync(0xffffffffu, v, o);
    return v;
}
__device__ __forceinline__ float warp_max(float v) {
#pragma unroll
    for (int o = 16; o; o >>= 1) v = fmaxf(v, __shfl_xor_sync(0xffffffffu, v, o));
    return v;
}
__device__ __forceinline__ float gelu_exact(float v) {
    return 0.5f * v * (1.0f + erff(v * 0.70710678118654752f));
}
__device__ __forceinline__ float to_tf32(float v) {
    float o; asm("cvt.rna.tf32.f32 %0, %1;" : "=f"(o) : "f"(v)); return o;
}

#define MMA_TF32(accp, a0, a1, a2, a3, b0, b1)                                  \
    asm volatile(                                                               \
        "mma.sync.aligned.m16n8k8.row.col.f32.tf32.tf32.f32 "                   \
        "{%0,%1,%2,%3}, {%4,%5,%6,%7}, {%8,%9}, {%0,%1,%2,%3};"                 \
        : "+f"((accp)[0]), "+f"((accp)[1]), "+f"((accp)[2]), "+f"((accp)[3])    \
        : "r"(a0), "r"(a1), "r"(a2), "r"(a3), "r"(b0), "r"(b1))

// ======== 3xTF32 tensor-core GEMM, spill-free + prefetch double-buffered ========
// C[Mv,N] = A[M,K] @ B[K,N], batched over blockIdx.z.
// 128x128 tile per CTA, 256 threads (8 warps as 2x4), K-chunks of 32.
// Raw fp32 in smem (pitches 36/136, conflict-free); hi/lo tf32 split in registers;
// 3 mma passes (hh, h*lo, lo*h). Global loads for chunk i+1 prefetched into
// registers while chunk i computes; two smem buffers.
// ep: 0=store, 1=add into C (residual), 2=bias+gelu, 3=bias
#define LDA_ 36
#define LDB_ 136
#define ABUF (128 * LDA_)              // 4608 floats
#define BBUF (32 * LDB_)               // 4352 floats
#define BUFSZ (ABUF + BBUF)            // 8960 floats per buffer
#define MM_SMEM (2 * BUFSZ * 4)        // 71680 bytes

__global__ void __launch_bounds__(256, 1)
mm_mma_kernel(const float* __restrict__ A, const float* __restrict__ B,
              float* __restrict__ C, const float* __restrict__ bias,
              int Mv, int N, int K,
              long sA, long sB, long sC, long sBias, int ep)
{
    extern __shared__ float sm[];
    int tid = threadIdx.x, lane = tid & 31, wid = tid >> 5;
    int wm = wid & 1, wn = wid >> 1;    // warp tile: rows wm*64..+63, cols wn*32..+31
    int r_lo = lane >> 2, c_lo = lane & 3;
    int z = blockIdx.z;
    A += (long)z * sA; B += (long)z * sB; C += (long)z * sC;
    const float* bp = bias ? bias + (long)z * sBias : nullptr;
    int m0 = blockIdx.x * 128, n0 = blockIdx.y * 128;

    float acc[4][4][4];
#pragma unroll
    for (int i = 0; i < 4; i++)
#pragma unroll
        for (int j = 0; j < 4; j++)
#pragma unroll
            for (int k = 0; k < 4; k++) acc[i][j][k] = 0.f;

    float4 pa[4], pb[4];

    auto prefetch = [&](int i) {
        int k0 = i << 5;
#pragma unroll
        for (int it = 0; it < 4; it++) {
            int idx = tid + it * 256;
            int m = idx >> 3, f4 = idx & 7;
            pa[it] = *(const float4*)(A + (size_t)(m0 + m) * K + k0 + f4 * 4);
        }
#pragma unroll
        for (int it = 0; it < 4; it++) {
            int idx = tid + it * 256;
            int k = idx >> 5, f4 = idx & 31;
            pb[it] = *(const float4*)(B + (size_t)(k0 + k) * N + n0 + f4 * 4);
        }
    };
    auto cstore = [&](int s) {
        float* smA = sm + s * BUFSZ;
        float* smB = smA + ABUF;
#pragma unroll
        for (int it = 0; it < 4; it++) {
            int idx = tid + it * 256;
            int m = idx >> 3, f4 = idx & 7;
            *(float4*)(smA + m * LDA_ + f4 * 4) = pa[it];
        }
#pragma unroll
        for (int it = 0; it < 4; it++) {
            int idx = tid + it * 256;
            int k = idx >> 5, f4 = idx & 31;
            *(float4*)(smB + k * LDB_ + f4 * 4) = pb[it];
        }
    };

    int nch = K >> 5;
    prefetch(0);
    cstore(0);
    __syncthreads();
    for (int i = 0; i < nch; i++) {
        if (i + 1 < nch) prefetch(i + 1);
        {
            float* smA = sm + (i & 1) * BUFSZ;
            float* smB = smA + ABUF;
#pragma unroll
            for (int ks = 0; ks < 4; ks++) {
                float ar[4][4], br[4][2];
                uint32_t ah[4][4], bh[4][2];
#pragma unroll
                for (int mt = 0; mt < 4; mt++) {
                    const float* ab = smA + (wm * 64 + mt * 16 + r_lo) * LDA_ + ks * 8 + c_lo;
                    ar[mt][0] = ab[0];
                    ar[mt][1] = ab[8 * LDA_];
                    ar[mt][2] = ab[4];
                    ar[mt][3] = ab[8 * LDA_ + 4];
#pragma unroll
                    for (int q = 0; q < 4; q++) ah[mt][q] = __float_as_uint(to_tf32(ar[mt][q]));
                }
#pragma unroll
                for (int nt = 0; nt < 4; nt++) {
                    const float* bb = smB + (ks * 8 + c_lo) * LDB_ + wn * 32 + nt * 8 + r_lo;
                    br[nt][0] = bb[0];
                    br[nt][1] = bb[4 * LDB_];
                    bh[nt][0] = __float_as_uint(to_tf32(br[nt][0]));
                    bh[nt][1] = __float_as_uint(to_tf32(br[nt][1]));
                }
                // pass 1: hi x hi
#pragma unroll
                for (int mt = 0; mt < 4; mt++)
#pragma unroll
                    for (int nt = 0; nt < 4; nt++)
                        MMA_TF32(acc[mt][nt], ah[mt][0], ah[mt][1], ah[mt][2], ah[mt][3],
                                 bh[nt][0], bh[nt][1]);
                // b_lo; pass 2: hi x b_lo
#pragma unroll
                for (int nt = 0; nt < 4; nt++) {
                    br[nt][0] = to_tf32(br[nt][0] - __uint_as_float(bh[nt][0]));
                    br[nt][1] = to_tf32(br[nt][1] - __uint_as_float(bh[nt][1]));
                }
#pragma unroll
                for (int mt = 0; mt < 4; mt++)
#pragma unroll
                    for (int nt = 0; nt < 4; nt++)
                        MMA_TF32(acc[mt][nt], ah[mt][0], ah[mt][1], ah[mt][2], ah[mt][3],
                                 __float_as_uint(br[nt][0]), __float_as_uint(br[nt][1]));
                // a_lo; pass 3: a_lo x hi
#pragma unroll
                for (int mt = 0; mt < 4; mt++)
#pragma unroll
                    for (int q = 0; q < 4; q++)
                        ar[mt][q] = to_tf32(ar[mt][q] - __uint_as_float(ah[mt][q]));
#pragma unroll
                for (int mt = 0; mt < 4; mt++)
#pragma unroll
                    for (int nt = 0; nt < 4; nt++)
                        MMA_TF32(acc[mt][nt],
                                 __float_as_uint(ar[mt][0]), __float_as_uint(ar[mt][1]),
                                 __float_as_uint(ar[mt][2]), __float_as_uint(ar[mt][3]),
                                 bh[nt][0], bh[nt][1]);
            }
        }
        __syncthreads();
        if (i + 1 < nch) {
            cstore((i + 1) & 1);
            __syncthreads();
        }
    }

    // epilogue
    int rbase = m0 + wm * 64 + (lane >> 2);
    int cbase = n0 + wn * 32 + (lane & 3) * 2;
#pragma unroll
    for (int mt = 0; mt < 4; mt++) {
#pragma unroll
        for (int half = 0; half < 2; half++) {
            int row = rbase + mt * 16 + half * 8;
            if (row >= Mv) continue;
#pragma unroll
            for (int nt = 0; nt < 4; nt++) {
                int col = cbase + nt * 8;
                float x0 = acc[mt][nt][half * 2 + 0];
                float x1 = acc[mt][nt][half * 2 + 1];
                if (ep == 2)      { x0 = gelu_exact(x0 + bp[col]); x1 = gelu_exact(x1 + bp[col + 1]); }
                else if (ep == 3) { x0 += bp[col]; x1 += bp[col + 1]; }
                float* cp = C + (size_t)row * N + col;
                if (ep == 1) { x0 += cp[0]; x1 += cp[1]; }
                float2 o; o.x = x0; o.y = x1;
                *(float2*)cp = o;
            }
        }
    }
}

// ---------------- embedding gather ----------------
__global__ void embed_kernel(const int* __restrict__ idx, const float* __restrict__ emb,
                             float* __restrict__ x) {
    int i = blockIdx.x * 256 + threadIdx.x;
    int n = i >> 10, c = i & 1023;
    x[i] = emb[(size_t)idx[n] * C_ + c];
}

// ---------------- layernorm ----------------
__global__ void ln_kernel(const float* __restrict__ x, const float* __restrict__ g,
                          const float* __restrict__ b, float* __restrict__ out) {
    int row = blockIdx.x;
    const float* xr = x + (size_t)row * C_;
    float s = 0.f, s2 = 0.f;
    for (int c = threadIdx.x; c < C_; c += 256) { float v = xr[c]; s += v; s2 += v * v; }
    __shared__ float sh1[8], sh2[8], shm[2];
    int lane = threadIdx.x & 31, w = threadIdx.x >> 5;
    s = warp_sum(s); s2 = warp_sum(s2);
    if (!lane) { sh1[w] = s; sh2[w] = s2; }
    __syncthreads();
    if (threadIdx.x == 0) {
        float S = 0.f, S2 = 0.f;
        for (int i = 0; i < 8; i++) { S += sh1[i]; S2 += sh2[i]; }
        float mean = S * (1.0f / C_);
        float var  = S2 * (1.0f / C_) - mean * mean;
        shm[0] = mean; shm[1] = rsqrtf(var + 1e-5f);
    }
    __syncthreads();
    float mean = shm[0], inv = shm[1];
    float* orow = out + (size_t)row * C_;
    for (int c = threadIdx.x; c < C_; c += 256)
        orow[c] = (xr[c] - mean) * inv * g[c] + b[c];
}

// ---------------- RoPE ----------------
__global__ void rope_kernel(float* __restrict__ qkv) {
    int i = blockIdx.x * 256 + threadIdx.x;
    if (i >= NTOK * H_ * (HD_ / 2)) return;
    int j = i & 31;
    int h = (i >> 5) & 15;
    int n = i >> 9;
    int t = n & (T_ - 1);
    float e = (float)(2 * j) / (float)HD_;
    float invf = 1.0f / powf(10000.0f, e);
    float ang = (float)t * invf;
    float s = sinf(ang), c = cosf(ang);
    float* base = qkv + (size_t)n * (3 * C_) + h * (3 * HD_);
    float q1 = base[j],      q2 = base[j + 32];
    base[j]      = q1 * c - q2 * s;
    base[j + 32] = q1 * s + q2 * c;
    float k1 = base[64 + j], k2 = base[64 + j + 32];
    base[64 + j]      = k1 * c - k2 * s;
    base[64 + j + 32] = k1 * s + k2 * c;
}

// ---------------- causal scores ----------------
__global__ void attn_scores_kernel(const float* __restrict__ qkv, float* __restrict__ sc) {
    int bh = blockIdx.z; int b = bh >> 4, h = bh & 15;
    int q0 = blockIdx.y * 16, k0 = blockIdx.x * 16;
    int tx = threadIdx.x, ty = threadIdx.y;
    float* S = sc + (size_t)bh * T_ * T_;
    const float NEG = -3.4028234663852886e38f;
    if (k0 > q0 + 15) { S[(size_t)(q0 + ty) * T_ + k0 + tx] = NEG; return; }
    __shared__ float Qs[16][65], Ks[16][65];
    int tid = ty * 16 + tx;
    const float* qb = qkv + (size_t)(b * T_ + q0) * (3 * C_) + h * (3 * HD_);
    const float* kb = qkv + (size_t)(b * T_ + k0) * (3 * C_) + h * (3 * HD_) + HD_;
#pragma unroll
    for (int r = 0; r < 4; r++) {
        int idx = tid + r * 256;
        int row = idx >> 6, col = idx & 63;
        Qs[row][col] = qb[(size_t)row * (3 * C_) + col];
        Ks[row][col] = kb[(size_t)row * (3 * C_) + col];
    }
    __syncthreads();
    float acc = 0.f;
#pragma unroll
    for (int d = 0; d < 64; d++) acc += Qs[ty][d] * Ks[tx][d];
    int q = q0 + ty, k = k0 + tx;
    S[(size_t)q * T_ + k] = (k <= q) ? acc * 0.125f : NEG;
}

// ---------------- row softmax ----------------
__global__ void softmax_kernel(float* __restrict__ sc) {
    size_t row = blockIdx.x;
    float* r = sc + row * T_;
    __shared__ float sh[8], shv[1];
    int lane = threadIdx.x & 31, w = threadIdx.x >> 5;
    float mx = -INFINITY;
    for (int k = threadIdx.x; k < T_; k += 256) mx = fmaxf(mx, r[k]);
    mx = warp_max(mx);
    if (!lane) sh[w] = mx;
    __syncthreads();
    if (threadIdx.x == 0) {
        float m = sh[0];
        for (int i = 1; i < 8; i++) m = fmaxf(m, sh[i]);
        shv[0] = m;
    }
    __syncthreads();
    float M = shv[0];
    float s = 0.f;
    for (int k = threadIdx.x; k < T_; k += 256) { float e = expf(r[k] - M); r[k] = e; s += e; }
    s = warp_sum(s);
    if (!lane) sh[w] = s;
    __syncthreads();
    if (threadIdx.x == 0) {
        float S = 0.f;
        for (int i = 0; i < 8; i++) S += sh[i];
        shv[0] = 1.0f / S;
    }
    __syncthreads();
    float inv = shv[0];
    for (int k = threadIdx.x; k < T_; k += 256) r[k] *= inv;
}

// ---------------- P @ V ----------------
__global__ void attn_pv_kernel(const float* __restrict__ sc, const float* __restrict__ qkv,
                               float* __restrict__ out) {
    int z = blockIdx.z; int b = z >> 4, h = z & 15;
    const float* A  = sc + (size_t)z * T_ * T_;
    const float* Bp = qkv + (size_t)b * T_ * (3 * C_) + h * (3 * HD_) + 2 * HD_;
    float* Cp = out + (size_t)b * T_ * C_ + h * HD_;
    __shared__ float As[16][68];
    __shared__ float Bs[16][68];
    int tid = threadIdx.x;
    int tx = tid & 15, ty = tid >> 4;
    int m0 = blockIdx.y * 64;
    float acc[4][4] = {};
    for (int k0 = 0; k0 < T_; k0 += 16) {
#pragma unroll
        for (int r = 0; r < 4; r++) {
            int idx = tid + r * 256;
            As[idx & 15][idx >> 4] = A[(size_t)(m0 + (idx >> 4)) * T_ + k0 + (idx & 15)];
        }
#pragma unroll
        for (int r = 0; r < 4; r++) {
            int idx = tid + r * 256;
            Bs[idx >> 6][idx & 63] = Bp[(size_t)(k0 + (idx >> 6)) * (3 * C_) + (idx & 63)];
        }
        __syncthreads();
#pragma unroll
        for (int kk = 0; kk < 16; kk++) {
            float a[4], bb[4];
#pragma unroll
            for (int i = 0; i < 4; i++) a[i]  = As[kk][ty * 4 + i];
#pragma unroll
            for (int j = 0; j < 4; j++) bb[j] = Bs[kk][tx * 4 + j];
#pragma unroll
            for (int i = 0; i < 4; i++)
#pragma unroll
                for (int j = 0; j < 4; j++) acc[i][j] += a[i] * bb[j];
        }
        __syncthreads();
    }
#pragma unroll
    for (int i = 0; i < 4; i++)
#pragma unroll
        for (int j = 0; j < 4; j++)
            Cp[(size_t)(m0 + ty * 4 + i) * C_ + tx * 4 + j] = acc[i][j];
}

// ---------------- gating ----------------
__global__ void gate_kernel(const float* __restrict__ x, const float* __restrict__ gw,
                            float* __restrict__ gates, int* __restrict__ top) {
    int n = blockIdx.x;
    int lane = threadIdx.x & 31, w = threadIdx.x >> 5;
    const float* xr = x + (size_t)n * C_;
    float acc = 0.f;
    for (int c = lane; c < C_; c += 32) acc += xr[c] * gw[(size_t)c * E_ + w];
    acc = warp_sum(acc);
    __shared__ float sl[E_];
    if (!lane) sl[w] = acc;
    __syncthreads();
    if (threadIdx.x == 0) {
        float p[E_];
        float m = sl[0];
        for (int e = 1; e < E_; e++) m = fmaxf(m, sl[e]);
        float s = 0.f;
        for (int e = 0; e < E_; e++) { p[e] = expf(sl[e] - m); s += p[e]; }
        float inv = 1.0f / s;
        for (int e = 0; e < E_; e++) { p[e] *= inv; gates[(size_t)n * E_ + e] = p[e]; }
        int i0 = 0;
        for (int e = 1; e < E_; e++) if (p[e] > p[i0]) i0 = e;
        int i1 = -1;
        for (int e = 0; e < E_; e++) {
            if (e == i0) continue;
            if (i1 < 0 || p[e] > p[i1]) i1 = e;
        }
        top[2 * n] = i0; top[2 * n + 1] = i1;
    }
}

// ---------------- routing ----------------
__global__ void route_kernel(const int* __restrict__ top, int* __restrict__ slot) {
    int e = threadIdx.x;
    if (e >= E_) return;
    int cnt = 0;
    for (int n = 0; n < NTOK; n++) {
        if (top[2 * n] == e)     { slot[2 * n]     = (cnt < CAP) ? cnt : -1; cnt++; }
        if (top[2 * n + 1] == e) { slot[2 * n + 1] = (cnt < CAP) ? cnt : -1; cnt++; }
    }
}

// ---------------- scatter ----------------
__global__ void scatter_kernel(const float* __restrict__ ln, const int* __restrict__ top,
                               const int* __restrict__ slot, float* __restrict__ buf) {
    int n = blockIdx.x;
    const float4* src = (const float4*)(ln + (size_t)n * C_);
#pragma unroll
    for (int kk = 0; kk < 2; kk++) {
        int s = slot[2 * n + kk];
        if (s < 0) continue;
        int e = top[2 * n + kk];
        float4* dst = (float4*)(buf + ((size_t)e * CAPP + s) * C_);
        for (int i = threadIdx.x; i < C_ / 4; i += 256) dst[i] = src[i];
    }
}

// ---------------- combine + residual ----------------
__global__ void combine_kernel(const float* __restrict__ y, const float* __restrict__ gates,
                               const int* __restrict__ top, const int* __restrict__ slot,
                               float* __restrict__ x) {
    int n = blockIdx.x;
    int e0 = top[2 * n], e1 = top[2 * n + 1];
    int s0 = slot[2 * n], s1 = slot[2 * n + 1];
    float w0 = (s0 >= 0) ? gates[(size_t)n * E_ + e0] : 0.f;
    float w1 = (s1 >= 0) ? gates[(size_t)n * E_ + e1] : 0.f;
    const float* y0 = y + ((size_t)e0 * CAPP + (s0 >= 0 ? s0 : 0)) * C_;
    const float* y1 = y + ((size_t)e1 * CAPP + (s1 >= 0 ? s1 : 0)) * C_;
    float* xr = x + (size_t)n * C_;
    for (int c = threadIdx.x; c < C_; c += 256)
        xr[c] += w0 * y0[c] + w1 * y1[c];
}

// ---------------- launch ----------------
extern "C" void kernel_launch(void* const* d_in, const int* in_sizes, int n_in,
                              void* d_out, int out_size) {
    const int*   idx     = (const int*)  d_in[0];
    const float* tok_emb = (const float*)d_in[1];
    const float* ln1_g   = (const float*)d_in[2];
    const float* ln1_b   = (const float*)d_in[3];
    const float* qkv_w   = (const float*)d_in[4];
    const float* proj_w  = (const float*)d_in[5];
    const float* ln2_g   = (const float*)d_in[6];
    const float* ln2_b   = (const float*)d_in[7];
    const float* gate_w  = (const float*)d_in[8];
    const float* w1      = (const float*)d_in[9];
    const float* b1      = (const float*)d_in[10];
    const float* w2      = (const float*)d_in[11];
    const float* b2      = (const float*)d_in[12];
    const float* lnf_g   = (const float*)d_in[13];
    const float* lnf_b   = (const float*)d_in[14];
    const float* lm_head = (const float*)d_in[15];
    float* out = (float*)d_out;

    float *x, *ln, *qkv, *sc, *attn, *gates, *buf, *hbuf, *ybuf;
    int *top, *slot;
    cudaGetSymbolAddress((void**)&x,     g_x);
    cudaGetSymbolAddress((void**)&ln,    g_ln);
    cudaGetSymbolAddress((void**)&qkv,   g_qkv);
    cudaGetSymbolAddress((void**)&sc,    g_scores);
    cudaGetSymbolAddress((void**)&attn,  g_attn);
    cudaGetSymbolAddress((void**)&gates, g_gates);
    cudaGetSymbolAddress((void**)&top,   g_top);
    cudaGetSymbolAddress((void**)&slot,  g_slot);
    cudaGetSymbolAddress((void**)&buf,   g_buf);
    cudaGetSymbolAddress((void**)&hbuf,  g_hbuf);
    cudaGetSymbolAddress((void**)&ybuf,  g_ybuf);

    cudaFuncSetAttribute(mm_mma_kernel, cudaFuncAttributeMaxDynamicSharedMemorySize, MM_SMEM);

    embed_kernel<<<NTOK * C_ / 256, 256>>>(idx, tok_emb, x);

    for (int l = 0; l < L_; l++) {
        // --- attention ---
        ln_kernel<<<NTOK, 256>>>(x, ln1_g + (size_t)l * C_, ln1_b + (size_t)l * C_, ln);
        mm_mma_kernel<<<dim3(NTOK / 128, 3 * C_ / 128, 1), 256, MM_SMEM>>>(
            ln, qkv_w + (size_t)l * C_ * 3 * C_, qkv, nullptr,
            NTOK, 3 * C_, C_, 0, 0, 0, 0, 0);
        rope_kernel<<<(NTOK * H_ * (HD_ / 2) + 255) / 256, 256>>>(qkv);
        attn_scores_kernel<<<dim3(T_ / 16, T_ / 16, B_ * H_), dim3(16, 16)>>>(qkv, sc);
        softmax_kernel<<<B_ * H_ * T_, 256>>>(sc);
        attn_pv_kernel<<<dim3(1, T_ / 64, B_ * H_), 256>>>(sc, qkv, attn);
        mm_mma_kernel<<<dim3(NTOK / 128, C_ / 128, 1), 256, MM_SMEM>>>(
            attn, proj_w + (size_t)l * C_ * C_, x, nullptr,
            NTOK, C_, C_, 0, 0, 0, 0, 1);  // += residual

        // --- MoE ---
        ln_kernel<<<NTOK, 256>>>(x, ln2_g + (size_t)l * C_, ln2_b + (size_t)l * C_, ln);
        gate_kernel<<<NTOK, 256>>>(ln, gate_w + (size_t)l * C_ * E_, gates, top);
        route_kernel<<<1, 32>>>(top, slot);
        scatter_kernel<<<NTOK, 256>>>(ln, top, slot, buf);
        mm_mma_kernel<<<dim3(CAPP / 128, FF_ / 128, E_), 256, MM_SMEM>>>(
            buf, w1 + (size_t)l * E_ * C_ * FF_, hbuf, b1 + (size_t)l * E_ * FF_,
            CAP, FF_, C_, (long)CAPP * C_, (long)C_ * FF_, (long)CAPP * FF_, (long)FF_, 2);
        mm_mma_kernel<<<dim3(CAPP / 128, C_ / 128, E_), 256, MM_SMEM>>>(
            hbuf, w2 + (size_t)l * E_ * FF_ * C_, ybuf, b2 + (size_t)l * E_ * C_,
            CAP, C_, FF_, (long)CAPP * FF_, (long)FF_ * C_, (long)CAPP * C_, (long)C_, 3);
        combine_kernel<<<NTOK, 256>>>(ybuf, gates, top, slot, x);
    }

    ln_kernel<<<NTOK, 256>>>(x, lnf_g, lnf_b, ln);
    mm_mma_kernel<<<dim3(NTOK / 128, V_ / 128, 1), 256, MM_SMEM>>>(
        ln, lm_head, out, nullptr, NTOK, V_, C_, 0, 0, 0, 0, 0);
}

// round 7
// speedup vs baseline: 1.7955x; 1.3139x over previous
#include <cuda_runtime.h>
#include <math.h>
#include <stdint.h>

#define B_   2
#define T_   1024
#define C_   1024
#define H_   16
#define HD_  64
#define L_   2
#define E_   8
#define FF_  4096
#define V_   32000
#define NTOK (B_ * T_)
#define CAP  320   // ceil(1.25 * 2048 / 8)
#define CAPP 384   // padded to multiple of 128

// ---------------- scratch (static device globals; no allocations) ----------------
__device__ float g_x[NTOK * C_];
__device__ float g_ln[NTOK * C_];
__device__ float g_qkv[NTOK * 3 * C_];
__device__ float g_scores[(size_t)B_ * H_ * T_ * T_];
__device__ float g_attn[NTOK * C_];
__device__ float g_gates[NTOK * E_];
__device__ int   g_top[NTOK * 2];
__device__ int   g_slot[NTOK * 2];
__device__ float g_buf [E_ * CAPP * C_];
__device__ float g_hbuf[E_ * CAPP * FF_];
__device__ float g_ybuf[E_ * CAPP * C_];

// ---------------- helpers ----------------
__device__ __forceinline__ float warp_sum(float v) {
#pragma unroll
    for (int o = 16; o; o >>= 1) v += __shfl_xor_sync(0xffffffffu, v, o);
    return v;
}
__device__ __forceinline__ float warp_max(float v) {
#pragma unroll
    for (int o = 16; o; o >>= 1) v = fmaxf(v, __shfl_xor_sync(0xffffffffu, v, o));
    return v;
}
__device__ __forceinline__ float gelu_exact(float v) {
    return 0.5f * v * (1.0f + erff(v * 0.70710678118654752f));
}
__device__ __forceinline__ float to_tf32(float v) {
    float o; asm("cvt.rna.tf32.f32 %0, %1;" : "=f"(o) : "f"(v)); return o;
}

#define MMA_TF32(accp, a0, a1, a2, a3, b0, b1)                                  \
    asm volatile(                                                               \
        "mma.sync.aligned.m16n8k8.row.col.f32.tf32.tf32.f32 "                   \
        "{%0,%1,%2,%3}, {%4,%5,%6,%7}, {%8,%9}, {%0,%1,%2,%3};"                 \
        : "+f"((accp)[0]), "+f"((accp)[1]), "+f"((accp)[2]), "+f"((accp)[3])    \
        : "r"(a0), "r"(a1), "r"(a2), "r"(a3), "r"(b0), "r"(b1))

// ======== TF32 tensor-core GEMM (1-pass or 3-pass error-compensated) ========
// C[Mv,N] = A[M,K] @ B[K,N], batched over blockIdx.z.
// 128x128 tile per CTA, 256 threads (8 warps as 2x4), K-chunks of 32.
// npass=3: hh + h*b_lo + a_lo*h (fp32-grade, for GEMMs feeding routing decisions)
// npass=1: hh only (for GEMMs with only smooth ops downstream; ~4e-4 rel)
// ep: 0=store, 1=add into C (residual), 2=bias+gelu, 3=bias
#define LDA_ 36
#define LDB_ 136
#define ABUF (128 * LDA_)              // 4608 floats
#define BBUF (32 * LDB_)               // 4352 floats
#define BUFSZ (ABUF + BBUF)            // 8960 floats per buffer
#define MM_SMEM (2 * BUFSZ * 4)        // 71680 bytes

__global__ void __launch_bounds__(256, 1)
mm_mma_kernel(const float* __restrict__ A, const float* __restrict__ B,
              float* __restrict__ C, const float* __restrict__ bias,
              int Mv, int N, int K,
              long sA, long sB, long sC, long sBias, int ep, int npass)
{
    extern __shared__ float sm[];
    int tid = threadIdx.x, lane = tid & 31, wid = tid >> 5;
    int wm = wid & 1, wn = wid >> 1;    // warp tile: rows wm*64..+63, cols wn*32..+31
    int r_lo = lane >> 2, c_lo = lane & 3;
    int z = blockIdx.z;
    A += (long)z * sA; B += (long)z * sB; C += (long)z * sC;
    const float* bp = bias ? bias + (long)z * sBias : nullptr;
    int m0 = blockIdx.x * 128, n0 = blockIdx.y * 128;

    float acc[4][4][4];
#pragma unroll
    for (int i = 0; i < 4; i++)
#pragma unroll
        for (int j = 0; j < 4; j++)
#pragma unroll
            for (int k = 0; k < 4; k++) acc[i][j][k] = 0.f;

    float4 pa[4], pb[4];

    auto prefetch = [&](int i) {
        int k0 = i << 5;
#pragma unroll
        for (int it = 0; it < 4; it++) {
            int idx = tid + it * 256;
            int m = idx >> 3, f4 = idx & 7;
            pa[it] = *(const float4*)(A + (size_t)(m0 + m) * K + k0 + f4 * 4);
        }
#pragma unroll
        for (int it = 0; it < 4; it++) {
            int idx = tid + it * 256;
            int k = idx >> 5, f4 = idx & 31;
            pb[it] = *(const float4*)(B + (size_t)(k0 + k) * N + n0 + f4 * 4);
        }
    };
    auto cstore = [&](int s) {
        float* smA = sm + s * BUFSZ;
        float* smB = smA + ABUF;
#pragma unroll
        for (int it = 0; it < 4; it++) {
            int idx = tid + it * 256;
            int m = idx >> 3, f4 = idx & 7;
            *(float4*)(smA + m * LDA_ + f4 * 4) = pa[it];
        }
#pragma unroll
        for (int it = 0; it < 4; it++) {
            int idx = tid + it * 256;
            int k = idx >> 5, f4 = idx & 31;
            *(float4*)(smB + k * LDB_ + f4 * 4) = pb[it];
        }
    };

    int nch = K >> 5;
    prefetch(0);
    cstore(0);
    __syncthreads();
    for (int i = 0; i < nch; i++) {
        if (i + 1 < nch) prefetch(i + 1);
        {
            float* smA = sm + (i & 1) * BUFSZ;
            float* smB = smA + ABUF;
#pragma unroll
            for (int ks = 0; ks < 4; ks++) {
                float ar[4][4], br[4][2];
                uint32_t ah[4][4], bh[4][2];
#pragma unroll
                for (int mt = 0; mt < 4; mt++) {
                    const float* ab = smA + (wm * 64 + mt * 16 + r_lo) * LDA_ + ks * 8 + c_lo;
                    ar[mt][0] = ab[0];
                    ar[mt][1] = ab[8 * LDA_];
                    ar[mt][2] = ab[4];
                    ar[mt][3] = ab[8 * LDA_ + 4];
#pragma unroll
                    for (int q = 0; q < 4; q++) ah[mt][q] = __float_as_uint(to_tf32(ar[mt][q]));
                }
#pragma unroll
                for (int nt = 0; nt < 4; nt++) {
                    const float* bb = smB + (ks * 8 + c_lo) * LDB_ + wn * 32 + nt * 8 + r_lo;
                    br[nt][0] = bb[0];
                    br[nt][1] = bb[4 * LDB_];
                    bh[nt][0] = __float_as_uint(to_tf32(br[nt][0]));
                    bh[nt][1] = __float_as_uint(to_tf32(br[nt][1]));
                }
                // pass 1: hi x hi
#pragma unroll
                for (int mt = 0; mt < 4; mt++)
#pragma unroll
                    for (int nt = 0; nt < 4; nt++)
                        MMA_TF32(acc[mt][nt], ah[mt][0], ah[mt][1], ah[mt][2], ah[mt][3],
                                 bh[nt][0], bh[nt][1]);
                if (npass == 3) {
                    // b_lo; pass 2: hi x b_lo
#pragma unroll
                    for (int nt = 0; nt < 4; nt++) {
                        br[nt][0] = to_tf32(br[nt][0] - __uint_as_float(bh[nt][0]));
                        br[nt][1] = to_tf32(br[nt][1] - __uint_as_float(bh[nt][1]));
                    }
#pragma unroll
                    for (int mt = 0; mt < 4; mt++)
#pragma unroll
                        for (int nt = 0; nt < 4; nt++)
                            MMA_TF32(acc[mt][nt], ah[mt][0], ah[mt][1], ah[mt][2], ah[mt][3],
                                     __float_as_uint(br[nt][0]), __float_as_uint(br[nt][1]));
                    // a_lo; pass 3: a_lo x hi
#pragma unroll
                    for (int mt = 0; mt < 4; mt++)
#pragma unroll
                        for (int q = 0; q < 4; q++)
                            ar[mt][q] = to_tf32(ar[mt][q] - __uint_as_float(ah[mt][q]));
#pragma unroll
                    for (int mt = 0; mt < 4; mt++)
#pragma unroll
                        for (int nt = 0; nt < 4; nt++)
                            MMA_TF32(acc[mt][nt],
                                     __float_as_uint(ar[mt][0]), __float_as_uint(ar[mt][1]),
                                     __float_as_uint(ar[mt][2]), __float_as_uint(ar[mt][3]),
                                     bh[nt][0], bh[nt][1]);
                }
            }
        }
        __syncthreads();
        if (i + 1 < nch) {
            cstore((i + 1) & 1);
            __syncthreads();
        }
    }

    // epilogue
    int rbase = m0 + wm * 64 + (lane >> 2);
    int cbase = n0 + wn * 32 + (lane & 3) * 2;
#pragma unroll
    for (int mt = 0; mt < 4; mt++) {
#pragma unroll
        for (int half = 0; half < 2; half++) {
            int row = rbase + mt * 16 + half * 8;
            if (row >= Mv) continue;
#pragma unroll
            for (int nt = 0; nt < 4; nt++) {
                int col = cbase + nt * 8;
                float x0 = acc[mt][nt][half * 2 + 0];
                float x1 = acc[mt][nt][half * 2 + 1];
                if (ep == 2)      { x0 = gelu_exact(x0 + bp[col]); x1 = gelu_exact(x1 + bp[col + 1]); }
                else if (ep == 3) { x0 += bp[col]; x1 += bp[col + 1]; }
                float* cp = C + (size_t)row * N + col;
                if (ep == 1) { x0 += cp[0]; x1 += cp[1]; }
                float2 o; o.x = x0; o.y = x1;
                *(float2*)cp = o;
            }
        }
    }
}

// ---------------- embedding gather ----------------
__global__ void embed_kernel(const int* __restrict__ idx, const float* __restrict__ emb,
                             float* __restrict__ x) {
    int i = blockIdx.x * 256 + threadIdx.x;
    int n = i >> 10, c = i & 1023;
    x[i] = emb[(size_t)idx[n] * C_ + c];
}

// ---------------- layernorm ----------------
__global__ void ln_kernel(const float* __restrict__ x, const float* __restrict__ g,
                          const float* __restrict__ b, float* __restrict__ out) {
    int row = blockIdx.x;
    const float* xr = x + (size_t)row * C_;
    float s = 0.f, s2 = 0.f;
    for (int c = threadIdx.x; c < C_; c += 256) { float v = xr[c]; s += v; s2 += v * v; }
    __shared__ float sh1[8], sh2[8], shm[2];
    int lane = threadIdx.x & 31, w = threadIdx.x >> 5;
    s = warp_sum(s); s2 = warp_sum(s2);
    if (!lane) { sh1[w] = s; sh2[w] = s2; }
    __syncthreads();
    if (threadIdx.x == 0) {
        float S = 0.f, S2 = 0.f;
        for (int i = 0; i < 8; i++) { S += sh1[i]; S2 += sh2[i]; }
        float mean = S * (1.0f / C_);
        float var  = S2 * (1.0f / C_) - mean * mean;
        shm[0] = mean; shm[1] = rsqrtf(var + 1e-5f);
    }
    __syncthreads();
    float mean = shm[0], inv = shm[1];
    float* orow = out + (size_t)row * C_;
    for (int c = threadIdx.x; c < C_; c += 256)
        orow[c] = (xr[c] - mean) * inv * g[c] + b[c];
}

// ---------------- RoPE ----------------
__global__ void rope_kernel(float* __restrict__ qkv) {
    int i = blockIdx.x * 256 + threadIdx.x;
    if (i >= NTOK * H_ * (HD_ / 2)) return;
    int j = i & 31;
    int h = (i >> 5) & 15;
    int n = i >> 9;
    int t = n & (T_ - 1);
    float e = (float)(2 * j) / (float)HD_;
    float invf = 1.0f / powf(10000.0f, e);
    float ang = (float)t * invf;
    float s = sinf(ang), c = cosf(ang);
    float* base = qkv + (size_t)n * (3 * C_) + h * (3 * HD_);
    float q1 = base[j],      q2 = base[j + 32];
    base[j]      = q1 * c - q2 * s;
    base[j + 32] = q1 * s + q2 * c;
    float k1 = base[64 + j], k2 = base[64 + j + 32];
    base[64 + j]      = k1 * c - k2 * s;
    base[64 + j + 32] = k1 * s + k2 * c;
}

// ---------------- causal scores ----------------
__global__ void attn_scores_kernel(const float* __restrict__ qkv, float* __restrict__ sc) {
    int bh = blockIdx.z; int b = bh >> 4, h = bh & 15;
    int q0 = blockIdx.y * 16, k0 = blockIdx.x * 16;
    int tx = threadIdx.x, ty = threadIdx.y;
    float* S = sc + (size_t)bh * T_ * T_;
    const float NEG = -3.4028234663852886e38f;
    if (k0 > q0 + 15) { S[(size_t)(q0 + ty) * T_ + k0 + tx] = NEG; return; }
    __shared__ float Qs[16][65], Ks[16][65];
    int tid = ty * 16 + tx;
    const float* qb = qkv + (size_t)(b * T_ + q0) * (3 * C_) + h * (3 * HD_);
    const float* kb = qkv + (size_t)(b * T_ + k0) * (3 * C_) + h * (3 * HD_) + HD_;
#pragma unroll
    for (int r = 0; r < 4; r++) {
        int idx = tid + r * 256;
        int row = idx >> 6, col = idx & 63;
        Qs[row][col] = qb[(size_t)row * (3 * C_) + col];
        Ks[row][col] = kb[(size_t)row * (3 * C_) + col];
    }
    __syncthreads();
    float acc = 0.f;
#pragma unroll
    for (int d = 0; d < 64; d++) acc += Qs[ty][d] * Ks[tx][d];
    int q = q0 + ty, k = k0 + tx;
    S[(size_t)q * T_ + k] = (k <= q) ? acc * 0.125f : NEG;
}

// ---------------- row softmax ----------------
__global__ void softmax_kernel(float* __restrict__ sc) {
    size_t row = blockIdx.x;
    float* r = sc + row * T_;
    __shared__ float sh[8], shv[1];
    int lane = threadIdx.x & 31, w = threadIdx.x >> 5;
    float mx = -INFINITY;
    for (int k = threadIdx.x; k < T_; k += 256) mx = fmaxf(mx, r[k]);
    mx = warp_max(mx);
    if (!lane) sh[w] = mx;
    __syncthreads();
    if (threadIdx.x == 0) {
        float m = sh[0];
        for (int i = 1; i < 8; i++) m = fmaxf(m, sh[i]);
        shv[0] = m;
    }
    __syncthreads();
    float M = shv[0];
    float s = 0.f;
    for (int k = threadIdx.x; k < T_; k += 256) { float e = expf(r[k] - M); r[k] = e; s += e; }
    s = warp_sum(s);
    if (!lane) sh[w] = s;
    __syncthreads();
    if (threadIdx.x == 0) {
        float S = 0.f;
        for (int i = 0; i < 8; i++) S += sh[i];
        shv[0] = 1.0f / S;
    }
    __syncthreads();
    float inv = shv[0];
    for (int k = threadIdx.x; k < T_; k += 256) r[k] *= inv;
}

// ---------------- P @ V ----------------
__global__ void attn_pv_kernel(const float* __restrict__ sc, const float* __restrict__ qkv,
                               float* __restrict__ out) {
    int z = blockIdx.z; int b = z >> 4, h = z & 15;
    const float* A  = sc + (size_t)z * T_ * T_;
    const float* Bp = qkv + (size_t)b * T_ * (3 * C_) + h * (3 * HD_) + 2 * HD_;
    float* Cp = out + (size_t)b * T_ * C_ + h * HD_;
    __shared__ float As[16][68];
    __shared__ float Bs[16][68];
    int tid = threadIdx.x;
    int tx = tid & 15, ty = tid >> 4;
    int m0 = blockIdx.y * 64;
    float acc[4][4] = {};
    for (int k0 = 0; k0 < T_; k0 += 16) {
#pragma unroll
        for (int r = 0; r < 4; r++) {
            int idx = tid + r * 256;
            As[idx & 15][idx >> 4] = A[(size_t)(m0 + (idx >> 4)) * T_ + k0 + (idx & 15)];
        }
#pragma unroll
        for (int r = 0; r < 4; r++) {
            int idx = tid + r * 256;
            Bs[idx >> 6][idx & 63] = Bp[(size_t)(k0 + (idx >> 6)) * (3 * C_) + (idx & 63)];
        }
        __syncthreads();
#pragma unroll
        for (int kk = 0; kk < 16; kk++) {
            float a[4], bb[4];
#pragma unroll
            for (int i = 0; i < 4; i++) a[i]  = As[kk][ty * 4 + i];
#pragma unroll
            for (int j = 0; j < 4; j++) bb[j] = Bs[kk][tx * 4 + j];
#pragma unroll
            for (int i = 0; i < 4; i++)
#pragma unroll
                for (int j = 0; j < 4; j++) acc[i][j] += a[i] * bb[j];
        }
        __syncthreads();
    }
#pragma unroll
    for (int i = 0; i < 4; i++)
#pragma unroll
        for (int j = 0; j < 4; j++)
            Cp[(size_t)(m0 + ty * 4 + i) * C_ + tx * 4 + j] = acc[i][j];
}

// ---------------- gating ----------------
__global__ void gate_kernel(const float* __restrict__ x, const float* __restrict__ gw,
                            float* __restrict__ gates, int* __restrict__ top) {
    int n = blockIdx.x;
    int lane = threadIdx.x & 31, w = threadIdx.x >> 5;
    const float* xr = x + (size_t)n * C_;
    float acc = 0.f;
    for (int c = lane; c < C_; c += 32) acc += xr[c] * gw[(size_t)c * E_ + w];
    acc = warp_sum(acc);
    __shared__ float sl[E_];
    if (!lane) sl[w] = acc;
    __syncthreads();
    if (threadIdx.x == 0) {
        float p[E_];
        float m = sl[0];
        for (int e = 1; e < E_; e++) m = fmaxf(m, sl[e]);
        float s = 0.f;
        for (int e = 0; e < E_; e++) { p[e] = expf(sl[e] - m); s += p[e]; }
        float inv = 1.0f / s;
        for (int e = 0; e < E_; e++) { p[e] *= inv; gates[(size_t)n * E_ + e] = p[e]; }
        int i0 = 0;
        for (int e = 1; e < E_; e++) if (p[e] > p[i0]) i0 = e;
        int i1 = -1;
        for (int e = 0; e < E_; e++) {
            if (e == i0) continue;
            if (i1 < 0 || p[e] > p[i1]) i1 = e;
        }
        top[2 * n] = i0; top[2 * n + 1] = i1;
    }
}

// ---------------- routing ----------------
__global__ void route_kernel(const int* __restrict__ top, int* __restrict__ slot) {
    int e = threadIdx.x;
    if (e >= E_) return;
    int cnt = 0;
    for (int n = 0; n < NTOK; n++) {
        if (top[2 * n] == e)     { slot[2 * n]     = (cnt < CAP) ? cnt : -1; cnt++; }
        if (top[2 * n + 1] == e) { slot[2 * n + 1] = (cnt < CAP) ? cnt : -1; cnt++; }
    }
}

// ---------------- scatter ----------------
__global__ void scatter_kernel(const float* __restrict__ ln, const int* __restrict__ top,
                               const int* __restrict__ slot, float* __restrict__ buf) {
    int n = blockIdx.x;
    const float4* src = (const float4*)(ln + (size_t)n * C_);
#pragma unroll
    for (int kk = 0; kk < 2; kk++) {
        int s = slot[2 * n + kk];
        if (s < 0) continue;
        int e = top[2 * n + kk];
        float4* dst = (float4*)(buf + ((size_t)e * CAPP + s) * C_);
        for (int i = threadIdx.x; i < C_ / 4; i += 256) dst[i] = src[i];
    }
}

// ---------------- combine + residual ----------------
__global__ void combine_kernel(const float* __restrict__ y, const float* __restrict__ gates,
                               const int* __restrict__ top, const int* __restrict__ slot,
                               float* __restrict__ x) {
    int n = blockIdx.x;
    int e0 = top[2 * n], e1 = top[2 * n + 1];
    int s0 = slot[2 * n], s1 = slot[2 * n + 1];
    float w0 = (s0 >= 0) ? gates[(size_t)n * E_ + e0] : 0.f;
    float w1 = (s1 >= 0) ? gates[(size_t)n * E_ + e1] : 0.f;
    const float* y0 = y + ((size_t)e0 * CAPP + (s0 >= 0 ? s0 : 0)) * C_;
    const float* y1 = y + ((size_t)e1 * CAPP + (s1 >= 0 ? s1 : 0)) * C_;
    float* xr = x + (size_t)n * C_;
    for (int c = threadIdx.x; c < C_; c += 256)
        xr[c] += w0 * y0[c] + w1 * y1[c];
}

// ---------------- launch ----------------
extern "C" void kernel_launch(void* const* d_in, const int* in_sizes, int n_in,
                              void* d_out, int out_size) {
    const int*   idx     = (const int*)  d_in[0];
    const float* tok_emb = (const float*)d_in[1];
    const float* ln1_g   = (const float*)d_in[2];
    const float* ln1_b   = (const float*)d_in[3];
    const float* qkv_w   = (const float*)d_in[4];
    const float* proj_w  = (const float*)d_in[5];
    const float* ln2_g   = (const float*)d_in[6];
    const float* ln2_b   = (const float*)d_in[7];
    const float* gate_w  = (const float*)d_in[8];
    const float* w1      = (const float*)d_in[9];
    const float* b1      = (const float*)d_in[10];
    const float* w2      = (const float*)d_in[11];
    const float* b2      = (const float*)d_in[12];
    const float* lnf_g   = (const float*)d_in[13];
    const float* lnf_b   = (const float*)d_in[14];
    const float* lm_head = (const float*)d_in[15];
    float* out = (float*)d_out;

    float *x, *ln, *qkv, *sc, *attn, *gates, *buf, *hbuf, *ybuf;
    int *top, *slot;
    cudaGetSymbolAddress((void**)&x,     g_x);
    cudaGetSymbolAddress((void**)&ln,    g_ln);
    cudaGetSymbolAddress((void**)&qkv,   g_qkv);
    cudaGetSymbolAddress((void**)&sc,    g_scores);
    cudaGetSymbolAddress((void**)&attn,  g_attn);
    cudaGetSymbolAddress((void**)&gates, g_gates);
    cudaGetSymbolAddress((void**)&top,   g_top);
    cudaGetSymbolAddress((void**)&slot,  g_slot);
    cudaGetSymbolAddress((void**)&buf,   g_buf);
    cudaGetSymbolAddress((void**)&hbuf,  g_hbuf);
    cudaGetSymbolAddress((void**)&ybuf,  g_ybuf);

    cudaFuncSetAttribute(mm_mma_kernel, cudaFuncAttributeMaxDynamicSharedMemorySize, MM_SMEM);

    embed_kernel<<<NTOK * C_ / 256, 256>>>(idx, tok_emb, x);

    for (int l = 0; l < L_; l++) {
        // --- attention ---
        ln_kernel<<<NTOK, 256>>>(x, ln1_g + (size_t)l * C_, ln1_b + (size_t)l * C_, ln);
        mm_mma_kernel<<<dim3(NTOK / 128, 3 * C_ / 128, 1), 256, MM_SMEM>>>(
            ln, qkv_w + (size_t)l * C_ * 3 * C_, qkv, nullptr,
            NTOK, 3 * C_, C_, 0, 0, 0, 0, 0, 3);
        rope_kernel<<<(NTOK * H_ * (HD_ / 2) + 255) / 256, 256>>>(qkv);
        attn_scores_kernel<<<dim3(T_ / 16, T_ / 16, B_ * H_), dim3(16, 16)>>>(qkv, sc);
        softmax_kernel<<<B_ * H_ * T_, 256>>>(sc);
        attn_pv_kernel<<<dim3(1, T_ / 64, B_ * H_), 256>>>(sc, qkv, attn);
        mm_mma_kernel<<<dim3(NTOK / 128, C_ / 128, 1), 256, MM_SMEM>>>(
            attn, proj_w + (size_t)l * C_ * C_, x, nullptr,
            NTOK, C_, C_, 0, 0, 0, 0, 1, 3);  // += residual

        // --- MoE ---
        // Layer l's MoE expert GEMMs run AFTER layer-l routing. For the last
        // layer there are no further routing decisions downstream (only final
        // LN + lm_head, both smooth) -> 1-pass tf32 suffices there.
        int moe_pass = (l == L_ - 1) ? 1 : 3;
        ln_kernel<<<NTOK, 256>>>(x, ln2_g + (size_t)l * C_, ln2_b + (size_t)l * C_, ln);
        gate_kernel<<<NTOK, 256>>>(ln, gate_w + (size_t)l * C_ * E_, gates, top);
        route_kernel<<<1, 32>>>(top, slot);
        scatter_kernel<<<NTOK, 256>>>(ln, top, slot, buf);
        mm_mma_kernel<<<dim3(CAPP / 128, FF_ / 128, E_), 256, MM_SMEM>>>(
            buf, w1 + (size_t)l * E_ * C_ * FF_, hbuf, b1 + (size_t)l * E_ * FF_,
            CAP, FF_, C_, (long)CAPP * C_, (long)C_ * FF_, (long)CAPP * FF_, (long)FF_, 2, moe_pass);
        mm_mma_kernel<<<dim3(CAPP / 128, C_ / 128, E_), 256, MM_SMEM>>>(
            hbuf, w2 + (size_t)l * E_ * FF_ * C_, ybuf, b2 + (size_t)l * E_ * C_,
            CAP, C_, FF_, (long)CAPP * FF_, (long)FF_ * C_, (long)CAPP * C_, (long)C_, 3, moe_pass);
        combine_kernel<<<NTOK, 256>>>(ybuf, gates, top, slot, x);
    }

    ln_kernel<<<NTOK, 256>>>(x, lnf_g, lnf_b, ln);
    // lm_head: final output, tolerance 1e-3, no decisions downstream -> 1-pass.
    mm_mma_kernel<<<dim3(NTOK / 128, V_ / 128, 1), 256, MM_SMEM>>>(
        ln, lm_head, out, nullptr, NTOK, V_, C_, 0, 0, 0, 0, 0, 1);
}

// round 8
// speedup vs baseline: 2.0155x; 1.1225x over previous
#include <cuda_runtime.h>
#include <math.h>
#include <stdint.h>

#define B_   2
#define T_   1024
#define C_   1024
#define H_   16
#define HD_  64
#define L_   2
#define E_   8
#define FF_  4096
#define V_   32000
#define NTOK (B_ * T_)
#define CAP  320   // ceil(1.25 * 2048 / 8)
#define CAPP 384   // padded to multiple of 128

// ---------------- scratch (static device globals; no allocations) ----------------
__device__ float g_x[NTOK * C_];
__device__ float g_ln[NTOK * C_];
__device__ float g_qkv[NTOK * 3 * C_];
__device__ float g_scores[(size_t)B_ * H_ * T_ * T_];
__device__ float g_attn[NTOK * C_];
__device__ float g_gates[NTOK * E_];
__device__ int   g_top[NTOK * 2];
__device__ int   g_slot[NTOK * 2];
__device__ float g_buf [E_ * CAPP * C_];
__device__ float g_hbuf[E_ * CAPP * FF_];
__device__ float g_ybuf[E_ * CAPP * C_];

// ---------------- helpers ----------------
__device__ __forceinline__ float warp_sum(float v) {
#pragma unroll
    for (int o = 16; o; o >>= 1) v += __shfl_xor_sync(0xffffffffu, v, o);
    return v;
}
__device__ __forceinline__ float warp_max(float v) {
#pragma unroll
    for (int o = 16; o; o >>= 1) v = fmaxf(v, __shfl_xor_sync(0xffffffffu, v, o));
    return v;
}
__device__ __forceinline__ float gelu_exact(float v) {
    return 0.5f * v * (1.0f + erff(v * 0.70710678118654752f));
}
__device__ __forceinline__ float to_tf32(float v) {
    float o; asm("cvt.rna.tf32.f32 %0, %1;" : "=f"(o) : "f"(v)); return o;
}

#define MMA_TF32(accp, a0, a1, a2, a3, b0, b1)                                  \
    asm volatile(                                                               \
        "mma.sync.aligned.m16n8k8.row.col.f32.tf32.tf32.f32 "                   \
        "{%0,%1,%2,%3}, {%4,%5,%6,%7}, {%8,%9}, {%0,%1,%2,%3};"                 \
        : "+f"((accp)[0]), "+f"((accp)[1]), "+f"((accp)[2]), "+f"((accp)[3])    \
        : "r"(a0), "r"(a1), "r"(a2), "r"(a3), "r"(b0), "r"(b1))

// ======== TF32 tensor-core GEMM (1-pass or 3-pass error-compensated) ========
#define LDA_ 36
#define LDB_ 136
#define ABUF (128 * LDA_)
#define BBUF (32 * LDB_)
#define BUFSZ (ABUF + BBUF)
#define MM_SMEM (2 * BUFSZ * 4)

__global__ void __launch_bounds__(256, 1)
mm_mma_kernel(const float* __restrict__ A, const float* __restrict__ B,
              float* __restrict__ C, const float* __restrict__ bias,
              int Mv, int N, int K,
              long sA, long sB, long sC, long sBias, int ep, int npass)
{
    extern __shared__ float sm[];
    int tid = threadIdx.x, lane = tid & 31, wid = tid >> 5;
    int wm = wid & 1, wn = wid >> 1;
    int r_lo = lane >> 2, c_lo = lane & 3;
    int z = blockIdx.z;
    A += (long)z * sA; B += (long)z * sB; C += (long)z * sC;
    const float* bp = bias ? bias + (long)z * sBias : nullptr;
    int m0 = blockIdx.x * 128, n0 = blockIdx.y * 128;

    float acc[4][4][4];
#pragma unroll
    for (int i = 0; i < 4; i++)
#pragma unroll
        for (int j = 0; j < 4; j++)
#pragma unroll
            for (int k = 0; k < 4; k++) acc[i][j][k] = 0.f;

    float4 pa[4], pb[4];

    auto prefetch = [&](int i) {
        int k0 = i << 5;
#pragma unroll
        for (int it = 0; it < 4; it++) {
            int idx = tid + it * 256;
            int m = idx >> 3, f4 = idx & 7;
            pa[it] = *(const float4*)(A + (size_t)(m0 + m) * K + k0 + f4 * 4);
        }
#pragma unroll
        for (int it = 0; it < 4; it++) {
            int idx = tid + it * 256;
            int k = idx >> 5, f4 = idx & 31;
            pb[it] = *(const float4*)(B + (size_t)(k0 + k) * N + n0 + f4 * 4);
        }
    };
    auto cstore = [&](int s) {
        float* smA = sm + s * BUFSZ;
        float* smB = smA + ABUF;
#pragma unroll
        for (int it = 0; it < 4; it++) {
            int idx = tid + it * 256;
            int m = idx >> 3, f4 = idx & 7;
            *(float4*)(smA + m * LDA_ + f4 * 4) = pa[it];
        }
#pragma unroll
        for (int it = 0; it < 4; it++) {
            int idx = tid + it * 256;
            int k = idx >> 5, f4 = idx & 31;
            *(float4*)(smB + k * LDB_ + f4 * 4) = pb[it];
        }
    };

    int nch = K >> 5;
    prefetch(0);
    cstore(0);
    __syncthreads();
    for (int i = 0; i < nch; i++) {
        if (i + 1 < nch) prefetch(i + 1);
        {
            float* smA = sm + (i & 1) * BUFSZ;
            float* smB = smA + ABUF;
#pragma unroll
            for (int ks = 0; ks < 4; ks++) {
                float ar[4][4], br[4][2];
                uint32_t ah[4][4], bh[4][2];
#pragma unroll
                for (int mt = 0; mt < 4; mt++) {
                    const float* ab = smA + (wm * 64 + mt * 16 + r_lo) * LDA_ + ks * 8 + c_lo;
                    ar[mt][0] = ab[0];
                    ar[mt][1] = ab[8 * LDA_];
                    ar[mt][2] = ab[4];
                    ar[mt][3] = ab[8 * LDA_ + 4];
#pragma unroll
                    for (int q = 0; q < 4; q++) ah[mt][q] = __float_as_uint(to_tf32(ar[mt][q]));
                }
#pragma unroll
                for (int nt = 0; nt < 4; nt++) {
                    const float* bb = smB + (ks * 8 + c_lo) * LDB_ + wn * 32 + nt * 8 + r_lo;
                    br[nt][0] = bb[0];
                    br[nt][1] = bb[4 * LDB_];
                    bh[nt][0] = __float_as_uint(to_tf32(br[nt][0]));
                    bh[nt][1] = __float_as_uint(to_tf32(br[nt][1]));
                }
                // pass 1: hi x hi
#pragma unroll
                for (int mt = 0; mt < 4; mt++)
#pragma unroll
                    for (int nt = 0; nt < 4; nt++)
                        MMA_TF32(acc[mt][nt], ah[mt][0], ah[mt][1], ah[mt][2], ah[mt][3],
                                 bh[nt][0], bh[nt][1]);
                if (npass == 3) {
                    // b_lo; pass 2: hi x b_lo
#pragma unroll
                    for (int nt = 0; nt < 4; nt++) {
                        br[nt][0] = to_tf32(br[nt][0] - __uint_as_float(bh[nt][0]));
                        br[nt][1] = to_tf32(br[nt][1] - __uint_as_float(bh[nt][1]));
                    }
#pragma unroll
                    for (int mt = 0; mt < 4; mt++)
#pragma unroll
                        for (int nt = 0; nt < 4; nt++)
                            MMA_TF32(acc[mt][nt], ah[mt][0], ah[mt][1], ah[mt][2], ah[mt][3],
                                     __float_as_uint(br[nt][0]), __float_as_uint(br[nt][1]));
                    // a_lo; pass 3: a_lo x hi
#pragma unroll
                    for (int mt = 0; mt < 4; mt++)
#pragma unroll
                        for (int q = 0; q < 4; q++)
                            ar[mt][q] = to_tf32(ar[mt][q] - __uint_as_float(ah[mt][q]));
#pragma unroll
                    for (int mt = 0; mt < 4; mt++)
#pragma unroll
                        for (int nt = 0; nt < 4; nt++)
                            MMA_TF32(acc[mt][nt],
                                     __float_as_uint(ar[mt][0]), __float_as_uint(ar[mt][1]),
                                     __float_as_uint(ar[mt][2]), __float_as_uint(ar[mt][3]),
                                     bh[nt][0], bh[nt][1]);
                }
            }
        }
        __syncthreads();
        if (i + 1 < nch) {
            cstore((i + 1) & 1);
            __syncthreads();
        }
    }

    // epilogue
    int rbase = m0 + wm * 64 + (lane >> 2);
    int cbase = n0 + wn * 32 + (lane & 3) * 2;
#pragma unroll
    for (int mt = 0; mt < 4; mt++) {
#pragma unroll
        for (int half = 0; half < 2; half++) {
            int row = rbase + mt * 16 + half * 8;
            if (row >= Mv) continue;
#pragma unroll
            for (int nt = 0; nt < 4; nt++) {
                int col = cbase + nt * 8;
                float x0 = acc[mt][nt][half * 2 + 0];
                float x1 = acc[mt][nt][half * 2 + 1];
                if (ep == 2)      { x0 = gelu_exact(x0 + bp[col]); x1 = gelu_exact(x1 + bp[col + 1]); }
                else if (ep == 3) { x0 += bp[col]; x1 += bp[col + 1]; }
                float* cp = C + (size_t)row * N + col;
                if (ep == 1) { x0 += cp[0]; x1 += cp[1]; }
                float2 o; o.x = x0; o.y = x1;
                *(float2*)cp = o;
            }
        }
    }
}

// ---------------- embedding gather ----------------
__global__ void embed_kernel(const int* __restrict__ idx, const float* __restrict__ emb,
                             float* __restrict__ x) {
    int i = blockIdx.x * 256 + threadIdx.x;
    int n = i >> 10, c = i & 1023;
    x[i] = emb[(size_t)idx[n] * C_ + c];
}

// ---------------- layernorm ----------------
__global__ void ln_kernel(const float* __restrict__ x, const float* __restrict__ g,
                          const float* __restrict__ b, float* __restrict__ out) {
    int row = blockIdx.x;
    const float* xr = x + (size_t)row * C_;
    float s = 0.f, s2 = 0.f;
    for (int c = threadIdx.x; c < C_; c += 256) { float v = xr[c]; s += v; s2 += v * v; }
    __shared__ float sh1[8], sh2[8], shm[2];
    int lane = threadIdx.x & 31, w = threadIdx.x >> 5;
    s = warp_sum(s); s2 = warp_sum(s2);
    if (!lane) { sh1[w] = s; sh2[w] = s2; }
    __syncthreads();
    if (threadIdx.x == 0) {
        float S = 0.f, S2 = 0.f;
        for (int i = 0; i < 8; i++) { S += sh1[i]; S2 += sh2[i]; }
        float mean = S * (1.0f / C_);
        float var  = S2 * (1.0f / C_) - mean * mean;
        shm[0] = mean; shm[1] = rsqrtf(var + 1e-5f);
    }
    __syncthreads();
    float mean = shm[0], inv = shm[1];
    float* orow = out + (size_t)row * C_;
    for (int c = threadIdx.x; c < C_; c += 256)
        orow[c] = (xr[c] - mean) * inv * g[c] + b[c];
}

// ---------------- RoPE ----------------
__global__ void rope_kernel(float* __restrict__ qkv) {
    int i = blockIdx.x * 256 + threadIdx.x;
    if (i >= NTOK * H_ * (HD_ / 2)) return;
    int j = i & 31;
    int h = (i >> 5) & 15;
    int n = i >> 9;
    int t = n & (T_ - 1);
    float e = (float)(2 * j) / (float)HD_;
    float invf = 1.0f / powf(10000.0f, e);
    float ang = (float)t * invf;
    float s = sinf(ang), c = cosf(ang);
    float* base = qkv + (size_t)n * (3 * C_) + h * (3 * HD_);
    float q1 = base[j],      q2 = base[j + 32];
    base[j]      = q1 * c - q2 * s;
    base[j + 32] = q1 * s + q2 * c;
    float k1 = base[64 + j], k2 = base[64 + j + 32];
    base[64 + j]      = k1 * c - k2 * s;
    base[64 + j + 32] = k1 * s + k2 * c;
}

// ---------------- causal scores: 64x64 tiles, lower triangle only ----------------
// S[q,k] = 0.125 * sum_d Q[q,d]*K[k,d]. No masking needed: softmax/PV only ever
// read k <= q (plus an explicitly-zeroed diagonal tail).
__global__ void attn_scores_kernel(const float* __restrict__ qkv, float* __restrict__ sc) {
    int bh = blockIdx.z; int b = bh >> 4, h = bh & 15;
    int q0 = blockIdx.y * 64, k0 = blockIdx.x * 64;
    if (k0 > q0) return;   // strictly-upper tiles never read
    __shared__ float Qs[64][65], Ks[64][65];   // transposed: [d][token]
    int tid = threadIdx.x;
    const float* qb = qkv + (size_t)(b * T_ + q0) * (3 * C_) + h * (3 * HD_);
    const float* kb = qkv + (size_t)(b * T_ + k0) * (3 * C_) + h * (3 * HD_) + HD_;
#pragma unroll
    for (int r = 0; r < 4; r++) {
        int idx = tid + r * 256;       // 1024 = 64 tokens * 16 float4
        int tok = idx >> 4, d4 = (idx & 15) * 4;
        float4 vq = *(const float4*)(qb + (size_t)tok * (3 * C_) + d4);
        float4 vk = *(const float4*)(kb + (size_t)tok * (3 * C_) + d4);
        Qs[d4 + 0][tok] = vq.x; Qs[d4 + 1][tok] = vq.y;
        Qs[d4 + 2][tok] = vq.z; Qs[d4 + 3][tok] = vq.w;
        Ks[d4 + 0][tok] = vk.x; Ks[d4 + 1][tok] = vk.y;
        Ks[d4 + 2][tok] = vk.z; Ks[d4 + 3][tok] = vk.w;
    }
    __syncthreads();
    int tx = tid & 15, ty = tid >> 4;
    float acc[4][4] = {};
#pragma unroll
    for (int d = 0; d < 64; d++) {
        float a[4], bb[4];
#pragma unroll
        for (int i = 0; i < 4; i++) a[i]  = Qs[d][ty * 4 + i];
#pragma unroll
        for (int j = 0; j < 4; j++) bb[j] = Ks[d][tx * 4 + j];
#pragma unroll
        for (int i = 0; i < 4; i++)
#pragma unroll
            for (int j = 0; j < 4; j++) acc[i][j] += a[i] * bb[j];
    }
    float* S = sc + (size_t)bh * T_ * T_;
#pragma unroll
    for (int i = 0; i < 4; i++) {
        float* srow = S + (size_t)(q0 + ty * 4 + i) * T_ + k0;
#pragma unroll
        for (int j = 0; j < 4; j++)
            srow[tx * 4 + j] = acc[i][j] * 0.125f;
    }
}

// ---------------- row softmax, bounded to [0,q]; zeroes diagonal tail ----------------
__global__ void softmax_kernel(float* __restrict__ sc) {
    size_t row = blockIdx.x;
    int q = (int)(row & (T_ - 1));
    int len = q + 1;
    int bound = (q | 63) + 1;            // PV reads k < bound for this row's tile
    float* r = sc + row * T_;
    __shared__ float sh[8], shv[1];
    int lane = threadIdx.x & 31, w = threadIdx.x >> 5;
    float mx = -INFINITY;
    for (int k = threadIdx.x; k < len; k += 256) mx = fmaxf(mx, r[k]);
    mx = warp_max(mx);
    if (!lane) sh[w] = mx;
    __syncthreads();
    if (threadIdx.x == 0) {
        float m = sh[0];
        for (int i = 1; i < 8; i++) m = fmaxf(m, sh[i]);
        shv[0] = m;
    }
    __syncthreads();
    float M = shv[0];
    float s = 0.f;
    for (int k = threadIdx.x; k < len; k += 256) { float e = expf(r[k] - M); r[k] = e; s += e; }
    s = warp_sum(s);
    if (!lane) sh[w] = s;
    __syncthreads();
    if (threadIdx.x == 0) {
        float S = 0.f;
        for (int i = 0; i < 8; i++) S += sh[i];
        shv[0] = 1.0f / S;
    }
    __syncthreads();
    float inv = shv[0];
    for (int k = threadIdx.x; k < len; k += 256) r[k] *= inv;
    for (int k = len + threadIdx.x; k < bound; k += 256) r[k] = 0.f;   // diagonal tail
}

// ---------------- P @ V, k-range bounded to the causal extent ----------------
__global__ void attn_pv_kernel(const float* __restrict__ sc, const float* __restrict__ qkv,
                               float* __restrict__ out) {
    int z = blockIdx.z; int b = z >> 4, h = z & 15;
    const float* A  = sc + (size_t)z * T_ * T_;
    const float* Bp = qkv + (size_t)b * T_ * (3 * C_) + h * (3 * HD_) + 2 * HD_;
    float* Cp = out + (size_t)b * T_ * C_ + h * HD_;
    __shared__ float As[16][68];
    __shared__ float Bs[16][68];
    int tid = threadIdx.x;
    int tx = tid & 15, ty = tid >> 4;
    int m0 = blockIdx.y * 64;
    int kmax = m0 + 64;   // P[q,k]=0 for k in (q, m0+63]; k>m0+63 never contributes
    float acc[4][4] = {};
    for (int k0 = 0; k0 < kmax; k0 += 16) {
#pragma unroll
        for (int r = 0; r < 4; r++) {
            int idx = tid + r * 256;
            As[idx & 15][idx >> 4] = A[(size_t)(m0 + (idx >> 4)) * T_ + k0 + (idx & 15)];
        }
#pragma unroll
        for (int r = 0; r < 4; r++) {
            int idx = tid + r * 256;
            Bs[idx >> 6][idx & 63] = Bp[(size_t)(k0 + (idx >> 6)) * (3 * C_) + (idx & 63)];
        }
        __syncthreads();
#pragma unroll
        for (int kk = 0; kk < 16; kk++) {
            float a[4], bb[4];
#pragma unroll
            for (int i = 0; i < 4; i++) a[i]  = As[kk][ty * 4 + i];
#pragma unroll
            for (int j = 0; j < 4; j++) bb[j] = Bs[kk][tx * 4 + j];
#pragma unroll
            for (int i = 0; i < 4; i++)
#pragma unroll
                for (int j = 0; j < 4; j++) acc[i][j] += a[i] * bb[j];
        }
        __syncthreads();
    }
#pragma unroll
    for (int i = 0; i < 4; i++)
#pragma unroll
        for (int j = 0; j < 4; j++)
            Cp[(size_t)(m0 + ty * 4 + i) * C_ + tx * 4 + j] = acc[i][j];
}

// ---------------- gating ----------------
__global__ void gate_kernel(const float* __restrict__ x, const float* __restrict__ gw,
                            float* __restrict__ gates, int* __restrict__ top) {
    int n = blockIdx.x;
    int lane = threadIdx.x & 31, w = threadIdx.x >> 5;
    const float* xr = x + (size_t)n * C_;
    float acc = 0.f;
    for (int c = lane; c < C_; c += 32) acc += xr[c] * gw[(size_t)c * E_ + w];
    acc = warp_sum(acc);
    __shared__ float sl[E_];
    if (!lane) sl[w] = acc;
    __syncthreads();
    if (threadIdx.x == 0) {
        float p[E_];
        float m = sl[0];
        for (int e = 1; e < E_; e++) m = fmaxf(m, sl[e]);
        float s = 0.f;
        for (int e = 0; e < E_; e++) { p[e] = expf(sl[e] - m); s += p[e]; }
        float inv = 1.0f / s;
        for (int e = 0; e < E_; e++) { p[e] *= inv; gates[(size_t)n * E_ + e] = p[e]; }
        int i0 = 0;
        for (int e = 1; e < E_; e++) if (p[e] > p[i0]) i0 = e;
        int i1 = -1;
        for (int e = 0; e < E_; e++) {
            if (e == i0) continue;
            if (i1 < 0 || p[e] > p[i1]) i1 = e;
        }
        top[2 * n] = i0; top[2 * n + 1] = i1;
    }
}

// ---------------- routing ----------------
__global__ void route_kernel(const int* __restrict__ top, int* __restrict__ slot) {
    int e = threadIdx.x;
    if (e >= E_) return;
    int cnt = 0;
    for (int n = 0; n < NTOK; n++) {
        if (top[2 * n] == e)     { slot[2 * n]     = (cnt < CAP) ? cnt : -1; cnt++; }
        if (top[2 * n + 1] == e) { slot[2 * n + 1] = (cnt < CAP) ? cnt : -1; cnt++; }
    }
}

// ---------------- scatter ----------------
__global__ void scatter_kernel(const float* __restrict__ ln, const int* __restrict__ top,
                               const int* __restrict__ slot, float* __restrict__ buf) {
    int n = blockIdx.x;
    const float4* src = (const float4*)(ln + (size_t)n * C_);
#pragma unroll
    for (int kk = 0; kk < 2; kk++) {
        int s = slot[2 * n + kk];
        if (s < 0) continue;
        int e = top[2 * n + kk];
        float4* dst = (float4*)(buf + ((size_t)e * CAPP + s) * C_);
        for (int i = threadIdx.x; i < C_ / 4; i += 256) dst[i] = src[i];
    }
}

// ---------------- combine + residual ----------------
__global__ void combine_kernel(const float* __restrict__ y, const float* __restrict__ gates,
                               const int* __restrict__ top, const int* __restrict__ slot,
                               float* __restrict__ x) {
    int n = blockIdx.x;
    int e0 = top[2 * n], e1 = top[2 * n + 1];
    int s0 = slot[2 * n], s1 = slot[2 * n + 1];
    float w0 = (s0 >= 0) ? gates[(size_t)n * E_ + e0] : 0.f;
    float w1 = (s1 >= 0) ? gates[(size_t)n * E_ + e1] : 0.f;
    const float* y0 = y + ((size_t)e0 * CAPP + (s0 >= 0 ? s0 : 0)) * C_;
    const float* y1 = y + ((size_t)e1 * CAPP + (s1 >= 0 ? s1 : 0)) * C_;
    float* xr = x + (size_t)n * C_;
    for (int c = threadIdx.x; c < C_; c += 256)
        xr[c] += w0 * y0[c] + w1 * y1[c];
}

// ---------------- launch ----------------
extern "C" void kernel_launch(void* const* d_in, const int* in_sizes, int n_in,
                              void* d_out, int out_size) {
    const int*   idx     = (const int*)  d_in[0];
    const float* tok_emb = (const float*)d_in[1];
    const float* ln1_g   = (const float*)d_in[2];
    const float* ln1_b   = (const float*)d_in[3];
    const float* qkv_w   = (const float*)d_in[4];
    const float* proj_w  = (const float*)d_in[5];
    const float* ln2_g   = (const float*)d_in[6];
    const float* ln2_b   = (const float*)d_in[7];
    const float* gate_w  = (const float*)d_in[8];
    const float* w1      = (const float*)d_in[9];
    const float* b1      = (const float*)d_in[10];
    const float* w2      = (const float*)d_in[11];
    const float* b2      = (const float*)d_in[12];
    const float* lnf_g   = (const float*)d_in[13];
    const float* lnf_b   = (const float*)d_in[14];
    const float* lm_head = (const float*)d_in[15];
    float* out = (float*)d_out;

    float *x, *ln, *qkv, *sc, *attn, *gates, *buf, *hbuf, *ybuf;
    int *top, *slot;
    cudaGetSymbolAddress((void**)&x,     g_x);
    cudaGetSymbolAddress((void**)&ln,    g_ln);
    cudaGetSymbolAddress((void**)&qkv,   g_qkv);
    cudaGetSymbolAddress((void**)&sc,    g_scores);
    cudaGetSymbolAddress((void**)&attn,  g_attn);
    cudaGetSymbolAddress((void**)&gates, g_gates);
    cudaGetSymbolAddress((void**)&top,   g_top);
    cudaGetSymbolAddress((void**)&slot,  g_slot);
    cudaGetSymbolAddress((void**)&buf,   g_buf);
    cudaGetSymbolAddress((void**)&hbuf,  g_hbuf);
    cudaGetSymbolAddress((void**)&ybuf,  g_ybuf);

    cudaFuncSetAttribute(mm_mma_kernel, cudaFuncAttributeMaxDynamicSharedMemorySize, MM_SMEM);

    embed_kernel<<<NTOK * C_ / 256, 256>>>(idx, tok_emb, x);

    for (int l = 0; l < L_; l++) {
        // --- attention ---
        ln_kernel<<<NTOK, 256>>>(x, ln1_g + (size_t)l * C_, ln1_b + (size_t)l * C_, ln);
        mm_mma_kernel<<<dim3(NTOK / 128, 3 * C_ / 128, 1), 256, MM_SMEM>>>(
            ln, qkv_w + (size_t)l * C_ * 3 * C_, qkv, nullptr,
            NTOK, 3 * C_, C_, 0, 0, 0, 0, 0, 3);
        rope_kernel<<<(NTOK * H_ * (HD_ / 2) + 255) / 256, 256>>>(qkv);
        attn_scores_kernel<<<dim3(T_ / 64, T_ / 64, B_ * H_), 256>>>(qkv, sc);
        softmax_kernel<<<B_ * H_ * T_, 256>>>(sc);
        attn_pv_kernel<<<dim3(1, T_ / 64, B_ * H_), 256>>>(sc, qkv, attn);
        mm_mma_kernel<<<dim3(NTOK / 128, C_ / 128, 1), 256, MM_SMEM>>>(
            attn, proj_w + (size_t)l * C_ * C_, x, nullptr,
            NTOK, C_, C_, 0, 0, 0, 0, 1, 3);  // += residual

        // --- MoE ---
        int moe_pass = (l == L_ - 1) ? 1 : 3;
        ln_kernel<<<NTOK, 256>>>(x, ln2_g + (size_t)l * C_, ln2_b + (size_t)l * C_, ln);
        gate_kernel<<<NTOK, 256>>>(ln, gate_w + (size_t)l * C_ * E_, gates, top);
        route_kernel<<<1, 32>>>(top, slot);
        scatter_kernel<<<NTOK, 256>>>(ln, top, slot, buf);
        mm_mma_kernel<<<dim3(CAPP / 128, FF_ / 128, E_), 256, MM_SMEM>>>(
            buf, w1 + (size_t)l * E_ * C_ * FF_, hbuf, b1 + (size_t)l * E_ * FF_,
            CAP, FF_, C_, (long)CAPP * C_, (long)C_ * FF_, (long)CAPP * FF_, (long)FF_, 2, moe_pass);
        mm_mma_kernel<<<dim3(CAPP / 128, C_ / 128, E_), 256, MM_SMEM>>>(
            hbuf, w2 + (size_t)l * E_ * FF_ * C_, ybuf, b2 + (size_t)l * E_ * C_,
            CAP, C_, FF_, (long)CAPP * FF_, (long)FF_ * C_, (long)CAPP * C_, (long)C_, 3, moe_pass);
        combine_kernel<<<NTOK, 256>>>(ybuf, gates, top, slot, x);
    }

    ln_kernel<<<NTOK, 256>>>(x, lnf_g, lnf_b, ln);
    mm_mma_kernel<<<dim3(NTOK / 128, V_ / 128, 1), 256, MM_SMEM>>>(
        ln, lm_head, out, nullptr, NTOK, V_, C_, 0, 0, 0, 0, 0, 1);
}

// round 9
// speedup vs baseline: 2.2405x; 1.1116x over previous
#include <cuda_runtime.h>
#include <math.h>
#include <stdint.h>

#define B_   2
#define T_   1024
#define C_   1024
#define H_   16
#define HD_  64
#define L_   2
#define E_   8
#define FF_  4096
#define V_   32000
#define NTOK (B_ * T_)
#define CAP  320   // ceil(1.25 * 2048 / 8); 320 = 5 * 64 -> exact 64-row tiling

// ---------------- scratch (static device globals; no allocations) ----------------
__device__ float g_x[NTOK * C_];
__device__ float g_ln[NTOK * C_];
__device__ float g_qkv[NTOK * 3 * C_];
__device__ float g_attn[NTOK * C_];
__device__ float g_gates[NTOK * E_];
__device__ int   g_top[NTOK * 2];
__device__ int   g_slot[NTOK * 2];
__device__ float g_buf [E_ * CAP * C_];
__device__ float g_hbuf[E_ * CAP * FF_];
__device__ float g_ybuf[E_ * CAP * C_];

// ---------------- helpers ----------------
__device__ __forceinline__ float warp_sum(float v) {
#pragma unroll
    for (int o = 16; o; o >>= 1) v += __shfl_xor_sync(0xffffffffu, v, o);
    return v;
}
__device__ __forceinline__ float gelu_exact(float v) {
    return 0.5f * v * (1.0f + erff(v * 0.70710678118654752f));
}
__device__ __forceinline__ float to_tf32(float v) {
    float o; asm("cvt.rna.tf32.f32 %0, %1;" : "=f"(o) : "f"(v)); return o;
}

#define MMA_TF32(accp, a0, a1, a2, a3, b0, b1)                                  \
    asm volatile(                                                               \
        "mma.sync.aligned.m16n8k8.row.col.f32.tf32.tf32.f32 "                   \
        "{%0,%1,%2,%3}, {%4,%5,%6,%7}, {%8,%9}, {%0,%1,%2,%3};"                 \
        : "+f"((accp)[0]), "+f"((accp)[1]), "+f"((accp)[2]), "+f"((accp)[3])    \
        : "r"(a0), "r"(a1), "r"(a2), "r"(a3), "r"(b0), "r"(b1))

// ======== TF32 tensor-core GEMM (1-pass or 3-pass), templated on M-tile ========
// C[Mv,N] = A[M,K] @ B[K,N], batched over blockIdx.z. MTxN128 tile per CTA,
// 256 threads (8 warps as 2x4, warp tile (MT/2)x32), K-chunks of 32.
#define LDA_ 36
#define LDB_ 136
#define BBUF (32 * LDB_)

template<int MT>
__global__ void __launch_bounds__(256, MT == 64 ? 2 : 1)
mm_mma_kernel(const float* __restrict__ A, const float* __restrict__ B,
              float* __restrict__ C, const float* __restrict__ bias,
              int Mv, int N, int K,
              long sA, long sB, long sC, long sBias, int ep, int npass)
{
    constexpr int MTW  = MT / 32;          // m-subtiles per warp (4 or 2)
    constexpr int AIT  = MT / 32;          // A prefetch float4 iters (4 or 2)
    constexpr int ABUF = MT * LDA_;
    constexpr int BUFSZ = ABUF + BBUF;
    extern __shared__ float sm[];
    int tid = threadIdx.x, lane = tid & 31, wid = tid >> 5;
    int wm = wid & 1, wn = wid >> 1;
    int r_lo = lane >> 2, c_lo = lane & 3;
    int z = blockIdx.z;
    A += (long)z * sA; B += (long)z * sB; C += (long)z * sC;
    const float* bp = bias ? bias + (long)z * sBias : nullptr;
    int m0 = blockIdx.x * MT, n0 = blockIdx.y * 128;

    float acc[MTW][4][4];
#pragma unroll
    for (int i = 0; i < MTW; i++)
#pragma unroll
        for (int j = 0; j < 4; j++)
#pragma unroll
            for (int k = 0; k < 4; k++) acc[i][j][k] = 0.f;

    float4 pa[AIT], pb[4];

    auto prefetch = [&](int i) {
        int k0 = i << 5;
#pragma unroll
        for (int it = 0; it < AIT; it++) {
            int idx = tid + it * 256;
            int m = idx >> 3, f4 = idx & 7;
            pa[it] = *(const float4*)(A + (size_t)(m0 + m) * K + k0 + f4 * 4);
        }
#pragma unroll
        for (int it = 0; it < 4; it++) {
            int idx = tid + it * 256;
            int k = idx >> 5, f4 = idx & 31;
            pb[it] = *(const float4*)(B + (size_t)(k0 + k) * N + n0 + f4 * 4);
        }
    };
    auto cstore = [&](int s) {
        float* smA = sm + s * BUFSZ;
        float* smB = smA + ABUF;
#pragma unroll
        for (int it = 0; it < AIT; it++) {
            int idx = tid + it * 256;
            int m = idx >> 3, f4 = idx & 7;
            *(float4*)(smA + m * LDA_ + f4 * 4) = pa[it];
        }
#pragma unroll
        for (int it = 0; it < 4; it++) {
            int idx = tid + it * 256;
            int k = idx >> 5, f4 = idx & 31;
            *(float4*)(smB + k * LDB_ + f4 * 4) = pb[it];
        }
    };

    int nch = K >> 5;
    prefetch(0);
    cstore(0);
    __syncthreads();
    for (int i = 0; i < nch; i++) {
        if (i + 1 < nch) prefetch(i + 1);
        {
            float* smA = sm + (i & 1) * BUFSZ;
            float* smB = smA + ABUF;
#pragma unroll
            for (int ks = 0; ks < 4; ks++) {
                float ar[MTW][4], br[4][2];
                uint32_t ah[MTW][4], bh[4][2];
#pragma unroll
                for (int mt = 0; mt < MTW; mt++) {
                    const float* ab = smA + (wm * (MT / 2) + mt * 16 + r_lo) * LDA_ + ks * 8 + c_lo;
                    ar[mt][0] = ab[0];
                    ar[mt][1] = ab[8 * LDA_];
                    ar[mt][2] = ab[4];
                    ar[mt][3] = ab[8 * LDA_ + 4];
#pragma unroll
                    for (int q = 0; q < 4; q++) ah[mt][q] = __float_as_uint(to_tf32(ar[mt][q]));
                }
#pragma unroll
                for (int nt = 0; nt < 4; nt++) {
                    const float* bb = smB + (ks * 8 + c_lo) * LDB_ + wn * 32 + nt * 8 + r_lo;
                    br[nt][0] = bb[0];
                    br[nt][1] = bb[4 * LDB_];
                    bh[nt][0] = __float_as_uint(to_tf32(br[nt][0]));
                    bh[nt][1] = __float_as_uint(to_tf32(br[nt][1]));
                }
#pragma unroll
                for (int mt = 0; mt < MTW; mt++)
#pragma unroll
                    for (int nt = 0; nt < 4; nt++)
                        MMA_TF32(acc[mt][nt], ah[mt][0], ah[mt][1], ah[mt][2], ah[mt][3],
                                 bh[nt][0], bh[nt][1]);
                if (npass == 3) {
#pragma unroll
                    for (int nt = 0; nt < 4; nt++) {
                        br[nt][0] = to_tf32(br[nt][0] - __uint_as_float(bh[nt][0]));
                        br[nt][1] = to_tf32(br[nt][1] - __uint_as_float(bh[nt][1]));
                    }
#pragma unroll
                    for (int mt = 0; mt < MTW; mt++)
#pragma unroll
                        for (int nt = 0; nt < 4; nt++)
                            MMA_TF32(acc[mt][nt], ah[mt][0], ah[mt][1], ah[mt][2], ah[mt][3],
                                     __float_as_uint(br[nt][0]), __float_as_uint(br[nt][1]));
#pragma unroll
                    for (int mt = 0; mt < MTW; mt++)
#pragma unroll
                        for (int q = 0; q < 4; q++)
                            ar[mt][q] = to_tf32(ar[mt][q] - __uint_as_float(ah[mt][q]));
#pragma unroll
                    for (int mt = 0; mt < MTW; mt++)
#pragma unroll
                        for (int nt = 0; nt < 4; nt++)
                            MMA_TF32(acc[mt][nt],
                                     __float_as_uint(ar[mt][0]), __float_as_uint(ar[mt][1]),
                                     __float_as_uint(ar[mt][2]), __float_as_uint(ar[mt][3]),
                                     bh[nt][0], bh[nt][1]);
                }
            }
        }
        __syncthreads();
        if (i + 1 < nch) {
            cstore((i + 1) & 1);
            __syncthreads();
        }
    }

    // epilogue
    int rbase = m0 + wm * (MT / 2) + (lane >> 2);
    int cbase = n0 + wn * 32 + (lane & 3) * 2;
#pragma unroll
    for (int mt = 0; mt < MTW; mt++) {
#pragma unroll
        for (int half = 0; half < 2; half++) {
            int row = rbase + mt * 16 + half * 8;
            if (row >= Mv) continue;
#pragma unroll
            for (int nt = 0; nt < 4; nt++) {
                int col = cbase + nt * 8;
                float x0 = acc[mt][nt][half * 2 + 0];
                float x1 = acc[mt][nt][half * 2 + 1];
                if (ep == 2)      { x0 = gelu_exact(x0 + bp[col]); x1 = gelu_exact(x1 + bp[col + 1]); }
                else if (ep == 3) { x0 += bp[col]; x1 += bp[col + 1]; }
                float* cp = C + (size_t)row * N + col;
                if (ep == 1) { x0 += cp[0]; x1 += cp[1]; }
                float2 o; o.x = x0; o.y = x1;
                *(float2*)cp = o;
            }
        }
    }
}
#define MM_SMEM_128 (2 * (128 * LDA_ + BBUF) * 4)
#define MM_SMEM_64  (2 * (64  * LDA_ + BBUF) * 4)

// ---------------- embedding gather ----------------
__global__ void embed_kernel(const int* __restrict__ idx, const float* __restrict__ emb,
                             float* __restrict__ x) {
    int i = blockIdx.x * 256 + threadIdx.x;
    int n = i >> 10, c = i & 1023;
    x[i] = emb[(size_t)idx[n] * C_ + c];
}

// ---------------- layernorm ----------------
__global__ void ln_kernel(const float* __restrict__ x, const float* __restrict__ g,
                          const float* __restrict__ b, float* __restrict__ out) {
    int row = blockIdx.x;
    const float* xr = x + (size_t)row * C_;
    float s = 0.f, s2 = 0.f;
    for (int c = threadIdx.x; c < C_; c += 256) { float v = xr[c]; s += v; s2 += v * v; }
    __shared__ float sh1[8], sh2[8], shm[2];
    int lane = threadIdx.x & 31, w = threadIdx.x >> 5;
    s = warp_sum(s); s2 = warp_sum(s2);
    if (!lane) { sh1[w] = s; sh2[w] = s2; }
    __syncthreads();
    if (threadIdx.x == 0) {
        float S = 0.f, S2 = 0.f;
        for (int i = 0; i < 8; i++) { S += sh1[i]; S2 += sh2[i]; }
        float mean = S * (1.0f / C_);
        float var  = S2 * (1.0f / C_) - mean * mean;
        shm[0] = mean; shm[1] = rsqrtf(var + 1e-5f);
    }
    __syncthreads();
    float mean = shm[0], inv = shm[1];
    float* orow = out + (size_t)row * C_;
    for (int c = threadIdx.x; c < C_; c += 256)
        orow[c] = (xr[c] - mean) * inv * g[c] + b[c];
}

// ---------------- RoPE ----------------
__global__ void rope_kernel(float* __restrict__ qkv) {
    int i = blockIdx.x * 256 + threadIdx.x;
    if (i >= NTOK * H_ * (HD_ / 2)) return;
    int j = i & 31;
    int h = (i >> 5) & 15;
    int n = i >> 9;
    int t = n & (T_ - 1);
    float e = (float)(2 * j) / (float)HD_;
    float invf = 1.0f / powf(10000.0f, e);
    float ang = (float)t * invf;
    float s = sinf(ang), c = cosf(ang);
    float* base = qkv + (size_t)n * (3 * C_) + h * (3 * HD_);
    float q1 = base[j],      q2 = base[j + 32];
    base[j]      = q1 * c - q2 * s;
    base[j + 32] = q1 * s + q2 * c;
    float k1 = base[64 + j], k2 = base[64 + j + 32];
    base[64 + j]      = k1 * c - k2 * s;
    base[64 + j + 32] = k1 * s + k2 * c;
}

// ---------------- fused flash attention (scores + online softmax + PV) ----------------
// One CTA per (bh, 64-row q-block). fp32 SIMT, exact-math reassociation of the
// reference softmax. No scores buffer, no separate softmax/PV kernels.
#define FA_QS  0
#define FA_KS  (64 * 65)
#define FA_VS  (FA_KS + 64 * 65)
#define FA_PS  (FA_VS + 64 * 68)
#define FA_SMEM ((FA_PS + 64 * 68) * 4)

__global__ void __launch_bounds__(256, 1)
flash_attn_kernel(const float* __restrict__ qkv, float* __restrict__ out) {
    extern __shared__ float fs[];
    float* Qs = fs + FA_QS;   // [d][i], pitch 65
    float* Ks = fs + FA_KS;   // [d][j], pitch 65
    float* Vs = fs + FA_VS;   // [j][d], pitch 68
    float* Ps = fs + FA_PS;   // [i][j], pitch 68
    int bh = blockIdx.y; int b = bh >> 4, h = bh & 15;
    int qb = (int)gridDim.x - 1 - (int)blockIdx.x;   // heavy blocks first
    int q0 = qb * 64;
    int tid = threadIdx.x, tx = tid & 15, ty = tid >> 4;

    const float* qbase = qkv + (size_t)(b * T_ + q0) * (3 * C_) + h * (3 * HD_);
#pragma unroll
    for (int r = 0; r < 4; r++) {
        int idx = tid + r * 256;
        int tok = idx >> 4, d4 = (idx & 15) * 4;
        float4 v = *(const float4*)(qbase + (size_t)tok * (3 * C_) + d4);
        Qs[(d4 + 0) * 65 + tok] = v.x; Qs[(d4 + 1) * 65 + tok] = v.y;
        Qs[(d4 + 2) * 65 + tok] = v.z; Qs[(d4 + 3) * 65 + tok] = v.w;
    }

    float o[4][4];
    float mrow[4], lrow[4];
#pragma unroll
    for (int i = 0; i < 4; i++) {
        mrow[i] = -1e30f; lrow[i] = 0.f;
#pragma unroll
        for (int j = 0; j < 4; j++) o[i][j] = 0.f;
    }

    for (int kb = 0; kb <= qb; kb++) {
        int k0 = kb * 64;
        __syncthreads();   // previous iter's Vs/Ps reads done; Qs ready (first iter)
        const float* kbase = qkv + (size_t)(b * T_ + k0) * (3 * C_) + h * (3 * HD_) + HD_;
        const float* vbase = kbase + HD_;
#pragma unroll
        for (int r = 0; r < 4; r++) {
            int idx = tid + r * 256;
            int tok = idx >> 4, d4 = (idx & 15) * 4;
            float4 vk = *(const float4*)(kbase + (size_t)tok * (3 * C_) + d4);
            Ks[(d4 + 0) * 65 + tok] = vk.x; Ks[(d4 + 1) * 65 + tok] = vk.y;
            Ks[(d4 + 2) * 65 + tok] = vk.z; Ks[(d4 + 3) * 65 + tok] = vk.w;
            float4 vv = *(const float4*)(vbase + (size_t)tok * (3 * C_) + d4);
            *(float4*)(Vs + tok * 68 + d4) = vv;
        }
        __syncthreads();

        // S tile (4x4 per thread)
        float s[4][4];
#pragma unroll
        for (int i = 0; i < 4; i++)
#pragma unroll
            for (int j = 0; j < 4; j++) s[i][j] = 0.f;
#pragma unroll
        for (int d = 0; d < 64; d++) {
            float a[4], bb[4];
#pragma unroll
            for (int i = 0; i < 4; i++) a[i]  = Qs[d * 65 + ty * 4 + i];
#pragma unroll
            for (int j = 0; j < 4; j++) bb[j] = Ks[d * 65 + tx * 4 + j];
#pragma unroll
            for (int i = 0; i < 4; i++)
#pragma unroll
                for (int j = 0; j < 4; j++) s[i][j] += a[i] * bb[j];
        }
        bool diag = (kb == qb);
#pragma unroll
        for (int i = 0; i < 4; i++)
#pragma unroll
            for (int j = 0; j < 4; j++) {
                s[i][j] *= 0.125f;
                if (diag && (tx * 4 + j) > (ty * 4 + i)) s[i][j] = -1e30f;
            }

        // online softmax update per row (16 threads per row, redundant compute)
#pragma unroll
        for (int i = 0; i < 4; i++) {
            float rm = fmaxf(fmaxf(s[i][0], s[i][1]), fmaxf(s[i][2], s[i][3]));
#pragma unroll
            for (int off = 1; off < 16; off <<= 1)
                rm = fmaxf(rm, __shfl_xor_sync(0xffffffffu, rm, off));
            float mn = fmaxf(mrow[i], rm);
            float alpha = expf(mrow[i] - mn);
            float rs = 0.f;
#pragma unroll
            for (int j = 0; j < 4; j++) {
                float p = expf(s[i][j] - mn);
                Ps[(ty * 4 + i) * 68 + tx * 4 + j] = p;
                rs += p;
            }
#pragma unroll
            for (int off = 1; off < 16; off <<= 1)
                rs += __shfl_xor_sync(0xffffffffu, rs, off);
            lrow[i] = lrow[i] * alpha + rs;
            mrow[i] = mn;
#pragma unroll
            for (int d = 0; d < 4; d++) o[i][d] *= alpha;
        }
        __syncthreads();

        // O += P @ V
#pragma unroll 4
        for (int kk = 0; kk < 64; kk++) {
            float a[4], v[4];
#pragma unroll
            for (int i = 0; i < 4; i++) a[i] = Ps[(ty * 4 + i) * 68 + kk];
#pragma unroll
            for (int d = 0; d < 4; d++) v[d] = Vs[kk * 68 + tx * 4 + d];
#pragma unroll
            for (int i = 0; i < 4; i++)
#pragma unroll
                for (int d = 0; d < 4; d++) o[i][d] += a[i] * v[d];
        }
    }

    // write O / l
#pragma unroll
    for (int i = 0; i < 4; i++) {
        float linv = 1.0f / lrow[i];
        float4 v;
        v.x = o[i][0] * linv; v.y = o[i][1] * linv;
        v.z = o[i][2] * linv; v.w = o[i][3] * linv;
        *(float4*)(out + (size_t)(b * T_ + q0 + ty * 4 + i) * C_ + h * HD_ + tx * 4) = v;
    }
}

// ---------------- gating ----------------
__global__ void gate_kernel(const float* __restrict__ x, const float* __restrict__ gw,
                            float* __restrict__ gates, int* __restrict__ top) {
    int n = blockIdx.x;
    int lane = threadIdx.x & 31, w = threadIdx.x >> 5;
    const float* xr = x + (size_t)n * C_;
    float acc = 0.f;
    for (int c = lane; c < C_; c += 32) acc += xr[c] * gw[(size_t)c * E_ + w];
    acc = warp_sum(acc);
    __shared__ float sl[E_];
    if (!lane) sl[w] = acc;
    __syncthreads();
    if (threadIdx.x == 0) {
        float p[E_];
        float m = sl[0];
        for (int e = 1; e < E_; e++) m = fmaxf(m, sl[e]);
        float s = 0.f;
        for (int e = 0; e < E_; e++) { p[e] = expf(sl[e] - m); s += p[e]; }
        float inv = 1.0f / s;
        for (int e = 0; e < E_; e++) { p[e] *= inv; gates[(size_t)n * E_ + e] = p[e]; }
        int i0 = 0;
        for (int e = 1; e < E_; e++) if (p[e] > p[i0]) i0 = e;
        int i1 = -1;
        for (int e = 0; e < E_; e++) {
            if (e == i0) continue;
            if (i1 < 0 || p[e] > p[i1]) i1 = e;
        }
        top[2 * n] = i0; top[2 * n + 1] = i1;
    }
}

// ---------------- routing ----------------
__global__ void route_kernel(const int* __restrict__ top, int* __restrict__ slot) {
    int e = threadIdx.x;
    if (e >= E_) return;
    int cnt = 0;
    for (int n = 0; n < NTOK; n++) {
        if (top[2 * n] == e)     { slot[2 * n]     = (cnt < CAP) ? cnt : -1; cnt++; }
        if (top[2 * n + 1] == e) { slot[2 * n + 1] = (cnt < CAP) ? cnt : -1; cnt++; }
    }
}

// ---------------- scatter ----------------
__global__ void scatter_kernel(const float* __restrict__ ln, const int* __restrict__ top,
                               const int* __restrict__ slot, float* __restrict__ buf) {
    int n = blockIdx.x;
    const float4* src = (const float4*)(ln + (size_t)n * C_);
#pragma unroll
    for (int kk = 0; kk < 2; kk++) {
        int s = slot[2 * n + kk];
        if (s < 0) continue;
        int e = top[2 * n + kk];
        float4* dst = (float4*)(buf + ((size_t)e * CAP + s) * C_);
        for (int i = threadIdx.x; i < C_ / 4; i += 256) dst[i] = src[i];
    }
}

// ---------------- combine + residual ----------------
__global__ void combine_kernel(const float* __restrict__ y, const float* __restrict__ gates,
                               const int* __restrict__ top, const int* __restrict__ slot,
                               float* __restrict__ x) {
    int n = blockIdx.x;
    int e0 = top[2 * n], e1 = top[2 * n + 1];
    int s0 = slot[2 * n], s1 = slot[2 * n + 1];
    float w0 = (s0 >= 0) ? gates[(size_t)n * E_ + e0] : 0.f;
    float w1 = (s1 >= 0) ? gates[(size_t)n * E_ + e1] : 0.f;
    const float* y0 = y + ((size_t)e0 * CAP + (s0 >= 0 ? s0 : 0)) * C_;
    const float* y1 = y + ((size_t)e1 * CAP + (s1 >= 0 ? s1 : 0)) * C_;
    float* xr = x + (size_t)n * C_;
    for (int c = threadIdx.x; c < C_; c += 256)
        xr[c] += w0 * y0[c] + w1 * y1[c];
}

// ---------------- launch ----------------
extern "C" void kernel_launch(void* const* d_in, const int* in_sizes, int n_in,
                              void* d_out, int out_size) {
    const int*   idx     = (const int*)  d_in[0];
    const float* tok_emb = (const float*)d_in[1];
    const float* ln1_g   = (const float*)d_in[2];
    const float* ln1_b   = (const float*)d_in[3];
    const float* qkv_w   = (const float*)d_in[4];
    const float* proj_w  = (const float*)d_in[5];
    const float* ln2_g   = (const float*)d_in[6];
    const float* ln2_b   = (const float*)d_in[7];
    const float* gate_w  = (const float*)d_in[8];
    const float* w1      = (const float*)d_in[9];
    const float* b1      = (const float*)d_in[10];
    const float* w2      = (const float*)d_in[11];
    const float* b2      = (const float*)d_in[12];
    const float* lnf_g   = (const float*)d_in[13];
    const float* lnf_b   = (const float*)d_in[14];
    const float* lm_head = (const float*)d_in[15];
    float* out = (float*)d_out;

    float *x, *ln, *qkv, *attn, *gates, *buf, *hbuf, *ybuf;
    int *top, *slot;
    cudaGetSymbolAddress((void**)&x,     g_x);
    cudaGetSymbolAddress((void**)&ln,    g_ln);
    cudaGetSymbolAddress((void**)&qkv,   g_qkv);
    cudaGetSymbolAddress((void**)&attn,  g_attn);
    cudaGetSymbolAddress((void**)&gates, g_gates);
    cudaGetSymbolAddress((void**)&top,   g_top);
    cudaGetSymbolAddress((void**)&slot,  g_slot);
    cudaGetSymbolAddress((void**)&buf,   g_buf);
    cudaGetSymbolAddress((void**)&hbuf,  g_hbuf);
    cudaGetSymbolAddress((void**)&ybuf,  g_ybuf);

    cudaFuncSetAttribute(mm_mma_kernel<128>, cudaFuncAttributeMaxDynamicSharedMemorySize, MM_SMEM_128);
    cudaFuncSetAttribute(mm_mma_kernel<64>,  cudaFuncAttributeMaxDynamicSharedMemorySize, MM_SMEM_64);
    cudaFuncSetAttribute(flash_attn_kernel,  cudaFuncAttributeMaxDynamicSharedMemorySize, FA_SMEM);

    embed_kernel<<<NTOK * C_ / 256, 256>>>(idx, tok_emb, x);

    for (int l = 0; l < L_; l++) {
        // --- attention ---
        ln_kernel<<<NTOK, 256>>>(x, ln1_g + (size_t)l * C_, ln1_b + (size_t)l * C_, ln);
        mm_mma_kernel<128><<<dim3(NTOK / 128, 3 * C_ / 128, 1), 256, MM_SMEM_128>>>(
            ln, qkv_w + (size_t)l * C_ * 3 * C_, qkv, nullptr,
            NTOK, 3 * C_, C_, 0, 0, 0, 0, 0, 3);
        rope_kernel<<<(NTOK * H_ * (HD_ / 2) + 255) / 256, 256>>>(qkv);
        flash_attn_kernel<<<dim3(T_ / 64, B_ * H_), 256, FA_SMEM>>>(qkv, attn);
        mm_mma_kernel<128><<<dim3(NTOK / 128, C_ / 128, 1), 256, MM_SMEM_128>>>(
            attn, proj_w + (size_t)l * C_ * C_, x, nullptr,
            NTOK, C_, C_, 0, 0, 0, 0, 1, 3);  // += residual

        // --- MoE (64-row tiles: exactly CAP=320 rows computed, no padding) ---
        int moe_pass = (l == L_ - 1) ? 1 : 3;
        ln_kernel<<<NTOK, 256>>>(x, ln2_g + (size_t)l * C_, ln2_b + (size_t)l * C_, ln);
        gate_kernel<<<NTOK, 256>>>(ln, gate_w + (size_t)l * C_ * E_, gates, top);
        route_kernel<<<1, 32>>>(top, slot);
        scatter_kernel<<<NTOK, 256>>>(ln, top, slot, buf);
        mm_mma_kernel<64><<<dim3(CAP / 64, FF_ / 128, E_), 256, MM_SMEM_64>>>(
            buf, w1 + (size_t)l * E_ * C_ * FF_, hbuf, b1 + (size_t)l * E_ * FF_,
            CAP, FF_, C_, (long)CAP * C_, (long)C_ * FF_, (long)CAP * FF_, (long)FF_, 2, moe_pass);
        mm_mma_kernel<64><<<dim3(CAP / 64, C_ / 128, E_), 256, MM_SMEM_64>>>(
            hbuf, w2 + (size_t)l * E_ * FF_ * C_, ybuf, b2 + (size_t)l * E_ * C_,
            CAP, C_, FF_, (long)CAP * FF_, (long)FF_ * C_, (long)CAP * C_, (long)C_, 3, moe_pass);
        combine_kernel<<<NTOK, 256>>>(ybuf, gates, top, slot, x);
    }

    ln_kernel<<<NTOK, 256>>>(x, lnf_g, lnf_b, ln);
    mm_mma_kernel<128><<<dim3(NTOK / 128, V_ / 128, 1), 256, MM_SMEM_128>>>(
        ln, lm_head, out, nullptr, NTOK, V_, C_, 0, 0, 0, 0, 0, 1);
}

// round 10
// speedup vs baseline: 2.5372x; 1.1324x over previous
#include <cuda_runtime.h>
#include <cuda_bf16.h>
#include <math.h>
#include <stdint.h>

#define B_   2
#define T_   1024
#define C_   1024
#define H_   16
#define HD_  64
#define L_   2
#define E_   8
#define FF_  4096
#define V_   32000
#define NTOK (B_ * T_)
#define CAP  320   // ceil(1.25 * 2048 / 8); 320 = 5 * 64 -> exact 64-row tiling

// ---------------- scratch (static device globals; no allocations) ----------------
__device__ float g_x[NTOK * C_];
__device__ float g_ln[NTOK * C_];
__device__ float g_qkv[NTOK * 3 * C_];
__device__ float g_attn[NTOK * C_];
__device__ float g_gates[NTOK * E_];
__device__ int   g_top[NTOK * 2];
__device__ int   g_slot[NTOK * 2];
__device__ float g_buf [E_ * CAP * C_];
__device__ float g_hbuf[E_ * CAP * FF_];
__device__ float g_ybuf[E_ * CAP * C_];

// ---------------- helpers ----------------
__device__ __forceinline__ float warp_sum(float v) {
#pragma unroll
    for (int o = 16; o; o >>= 1) v += __shfl_xor_sync(0xffffffffu, v, o);
    return v;
}
__device__ __forceinline__ float gelu_exact(float v) {
    return 0.5f * v * (1.0f + erff(v * 0.70710678118654752f));
}
__device__ __forceinline__ float to_tf32(float v) {
    float o; asm("cvt.rna.tf32.f32 %0, %1;" : "=f"(o) : "f"(v)); return o;
}
// round-to-nearest bf16 of v, back as float
__device__ __forceinline__ float bf_hi(float v) {
    return __bfloat162float(__float2bfloat16(v));
}
// pack {lo half = a, hi half = b} with rn rounding
__device__ __forceinline__ uint32_t pack_bf2(float a, float b) {
    uint32_t r;
    asm("cvt.rn.bf16x2.f32 %0, %1, %2;" : "=r"(r) : "f"(b), "f"(a));
    return r;
}
// split a k-pair (x0 even-k, x1 odd-k) into rounded hi/lo bf16x2 words
__device__ __forceinline__ void split_pack(float x0, float x1, uint32_t& hi, uint32_t& lo) {
    float h0 = bf_hi(x0), h1 = bf_hi(x1);
    hi = pack_bf2(h0, h1);
    lo = pack_bf2(x0 - h0, x1 - h1);
}

#define MMA_TF32(accp, a0, a1, a2, a3, b0, b1)                                  \
    asm volatile(                                                               \
        "mma.sync.aligned.m16n8k8.row.col.f32.tf32.tf32.f32 "                   \
        "{%0,%1,%2,%3}, {%4,%5,%6,%7}, {%8,%9}, {%0,%1,%2,%3};"                 \
        : "+f"((accp)[0]), "+f"((accp)[1]), "+f"((accp)[2]), "+f"((accp)[3])    \
        : "r"(a0), "r"(a1), "r"(a2), "r"(a3), "r"(b0), "r"(b1))

#define MMA_BF16(accp, a0, a1, a2, a3, b0, b1)                                  \
    asm volatile(                                                               \
        "mma.sync.aligned.m16n8k16.row.col.f32.bf16.bf16.f32 "                  \
        "{%0,%1,%2,%3}, {%4,%5,%6,%7}, {%8,%9}, {%0,%1,%2,%3};"                 \
        : "+f"((accp)[0]), "+f"((accp)[1]), "+f"((accp)[2]), "+f"((accp)[3])    \
        : "r"(a0), "r"(a1), "r"(a2), "r"(a3), "r"(b0), "r"(b1))

// ======== tensor-core GEMM: tf32 (1/3-pass) or bf16x3, templated on M-tile ========
// C[Mv,N] = A[M,K] @ B[K,N], batched over blockIdx.z. MTxN128 tile per CTA,
// 256 threads (8 warps as 2x4, warp tile (MT/2)x32), K-chunks of 32.
// Raw fp32 in smem; splits happen at fragment-load time.
// BF16 path: rounded 3-term bf16 compensation (err ~3*2^-18/product) at half the
// instruction count of tf32x3 -- used for routing-critical GEMMs.
template<int MT, bool BF16>
__global__ void __launch_bounds__(256, MT == 64 ? 2 : 1)
mm_mma_kernel(const float* __restrict__ A, const float* __restrict__ B,
              float* __restrict__ C, const float* __restrict__ bias,
              int Mv, int N, int K,
              long sA, long sB, long sC, long sBias, int ep, int npass)
{
    constexpr int LDA = BF16 ? 40 : 36;    // conflict-free for each access shape
    constexpr int LDB = BF16 ? 132 : 136;
    constexpr int MTW  = MT / 32;
    constexpr int AIT  = MT / 32;
    constexpr int ABUF = MT * LDA;
    constexpr int BUFSZ = ABUF + 32 * LDB;
    extern __shared__ float sm[];
    int tid = threadIdx.x, lane = tid & 31, wid = tid >> 5;
    int wm = wid & 1, wn = wid >> 1;
    int r_lo = lane >> 2, c_lo = lane & 3;
    int z = blockIdx.z;
    A += (long)z * sA; B += (long)z * sB; C += (long)z * sC;
    const float* bp = bias ? bias + (long)z * sBias : nullptr;
    int m0 = blockIdx.x * MT, n0 = blockIdx.y * 128;

    float acc[MTW][4][4];
#pragma unroll
    for (int i = 0; i < MTW; i++)
#pragma unroll
        for (int j = 0; j < 4; j++)
#pragma unroll
            for (int k = 0; k < 4; k++) acc[i][j][k] = 0.f;

    float4 pa[AIT], pb[4];

    auto prefetch = [&](int i) {
        int k0 = i << 5;
#pragma unroll
        for (int it = 0; it < AIT; it++) {
            int idx = tid + it * 256;
            int m = idx >> 3, f4 = idx & 7;
            pa[it] = *(const float4*)(A + (size_t)(m0 + m) * K + k0 + f4 * 4);
        }
#pragma unroll
        for (int it = 0; it < 4; it++) {
            int idx = tid + it * 256;
            int k = idx >> 5, f4 = idx & 31;
            pb[it] = *(const float4*)(B + (size_t)(k0 + k) * N + n0 + f4 * 4);
        }
    };
    auto cstore = [&](int s) {
        float* smA = sm + s * BUFSZ;
        float* smB = smA + ABUF;
#pragma unroll
        for (int it = 0; it < AIT; it++) {
            int idx = tid + it * 256;
            int m = idx >> 3, f4 = idx & 7;
            *(float4*)(smA + m * LDA + f4 * 4) = pa[it];
        }
#pragma unroll
        for (int it = 0; it < 4; it++) {
            int idx = tid + it * 256;
            int k = idx >> 5, f4 = idx & 31;
            *(float4*)(smB + k * LDB + f4 * 4) = pb[it];
        }
    };

    int nch = K >> 5;
    prefetch(0);
    cstore(0);
    __syncthreads();
    for (int i = 0; i < nch; i++) {
        if (i + 1 < nch) prefetch(i + 1);
        {
            float* smA = sm + (i & 1) * BUFSZ;
            float* smB = smA + ABUF;
            if constexpr (BF16) {
                // two k16 slabs per 32-chunk; 3 bf16 mma per (mt,nt) per slab
#pragma unroll
                for (int ks = 0; ks < 2; ks++) {
                    int kb = ks * 16 + 2 * c_lo;
                    uint32_t ah[MTW][4], al[MTW][4], bh[4][2], bl[4][2];
#pragma unroll
                    for (int mt = 0; mt < MTW; mt++) {
                        const float* ab = smA + (wm * (MT / 2) + mt * 16 + r_lo) * LDA + kb;
                        float2 p0 = *(const float2*)ab;               // (r,   k..k+1)
                        float2 p1 = *(const float2*)(ab + 8 * LDA);   // (r+8, k..k+1)
                        float2 p2 = *(const float2*)(ab + 8);         // (r,   k+8..k+9)
                        float2 p3 = *(const float2*)(ab + 8 * LDA + 8);
                        split_pack(p0.x, p0.y, ah[mt][0], al[mt][0]);
                        split_pack(p1.x, p1.y, ah[mt][1], al[mt][1]);
                        split_pack(p2.x, p2.y, ah[mt][2], al[mt][2]);
                        split_pack(p3.x, p3.y, ah[mt][3], al[mt][3]);
                    }
#pragma unroll
                    for (int nt = 0; nt < 4; nt++) {
                        const float* bb = smB + kb * LDB + wn * 32 + nt * 8 + r_lo;
                        split_pack(bb[0],       bb[LDB],     bh[nt][0], bl[nt][0]);
                        split_pack(bb[8 * LDB], bb[9 * LDB], bh[nt][1], bl[nt][1]);
                    }
#pragma unroll
                    for (int mt = 0; mt < MTW; mt++)
#pragma unroll
                        for (int nt = 0; nt < 4; nt++) {
                            MMA_BF16(acc[mt][nt], ah[mt][0], ah[mt][1], ah[mt][2], ah[mt][3],
                                     bh[nt][0], bh[nt][1]);
                            MMA_BF16(acc[mt][nt], ah[mt][0], ah[mt][1], ah[mt][2], ah[mt][3],
                                     bl[nt][0], bl[nt][1]);
                            MMA_BF16(acc[mt][nt], al[mt][0], al[mt][1], al[mt][2], al[mt][3],
                                     bh[nt][0], bh[nt][1]);
                        }
                }
            } else {
#pragma unroll
                for (int ks = 0; ks < 4; ks++) {
                    float ar[MTW][4], br[4][2];
                    uint32_t ah[MTW][4], bh[4][2];
#pragma unroll
                    for (int mt = 0; mt < MTW; mt++) {
                        const float* ab = smA + (wm * (MT / 2) + mt * 16 + r_lo) * LDA + ks * 8 + c_lo;
                        ar[mt][0] = ab[0];
                        ar[mt][1] = ab[8 * LDA];
                        ar[mt][2] = ab[4];
                        ar[mt][3] = ab[8 * LDA + 4];
#pragma unroll
                        for (int q = 0; q < 4; q++) ah[mt][q] = __float_as_uint(to_tf32(ar[mt][q]));
                    }
#pragma unroll
                    for (int nt = 0; nt < 4; nt++) {
                        const float* bb = smB + (ks * 8 + c_lo) * LDB + wn * 32 + nt * 8 + r_lo;
                        br[nt][0] = bb[0];
                        br[nt][1] = bb[4 * LDB];
                        bh[nt][0] = __float_as_uint(to_tf32(br[nt][0]));
                        bh[nt][1] = __float_as_uint(to_tf32(br[nt][1]));
                    }
#pragma unroll
                    for (int mt = 0; mt < MTW; mt++)
#pragma unroll
                        for (int nt = 0; nt < 4; nt++)
                            MMA_TF32(acc[mt][nt], ah[mt][0], ah[mt][1], ah[mt][2], ah[mt][3],
                                     bh[nt][0], bh[nt][1]);
                    if (npass == 3) {
#pragma unroll
                        for (int nt = 0; nt < 4; nt++) {
                            br[nt][0] = to_tf32(br[nt][0] - __uint_as_float(bh[nt][0]));
                            br[nt][1] = to_tf32(br[nt][1] - __uint_as_float(bh[nt][1]));
                        }
#pragma unroll
                        for (int mt = 0; mt < MTW; mt++)
#pragma unroll
                            for (int nt = 0; nt < 4; nt++)
                                MMA_TF32(acc[mt][nt], ah[mt][0], ah[mt][1], ah[mt][2], ah[mt][3],
                                         __float_as_uint(br[nt][0]), __float_as_uint(br[nt][1]));
#pragma unroll
                        for (int mt = 0; mt < MTW; mt++)
#pragma unroll
                            for (int q = 0; q < 4; q++)
                                ar[mt][q] = to_tf32(ar[mt][q] - __uint_as_float(ah[mt][q]));
#pragma unroll
                        for (int mt = 0; mt < MTW; mt++)
#pragma unroll
                            for (int nt = 0; nt < 4; nt++)
                                MMA_TF32(acc[mt][nt],
                                         __float_as_uint(ar[mt][0]), __float_as_uint(ar[mt][1]),
                                         __float_as_uint(ar[mt][2]), __float_as_uint(ar[mt][3]),
                                         bh[nt][0], bh[nt][1]);
                    }
                }
            }
        }
        __syncthreads();
        if (i + 1 < nch) {
            cstore((i + 1) & 1);
            __syncthreads();
        }
    }

    // epilogue (D layout identical for k8/k16 mma)
    int rbase = m0 + wm * (MT / 2) + (lane >> 2);
    int cbase = n0 + wn * 32 + (lane & 3) * 2;
#pragma unroll
    for (int mt = 0; mt < MTW; mt++) {
#pragma unroll
        for (int half = 0; half < 2; half++) {
            int row = rbase + mt * 16 + half * 8;
            if (row >= Mv) continue;
#pragma unroll
            for (int nt = 0; nt < 4; nt++) {
                int col = cbase + nt * 8;
                float x0 = acc[mt][nt][half * 2 + 0];
                float x1 = acc[mt][nt][half * 2 + 1];
                if (ep == 2)      { x0 = gelu_exact(x0 + bp[col]); x1 = gelu_exact(x1 + bp[col + 1]); }
                else if (ep == 3) { x0 += bp[col]; x1 += bp[col + 1]; }
                float* cp = C + (size_t)row * N + col;
                if (ep == 1) { x0 += cp[0]; x1 += cp[1]; }
                float2 o; o.x = x0; o.y = x1;
                *(float2*)cp = o;
            }
        }
    }
}
#define MM_SMEM(MT, LDA, LDB) (2 * ((MT) * (LDA) + 32 * (LDB)) * 4)
#define SM_128_BF MM_SMEM(128, 40, 132)
#define SM_128_TF MM_SMEM(128, 36, 136)
#define SM_64_BF  MM_SMEM(64, 40, 132)
#define SM_64_TF  MM_SMEM(64, 36, 136)

// ---------------- embedding gather ----------------
__global__ void embed_kernel(const int* __restrict__ idx, const float* __restrict__ emb,
                             float* __restrict__ x) {
    int i = blockIdx.x * 256 + threadIdx.x;
    int n = i >> 10, c = i & 1023;
    x[i] = emb[(size_t)idx[n] * C_ + c];
}

// ---------------- layernorm ----------------
__global__ void ln_kernel(const float* __restrict__ x, const float* __restrict__ g,
                          const float* __restrict__ b, float* __restrict__ out) {
    int row = blockIdx.x;
    const float* xr = x + (size_t)row * C_;
    float s = 0.f, s2 = 0.f;
    for (int c = threadIdx.x; c < C_; c += 256) { float v = xr[c]; s += v; s2 += v * v; }
    __shared__ float sh1[8], sh2[8], shm[2];
    int lane = threadIdx.x & 31, w = threadIdx.x >> 5;
    s = warp_sum(s); s2 = warp_sum(s2);
    if (!lane) { sh1[w] = s; sh2[w] = s2; }
    __syncthreads();
    if (threadIdx.x == 0) {
        float S = 0.f, S2 = 0.f;
        for (int i = 0; i < 8; i++) { S += sh1[i]; S2 += sh2[i]; }
        float mean = S * (1.0f / C_);
        float var  = S2 * (1.0f / C_) - mean * mean;
        shm[0] = mean; shm[1] = rsqrtf(var + 1e-5f);
    }
    __syncthreads();
    float mean = shm[0], inv = shm[1];
    float* orow = out + (size_t)row * C_;
    for (int c = threadIdx.x; c < C_; c += 256)
        orow[c] = (xr[c] - mean) * inv * g[c] + b[c];
}

// ---------------- RoPE ----------------
__global__ void rope_kernel(float* __restrict__ qkv) {
    int i = blockIdx.x * 256 + threadIdx.x;
    if (i >= NTOK * H_ * (HD_ / 2)) return;
    int j = i & 31;
    int h = (i >> 5) & 15;
    int n = i >> 9;
    int t = n & (T_ - 1);
    float e = (float)(2 * j) / (float)HD_;
    float invf = 1.0f / powf(10000.0f, e);
    float ang = (float)t * invf;
    float s = sinf(ang), c = cosf(ang);
    float* base = qkv + (size_t)n * (3 * C_) + h * (3 * HD_);
    float q1 = base[j],      q2 = base[j + 32];
    base[j]      = q1 * c - q2 * s;
    base[j + 32] = q1 * s + q2 * c;
    float k1 = base[64 + j], k2 = base[64 + j + 32];
    base[64 + j]      = k1 * c - k2 * s;
    base[64 + j + 32] = k1 * s + k2 * c;
}

// ---------------- fused flash attention ----------------
#define FA_QS  0
#define FA_KS  (64 * 65)
#define FA_VS  (FA_KS + 64 * 65)
#define FA_PS  (FA_VS + 64 * 68)
#define FA_SMEM ((FA_PS + 64 * 68) * 4)

__global__ void __launch_bounds__(256, 1)
flash_attn_kernel(const float* __restrict__ qkv, float* __restrict__ out) {
    extern __shared__ float fs[];
    float* Qs = fs + FA_QS;
    float* Ks = fs + FA_KS;
    float* Vs = fs + FA_VS;
    float* Ps = fs + FA_PS;
    int bh = blockIdx.y; int b = bh >> 4, h = bh & 15;
    int qb = (int)gridDim.x - 1 - (int)blockIdx.x;
    int q0 = qb * 64;
    int tid = threadIdx.x, tx = tid & 15, ty = tid >> 4;

    const float* qbase = qkv + (size_t)(b * T_ + q0) * (3 * C_) + h * (3 * HD_);
#pragma unroll
    for (int r = 0; r < 4; r++) {
        int idx = tid + r * 256;
        int tok = idx >> 4, d4 = (idx & 15) * 4;
        float4 v = *(const float4*)(qbase + (size_t)tok * (3 * C_) + d4);
        Qs[(d4 + 0) * 65 + tok] = v.x; Qs[(d4 + 1) * 65 + tok] = v.y;
        Qs[(d4 + 2) * 65 + tok] = v.z; Qs[(d4 + 3) * 65 + tok] = v.w;
    }

    float o[4][4];
    float mrow[4], lrow[4];
#pragma unroll
    for (int i = 0; i < 4; i++) {
        mrow[i] = -1e30f; lrow[i] = 0.f;
#pragma unroll
        for (int j = 0; j < 4; j++) o[i][j] = 0.f;
    }

    for (int kb = 0; kb <= qb; kb++) {
        int k0 = kb * 64;
        __syncthreads();
        const float* kbase = qkv + (size_t)(b * T_ + k0) * (3 * C_) + h * (3 * HD_) + HD_;
        const float* vbase = kbase + HD_;
#pragma unroll
        for (int r = 0; r < 4; r++) {
            int idx = tid + r * 256;
            int tok = idx >> 4, d4 = (idx & 15) * 4;
            float4 vk = *(const float4*)(kbase + (size_t)tok * (3 * C_) + d4);
            Ks[(d4 + 0) * 65 + tok] = vk.x; Ks[(d4 + 1) * 65 + tok] = vk.y;
            Ks[(d4 + 2) * 65 + tok] = vk.z; Ks[(d4 + 3) * 65 + tok] = vk.w;
            float4 vv = *(const float4*)(vbase + (size_t)tok * (3 * C_) + d4);
            *(float4*)(Vs + tok * 68 + d4) = vv;
        }
        __syncthreads();

        float s[4][4];
#pragma unroll
        for (int i = 0; i < 4; i++)
#pragma unroll
            for (int j = 0; j < 4; j++) s[i][j] = 0.f;
#pragma unroll
        for (int d = 0; d < 64; d++) {
            float a[4], bb[4];
#pragma unroll
            for (int i = 0; i < 4; i++) a[i]  = Qs[d * 65 + ty * 4 + i];
#pragma unroll
            for (int j = 0; j < 4; j++) bb[j] = Ks[d * 65 + tx * 4 + j];
#pragma unroll
            for (int i = 0; i < 4; i++)
#pragma unroll
                for (int j = 0; j < 4; j++) s[i][j] += a[i] * bb[j];
        }
        bool diag = (kb == qb);
#pragma unroll
        for (int i = 0; i < 4; i++)
#pragma unroll
            for (int j = 0; j < 4; j++) {
                s[i][j] *= 0.125f;
                if (diag && (tx * 4 + j) > (ty * 4 + i)) s[i][j] = -1e30f;
            }

#pragma unroll
        for (int i = 0; i < 4; i++) {
            float rm = fmaxf(fmaxf(s[i][0], s[i][1]), fmaxf(s[i][2], s[i][3]));
#pragma unroll
            for (int off = 1; off < 16; off <<= 1)
                rm = fmaxf(rm, __shfl_xor_sync(0xffffffffu, rm, off));
            float mn = fmaxf(mrow[i], rm);
            float alpha = expf(mrow[i] - mn);
            float rs = 0.f;
#pragma unroll
            for (int j = 0; j < 4; j++) {
                float p = expf(s[i][j] - mn);
                Ps[(ty * 4 + i) * 68 + tx * 4 + j] = p;
                rs += p;
            }
#pragma unroll
            for (int off = 1; off < 16; off <<= 1)
                rs += __shfl_xor_sync(0xffffffffu, rs, off);
            lrow[i] = lrow[i] * alpha + rs;
            mrow[i] = mn;
#pragma unroll
            for (int d = 0; d < 4; d++) o[i][d] *= alpha;
        }
        __syncthreads();

#pragma unroll 4
        for (int kk = 0; kk < 64; kk++) {
            float a[4], v[4];
#pragma unroll
            for (int i = 0; i < 4; i++) a[i] = Ps[(ty * 4 + i) * 68 + kk];
#pragma unroll
            for (int d = 0; d < 4; d++) v[d] = Vs[kk * 68 + tx * 4 + d];
#pragma unroll
            for (int i = 0; i < 4; i++)
#pragma unroll
                for (int d = 0; d < 4; d++) o[i][d] += a[i] * v[d];
        }
    }

#pragma unroll
    for (int i = 0; i < 4; i++) {
        float linv = 1.0f / lrow[i];
        float4 v;
        v.x = o[i][0] * linv; v.y = o[i][1] * linv;
        v.z = o[i][2] * linv; v.w = o[i][3] * linv;
        *(float4*)(out + (size_t)(b * T_ + q0 + ty * 4 + i) * C_ + h * HD_ + tx * 4) = v;
    }
}

// ---------------- gating ----------------
__global__ void gate_kernel(const float* __restrict__ x, const float* __restrict__ gw,
                            float* __restrict__ gates, int* __restrict__ top) {
    int n = blockIdx.x;
    int lane = threadIdx.x & 31, w = threadIdx.x >> 5;
    const float* xr = x + (size_t)n * C_;
    float acc = 0.f;
    for (int c = lane; c < C_; c += 32) acc += xr[c] * gw[(size_t)c * E_ + w];
    acc = warp_sum(acc);
    __shared__ float sl[E_];
    if (!lane) sl[w] = acc;
    __syncthreads();
    if (threadIdx.x == 0) {
        float p[E_];
        float m = sl[0];
        for (int e = 1; e < E_; e++) m = fmaxf(m, sl[e]);
        float s = 0.f;
        for (int e = 0; e < E_; e++) { p[e] = expf(sl[e] - m); s += p[e]; }
        float inv = 1.0f / s;
        for (int e = 0; e < E_; e++) { p[e] *= inv; gates[(size_t)n * E_ + e] = p[e]; }
        int i0 = 0;
        for (int e = 1; e < E_; e++) if (p[e] > p[i0]) i0 = e;
        int i1 = -1;
        for (int e = 0; e < E_; e++) {
            if (e == i0) continue;
            if (i1 < 0 || p[e] > p[i1]) i1 = e;
        }
        top[2 * n] = i0; top[2 * n + 1] = i1;
    }
}

// ---------------- routing ----------------
__global__ void route_kernel(const int* __restrict__ top, int* __restrict__ slot) {
    int e = threadIdx.x;
    if (e >= E_) return;
    int cnt = 0;
    for (int n = 0; n < NTOK; n++) {
        if (top[2 * n] == e)     { slot[2 * n]     = (cnt < CAP) ? cnt : -1; cnt++; }
        if (top[2 * n + 1] == e) { slot[2 * n + 1] = (cnt < CAP) ? cnt : -1; cnt++; }
    }
}

// ---------------- scatter ----------------
__global__ void scatter_kernel(const float* __restrict__ ln, const int* __restrict__ top,
                               const int* __restrict__ slot, float* __restrict__ buf) {
    int n = blockIdx.x;
    const float4* src = (const float4*)(ln + (size_t)n * C_);
#pragma unroll
    for (int kk = 0; kk < 2; kk++) {
        int s = slot[2 * n + kk];
        if (s < 0) continue;
        int e = top[2 * n + kk];
        float4* dst = (float4*)(buf + ((size_t)e * CAP + s) * C_);
        for (int i = threadIdx.x; i < C_ / 4; i += 256) dst[i] = src[i];
    }
}

// ---------------- combine + residual ----------------
__global__ void combine_kernel(const float* __restrict__ y, const float* __restrict__ gates,
                               const int* __restrict__ top, const int* __restrict__ slot,
                               float* __restrict__ x) {
    int n = blockIdx.x;
    int e0 = top[2 * n], e1 = top[2 * n + 1];
    int s0 = slot[2 * n], s1 = slot[2 * n + 1];
    float w0 = (s0 >= 0) ? gates[(size_t)n * E_ + e0] : 0.f;
    float w1 = (s1 >= 0) ? gates[(size_t)n * E_ + e1] : 0.f;
    const float* y0 = y + ((size_t)e0 * CAP + (s0 >= 0 ? s0 : 0)) * C_;
    const float* y1 = y + ((size_t)e1 * CAP + (s1 >= 0 ? s1 : 0)) * C_;
    float* xr = x + (size_t)n * C_;
    for (int c = threadIdx.x; c < C_; c += 256)
        xr[c] += w0 * y0[c] + w1 * y1[c];
}

// ---------------- launch ----------------
extern "C" void kernel_launch(void* const* d_in, const int* in_sizes, int n_in,
                              void* d_out, int out_size) {
    const int*   idx     = (const int*)  d_in[0];
    const float* tok_emb = (const float*)d_in[1];
    const float* ln1_g   = (const float*)d_in[2];
    const float* ln1_b   = (const float*)d_in[3];
    const float* qkv_w   = (const float*)d_in[4];
    const float* proj_w  = (const float*)d_in[5];
    const float* ln2_g   = (const float*)d_in[6];
    const float* ln2_b   = (const float*)d_in[7];
    const float* gate_w  = (const float*)d_in[8];
    const float* w1      = (const float*)d_in[9];
    const float* b1      = (const float*)d_in[10];
    const float* w2      = (const float*)d_in[11];
    const float* b2      = (const float*)d_in[12];
    const float* lnf_g   = (const float*)d_in[13];
    const float* lnf_b   = (const float*)d_in[14];
    const float* lm_head = (const float*)d_in[15];
    float* out = (float*)d_out;

    float *x, *ln, *qkv, *attn, *gates, *buf, *hbuf, *ybuf;
    int *top, *slot;
    cudaGetSymbolAddress((void**)&x,     g_x);
    cudaGetSymbolAddress((void**)&ln,    g_ln);
    cudaGetSymbolAddress((void**)&qkv,   g_qkv);
    cudaGetSymbolAddress((void**)&attn,  g_attn);
    cudaGetSymbolAddress((void**)&gates, g_gates);
    cudaGetSymbolAddress((void**)&top,   g_top);
    cudaGetSymbolAddress((void**)&slot,  g_slot);
    cudaGetSymbolAddress((void**)&buf,   g_buf);
    cudaGetSymbolAddress((void**)&hbuf,  g_hbuf);
    cudaGetSymbolAddress((void**)&ybuf,  g_ybuf);

    cudaFuncSetAttribute((const void*)mm_mma_kernel<128, true>,  cudaFuncAttributeMaxDynamicSharedMemorySize, SM_128_BF);
    cudaFuncSetAttribute((const void*)mm_mma_kernel<128, false>, cudaFuncAttributeMaxDynamicSharedMemorySize, SM_128_TF);
    cudaFuncSetAttribute((const void*)mm_mma_kernel<64, true>,   cudaFuncAttributeMaxDynamicSharedMemorySize, SM_64_BF);
    cudaFuncSetAttribute((const void*)mm_mma_kernel<64, false>,  cudaFuncAttributeMaxDynamicSharedMemorySize, SM_64_TF);
    cudaFuncSetAttribute((const void*)flash_attn_kernel, cudaFuncAttributeMaxDynamicSharedMemorySize, FA_SMEM);

    embed_kernel<<<NTOK * C_ / 256, 256>>>(idx, tok_emb, x);

    for (int l = 0; l < L_; l++) {
        // --- attention (routing-critical -> bf16x3) ---
        ln_kernel<<<NTOK, 256>>>(x, ln1_g + (size_t)l * C_, ln1_b + (size_t)l * C_, ln);
        mm_mma_kernel<128, true><<<dim3(NTOK / 128, 3 * C_ / 128, 1), 256, SM_128_BF>>>(
            ln, qkv_w + (size_t)l * C_ * 3 * C_, qkv, nullptr,
            NTOK, 3 * C_, C_, 0, 0, 0, 0, 0, 3);
        rope_kernel<<<(NTOK * H_ * (HD_ / 2) + 255) / 256, 256>>>(qkv);
        flash_attn_kernel<<<dim3(T_ / 64, B_ * H_), 256, FA_SMEM>>>(qkv, attn);
        mm_mma_kernel<128, true><<<dim3(NTOK / 128, C_ / 128, 1), 256, SM_128_BF>>>(
            attn, proj_w + (size_t)l * C_ * C_, x, nullptr,
            NTOK, C_, C_, 0, 0, 0, 0, 1, 3);  // += residual

        // --- MoE ---
        ln_kernel<<<NTOK, 256>>>(x, ln2_g + (size_t)l * C_, ln2_b + (size_t)l * C_, ln);
        gate_kernel<<<NTOK, 256>>>(ln, gate_w + (size_t)l * C_ * E_, gates, top);
        route_kernel<<<1, 32>>>(top, slot);
        scatter_kernel<<<NTOK, 256>>>(ln, top, slot, buf);
        if (l < L_ - 1) {
            // feeds next layer's routing -> bf16x3
            mm_mma_kernel<64, true><<<dim3(CAP / 64, FF_ / 128, E_), 256, SM_64_BF>>>(
                buf, w1 + (size_t)l * E_ * C_ * FF_, hbuf, b1 + (size_t)l * E_ * FF_,
                CAP, FF_, C_, (long)CAP * C_, (long)C_ * FF_, (long)CAP * FF_, (long)FF_, 2, 3);
            mm_mma_kernel<64, true><<<dim3(CAP / 64, C_ / 128, E_), 256, SM_64_BF>>>(
                hbuf, w2 + (size_t)l * E_ * FF_ * C_, ybuf, b2 + (size_t)l * E_ * C_,
                CAP, C_, FF_, (long)CAP * FF_, (long)FF_ * C_, (long)CAP * C_, (long)C_, 3, 3);
        } else {
            // only smooth ops downstream -> 1-pass tf32
            mm_mma_kernel<64, false><<<dim3(CAP / 64, FF_ / 128, E_), 256, SM_64_TF>>>(
                buf, w1 + (size_t)l * E_ * C_ * FF_, hbuf, b1 + (size_t)l * E_ * FF_,
                CAP, FF_, C_, (long)CAP * C_, (long)C_ * FF_, (long)CAP * FF_, (long)FF_, 2, 1);
            mm_mma_kernel<64, false><<<dim3(CAP / 64, C_ / 128, E_), 256, SM_64_TF>>>(
                hbuf, w2 + (size_t)l * E_ * FF_ * C_, ybuf, b2 + (size_t)l * E_ * C_,
                CAP, C_, FF_, (long)CAP * FF_, (long)FF_ * C_, (long)CAP * C_, (long)C_, 3, 1);
        }
        combine_kernel<<<NTOK, 256>>>(ybuf, gates, top, slot, x);
    }

    ln_kernel<<<NTOK, 256>>>(x, lnf_g, lnf_b, ln);
    mm_mma_kernel<128, false><<<dim3(NTOK / 128, V_ / 128, 1), 256, SM_128_TF>>>(
        ln, lm_head, out, nullptr, NTOK, V_, C_, 0, 0, 0, 0, 0, 1);
}

// round 11
// speedup vs baseline: 2.8129x; 1.1087x over previous
#include <cuda_runtime.h>
#include <cuda_bf16.h>
#include <cuda_fp16.h>
#include <math.h>
#include <stdint.h>

#define B_   2
#define T_   1024
#define C_   1024
#define H_   16
#define HD_  64
#define L_   2
#define E_   8
#define FF_  4096
#define V_   32000
#define NTOK (B_ * T_)
#define CAP  320   // ceil(1.25 * 2048 / 8); 320 = 5 * 64 -> exact 64-row tiling

// ---------------- scratch (static device globals; no allocations) ----------------
__device__ float g_x[NTOK * C_];
__device__ float g_ln[NTOK * C_];
__device__ float g_qkv[NTOK * 3 * C_];
__device__ float g_attn[NTOK * C_];
__device__ float g_gates[NTOK * E_];
__device__ int   g_top[NTOK * 2];
__device__ int   g_slot[NTOK * 2];
__device__ float g_buf [E_ * CAP * C_];
__device__ float g_hbuf[E_ * CAP * FF_];
__device__ float g_ybuf[E_ * CAP * C_];

// ---------------- helpers ----------------
__device__ __forceinline__ float warp_sum(float v) {
#pragma unroll
    for (int o = 16; o; o >>= 1) v += __shfl_xor_sync(0xffffffffu, v, o);
    return v;
}
__device__ __forceinline__ float gelu_exact(float v) {
    return 0.5f * v * (1.0f + erff(v * 0.70710678118654752f));
}
__device__ __forceinline__ float to_tf32(float v) {
    float o; asm("cvt.rna.tf32.f32 %0, %1;" : "=f"(o) : "f"(v)); return o;
}
__device__ __forceinline__ float bf_hi(float v) {
    return __bfloat162float(__float2bfloat16(v));
}
// pack {lo half = a, hi half = b} with rn rounding (bf16)
__device__ __forceinline__ uint32_t pack_bf2(float a, float b) {
    uint32_t r;
    asm("cvt.rn.bf16x2.f32 %0, %1, %2;" : "=r"(r) : "f"(b), "f"(a));
    return r;
}
// pack {lo half = a, hi half = b} with rn rounding (fp16)
__device__ __forceinline__ uint32_t pack_f16(float a, float b) {
    uint32_t r;
    asm("cvt.rn.f16x2.f32 %0, %1, %2;" : "=r"(r) : "f"(b), "f"(a));
    return r;
}
// split a k-pair into rounded hi/lo bf16x2 words
__device__ __forceinline__ void split_pack(float x0, float x1, uint32_t& hi, uint32_t& lo) {
    float h0 = bf_hi(x0), h1 = bf_hi(x1);
    hi = pack_bf2(h0, h1);
    lo = pack_bf2(x0 - h0, x1 - h1);
}

#define MMA_TF32(accp, a0, a1, a2, a3, b0, b1)                                  \
    asm volatile(                                                               \
        "mma.sync.aligned.m16n8k8.row.col.f32.tf32.tf32.f32 "                   \
        "{%0,%1,%2,%3}, {%4,%5,%6,%7}, {%8,%9}, {%0,%1,%2,%3};"                 \
        : "+f"((accp)[0]), "+f"((accp)[1]), "+f"((accp)[2]), "+f"((accp)[3])    \
        : "r"(a0), "r"(a1), "r"(a2), "r"(a3), "r"(b0), "r"(b1))

#define MMA_BF16(accp, a0, a1, a2, a3, b0, b1)                                  \
    asm volatile(                                                               \
        "mma.sync.aligned.m16n8k16.row.col.f32.bf16.bf16.f32 "                  \
        "{%0,%1,%2,%3}, {%4,%5,%6,%7}, {%8,%9}, {%0,%1,%2,%3};"                 \
        : "+f"((accp)[0]), "+f"((accp)[1]), "+f"((accp)[2]), "+f"((accp)[3])    \
        : "r"(a0), "r"(a1), "r"(a2), "r"(a3), "r"(b0), "r"(b1))

#define MMA_F16(accp, a0, a1, a2, a3, b0, b1)                                   \
    asm volatile(                                                               \
        "mma.sync.aligned.m16n8k16.row.col.f32.f16.f16.f32 "                    \
        "{%0,%1,%2,%3}, {%4,%5,%6,%7}, {%8,%9}, {%0,%1,%2,%3};"                 \
        : "+f"((accp)[0]), "+f"((accp)[1]), "+f"((accp)[2]), "+f"((accp)[3])    \
        : "r"(a0), "r"(a1), "r"(a2), "r"(a3), "r"(b0), "r"(b1))

// ======== tensor-core GEMM, templated on M-tile and numeric MODE ========
// MODE 0: tf32 (npass runtime, 1 or 3)   -- legacy
// MODE 1: bf16x3 rounded compensation    -- routing-critical (err ~3*2^-18/product)
// MODE 2: fp16 1-pass                    -- non-routing (same 10-bit mantissa as tf32,
//                                           half the instructions; fp32 accumulate)
// C[Mv,N] = A[M,K] @ B[K,N], batched over blockIdx.z. MTxN128 tile per CTA,
// 256 threads (8 warps as 2x4, warp tile (MT/2)x32), K-chunks of 32.
template<int MT, int MODE>
__global__ void __launch_bounds__(256, MT == 64 ? 2 : 1)
mm_mma_kernel(const float* __restrict__ A, const float* __restrict__ B,
              float* __restrict__ C, const float* __restrict__ bias,
              int Mv, int N, int K,
              long sA, long sB, long sC, long sBias, int ep, int npass)
{
    constexpr int LDA = (MODE == 0) ? 36 : 40;
    constexpr int LDB = (MODE == 0) ? 136 : 132;
    constexpr int MTW  = MT / 32;
    constexpr int AIT  = MT / 32;
    constexpr int ABUF = MT * LDA;
    constexpr int BUFSZ = ABUF + 32 * LDB;
    extern __shared__ float sm[];
    int tid = threadIdx.x, lane = tid & 31, wid = tid >> 5;
    int wm = wid & 1, wn = wid >> 1;
    int r_lo = lane >> 2, c_lo = lane & 3;
    int z = blockIdx.z;
    A += (long)z * sA; B += (long)z * sB; C += (long)z * sC;
    const float* bp = bias ? bias + (long)z * sBias : nullptr;
    int m0 = blockIdx.x * MT, n0 = blockIdx.y * 128;

    float acc[MTW][4][4];
#pragma unroll
    for (int i = 0; i < MTW; i++)
#pragma unroll
        for (int j = 0; j < 4; j++)
#pragma unroll
            for (int k = 0; k < 4; k++) acc[i][j][k] = 0.f;

    float4 pa[AIT], pb[4];

    auto prefetch = [&](int i) {
        int k0 = i << 5;
#pragma unroll
        for (int it = 0; it < AIT; it++) {
            int idx = tid + it * 256;
            int m = idx >> 3, f4 = idx & 7;
            pa[it] = *(const float4*)(A + (size_t)(m0 + m) * K + k0 + f4 * 4);
        }
#pragma unroll
        for (int it = 0; it < 4; it++) {
            int idx = tid + it * 256;
            int k = idx >> 5, f4 = idx & 31;
            pb[it] = *(const float4*)(B + (size_t)(k0 + k) * N + n0 + f4 * 4);
        }
    };
    auto cstore = [&](int s) {
        float* smA = sm + s * BUFSZ;
        float* smB = smA + ABUF;
#pragma unroll
        for (int it = 0; it < AIT; it++) {
            int idx = tid + it * 256;
            int m = idx >> 3, f4 = idx & 7;
            *(float4*)(smA + m * LDA + f4 * 4) = pa[it];
        }
#pragma unroll
        for (int it = 0; it < 4; it++) {
            int idx = tid + it * 256;
            int k = idx >> 5, f4 = idx & 31;
            *(float4*)(smB + k * LDB + f4 * 4) = pb[it];
        }
    };

    int nch = K >> 5;
    prefetch(0);
    cstore(0);
    __syncthreads();
    for (int i = 0; i < nch; i++) {
        if (i + 1 < nch) prefetch(i + 1);
        {
            float* smA = sm + (i & 1) * BUFSZ;
            float* smB = smA + ABUF;
            if constexpr (MODE == 1) {
                // bf16x3: two k16 slabs; 3 mma per (mt,nt) per slab
#pragma unroll
                for (int ks = 0; ks < 2; ks++) {
                    int kb = ks * 16 + 2 * c_lo;
                    uint32_t ah[MTW][4], al[MTW][4], bh[4][2], bl[4][2];
#pragma unroll
                    for (int mt = 0; mt < MTW; mt++) {
                        const float* ab = smA + (wm * (MT / 2) + mt * 16 + r_lo) * LDA + kb;
                        float2 p0 = *(const float2*)ab;
                        float2 p1 = *(const float2*)(ab + 8 * LDA);
                        float2 p2 = *(const float2*)(ab + 8);
                        float2 p3 = *(const float2*)(ab + 8 * LDA + 8);
                        split_pack(p0.x, p0.y, ah[mt][0], al[mt][0]);
                        split_pack(p1.x, p1.y, ah[mt][1], al[mt][1]);
                        split_pack(p2.x, p2.y, ah[mt][2], al[mt][2]);
                        split_pack(p3.x, p3.y, ah[mt][3], al[mt][3]);
                    }
#pragma unroll
                    for (int nt = 0; nt < 4; nt++) {
                        const float* bb = smB + kb * LDB + wn * 32 + nt * 8 + r_lo;
                        split_pack(bb[0],       bb[LDB],     bh[nt][0], bl[nt][0]);
                        split_pack(bb[8 * LDB], bb[9 * LDB], bh[nt][1], bl[nt][1]);
                    }
#pragma unroll
                    for (int mt = 0; mt < MTW; mt++)
#pragma unroll
                        for (int nt = 0; nt < 4; nt++) {
                            MMA_BF16(acc[mt][nt], ah[mt][0], ah[mt][1], ah[mt][2], ah[mt][3],
                                     bh[nt][0], bh[nt][1]);
                            MMA_BF16(acc[mt][nt], ah[mt][0], ah[mt][1], ah[mt][2], ah[mt][3],
                                     bl[nt][0], bl[nt][1]);
                            MMA_BF16(acc[mt][nt], al[mt][0], al[mt][1], al[mt][2], al[mt][3],
                                     bh[nt][0], bh[nt][1]);
                        }
                }
            } else if constexpr (MODE == 2) {
                // fp16 1-pass: two k16 slabs; 1 mma per (mt,nt) per slab
#pragma unroll
                for (int ks = 0; ks < 2; ks++) {
                    int kb = ks * 16 + 2 * c_lo;
                    uint32_t ah[MTW][4], bh[4][2];
#pragma unroll
                    for (int mt = 0; mt < MTW; mt++) {
                        const float* ab = smA + (wm * (MT / 2) + mt * 16 + r_lo) * LDA + kb;
                        float2 p0 = *(const float2*)ab;
                        float2 p1 = *(const float2*)(ab + 8 * LDA);
                        float2 p2 = *(const float2*)(ab + 8);
                        float2 p3 = *(const float2*)(ab + 8 * LDA + 8);
                        ah[mt][0] = pack_f16(p0.x, p0.y);
                        ah[mt][1] = pack_f16(p1.x, p1.y);
                        ah[mt][2] = pack_f16(p2.x, p2.y);
                        ah[mt][3] = pack_f16(p3.x, p3.y);
                    }
#pragma unroll
                    for (int nt = 0; nt < 4; nt++) {
                        const float* bb = smB + kb * LDB + wn * 32 + nt * 8 + r_lo;
                        bh[nt][0] = pack_f16(bb[0], bb[LDB]);
                        bh[nt][1] = pack_f16(bb[8 * LDB], bb[9 * LDB]);
                    }
#pragma unroll
                    for (int mt = 0; mt < MTW; mt++)
#pragma unroll
                        for (int nt = 0; nt < 4; nt++)
                            MMA_F16(acc[mt][nt], ah[mt][0], ah[mt][1], ah[mt][2], ah[mt][3],
                                    bh[nt][0], bh[nt][1]);
                }
            } else {
#pragma unroll
                for (int ks = 0; ks < 4; ks++) {
                    float ar[MTW][4], br[4][2];
                    uint32_t ah[MTW][4], bh[4][2];
#pragma unroll
                    for (int mt = 0; mt < MTW; mt++) {
                        const float* ab = smA + (wm * (MT / 2) + mt * 16 + r_lo) * LDA + ks * 8 + c_lo;
                        ar[mt][0] = ab[0];
                        ar[mt][1] = ab[8 * LDA];
                        ar[mt][2] = ab[4];
                        ar[mt][3] = ab[8 * LDA + 4];
#pragma unroll
                        for (int q = 0; q < 4; q++) ah[mt][q] = __float_as_uint(to_tf32(ar[mt][q]));
                    }
#pragma unroll
                    for (int nt = 0; nt < 4; nt++) {
                        const float* bb = smB + (ks * 8 + c_lo) * LDB + wn * 32 + nt * 8 + r_lo;
                        br[nt][0] = bb[0];
                        br[nt][1] = bb[4 * LDB];
                        bh[nt][0] = __float_as_uint(to_tf32(br[nt][0]));
                        bh[nt][1] = __float_as_uint(to_tf32(br[nt][1]));
                    }
#pragma unroll
                    for (int mt = 0; mt < MTW; mt++)
#pragma unroll
                        for (int nt = 0; nt < 4; nt++)
                            MMA_TF32(acc[mt][nt], ah[mt][0], ah[mt][1], ah[mt][2], ah[mt][3],
                                     bh[nt][0], bh[nt][1]);
                    if (npass == 3) {
#pragma unroll
                        for (int nt = 0; nt < 4; nt++) {
                            br[nt][0] = to_tf32(br[nt][0] - __uint_as_float(bh[nt][0]));
                            br[nt][1] = to_tf32(br[nt][1] - __uint_as_float(bh[nt][1]));
                        }
#pragma unroll
                        for (int mt = 0; mt < MTW; mt++)
#pragma unroll
                            for (int nt = 0; nt < 4; nt++)
                                MMA_TF32(acc[mt][nt], ah[mt][0], ah[mt][1], ah[mt][2], ah[mt][3],
                                         __float_as_uint(br[nt][0]), __float_as_uint(br[nt][1]));
#pragma unroll
                        for (int mt = 0; mt < MTW; mt++)
#pragma unroll
                            for (int q = 0; q < 4; q++)
                                ar[mt][q] = to_tf32(ar[mt][q] - __uint_as_float(ah[mt][q]));
#pragma unroll
                        for (int mt = 0; mt < MTW; mt++)
#pragma unroll
                            for (int nt = 0; nt < 4; nt++)
                                MMA_TF32(acc[mt][nt],
                                         __float_as_uint(ar[mt][0]), __float_as_uint(ar[mt][1]),
                                         __float_as_uint(ar[mt][2]), __float_as_uint(ar[mt][3]),
                                         bh[nt][0], bh[nt][1]);
                    }
                }
            }
        }
        __syncthreads();
        if (i + 1 < nch) {
            cstore((i + 1) & 1);
            __syncthreads();
        }
    }

    // epilogue (D layout identical across mma shapes)
    int rbase = m0 + wm * (MT / 2) + (lane >> 2);
    int cbase = n0 + wn * 32 + (lane & 3) * 2;
#pragma unroll
    for (int mt = 0; mt < MTW; mt++) {
#pragma unroll
        for (int half = 0; half < 2; half++) {
            int row = rbase + mt * 16 + half * 8;
            if (row >= Mv) continue;
#pragma unroll
            for (int nt = 0; nt < 4; nt++) {
                int col = cbase + nt * 8;
                float x0 = acc[mt][nt][half * 2 + 0];
                float x1 = acc[mt][nt][half * 2 + 1];
                if (ep == 2)      { x0 = gelu_exact(x0 + bp[col]); x1 = gelu_exact(x1 + bp[col + 1]); }
                else if (ep == 3) { x0 += bp[col]; x1 += bp[col + 1]; }
                float* cp = C + (size_t)row * N + col;
                if (ep == 1) { x0 += cp[0]; x1 += cp[1]; }
                float2 o; o.x = x0; o.y = x1;
                *(float2*)cp = o;
            }
        }
    }
}
#define MM_SMEM(MT, LDA, LDB) (2 * ((MT) * (LDA) + 32 * (LDB)) * 4)
#define SM_128_BF MM_SMEM(128, 40, 132)
#define SM_128_TF MM_SMEM(128, 36, 136)
#define SM_128_HF MM_SMEM(128, 40, 132)
#define SM_64_BF  MM_SMEM(64, 40, 132)
#define SM_64_HF  MM_SMEM(64, 40, 132)

// ---------------- embedding gather ----------------
__global__ void embed_kernel(const int* __restrict__ idx, const float* __restrict__ emb,
                             float* __restrict__ x) {
    int i = blockIdx.x * 256 + threadIdx.x;
    int n = i >> 10, c = i & 1023;
    x[i] = emb[(size_t)idx[n] * C_ + c];
}

// ---------------- layernorm ----------------
__global__ void ln_kernel(const float* __restrict__ x, const float* __restrict__ g,
                          const float* __restrict__ b, float* __restrict__ out) {
    int row = blockIdx.x;
    const float* xr = x + (size_t)row * C_;
    float s = 0.f, s2 = 0.f;
    for (int c = threadIdx.x; c < C_; c += 256) { float v = xr[c]; s += v; s2 += v * v; }
    __shared__ float sh1[8], sh2[8], shm[2];
    int lane = threadIdx.x & 31, w = threadIdx.x >> 5;
    s = warp_sum(s); s2 = warp_sum(s2);
    if (!lane) { sh1[w] = s; sh2[w] = s2; }
    __syncthreads();
    if (threadIdx.x == 0) {
        float S = 0.f, S2 = 0.f;
        for (int i = 0; i < 8; i++) { S += sh1[i]; S2 += sh2[i]; }
        float mean = S * (1.0f / C_);
        float var  = S2 * (1.0f / C_) - mean * mean;
        shm[0] = mean; shm[1] = rsqrtf(var + 1e-5f);
    }
    __syncthreads();
    float mean = shm[0], inv = shm[1];
    float* orow = out + (size_t)row * C_;
    for (int c = threadIdx.x; c < C_; c += 256)
        orow[c] = (xr[c] - mean) * inv * g[c] + b[c];
}

// ---------------- RoPE ----------------
__global__ void rope_kernel(float* __restrict__ qkv) {
    int i = blockIdx.x * 256 + threadIdx.x;
    if (i >= NTOK * H_ * (HD_ / 2)) return;
    int j = i & 31;
    int h = (i >> 5) & 15;
    int n = i >> 9;
    int t = n & (T_ - 1);
    float e = (float)(2 * j) / (float)HD_;
    float invf = 1.0f / powf(10000.0f, e);
    float ang = (float)t * invf;
    float s = sinf(ang), c = cosf(ang);
    float* base = qkv + (size_t)n * (3 * C_) + h * (3 * HD_);
    float q1 = base[j],      q2 = base[j + 32];
    base[j]      = q1 * c - q2 * s;
    base[j + 32] = q1 * s + q2 * c;
    float k1 = base[64 + j], k2 = base[64 + j + 32];
    base[64 + j]      = k1 * c - k2 * s;
    base[64 + j + 32] = k1 * s + k2 * c;
}

// ---------------- fused flash attention ----------------
#define FA_QS  0
#define FA_KS  (64 * 65)
#define FA_VS  (FA_KS + 64 * 65)
#define FA_PS  (FA_VS + 64 * 68)
#define FA_SMEM ((FA_PS + 64 * 68) * 4)

__global__ void __launch_bounds__(256, 1)
flash_attn_kernel(const float* __restrict__ qkv, float* __restrict__ out) {
    extern __shared__ float fs[];
    float* Qs = fs + FA_QS;
    float* Ks = fs + FA_KS;
    float* Vs = fs + FA_VS;
    float* Ps = fs + FA_PS;
    int bh = blockIdx.y; int b = bh >> 4, h = bh & 15;
    int qb = (int)gridDim.x - 1 - (int)blockIdx.x;
    int q0 = qb * 64;
    int tid = threadIdx.x, tx = tid & 15, ty = tid >> 4;

    const float* qbase = qkv + (size_t)(b * T_ + q0) * (3 * C_) + h * (3 * HD_);
#pragma unroll
    for (int r = 0; r < 4; r++) {
        int idx = tid + r * 256;
        int tok = idx >> 4, d4 = (idx & 15) * 4;
        float4 v = *(const float4*)(qbase + (size_t)tok * (3 * C_) + d4);
        Qs[(d4 + 0) * 65 + tok] = v.x; Qs[(d4 + 1) * 65 + tok] = v.y;
        Qs[(d4 + 2) * 65 + tok] = v.z; Qs[(d4 + 3) * 65 + tok] = v.w;
    }

    float o[4][4];
    float mrow[4], lrow[4];
#pragma unroll
    for (int i = 0; i < 4; i++) {
        mrow[i] = -1e30f; lrow[i] = 0.f;
#pragma unroll
        for (int j = 0; j < 4; j++) o[i][j] = 0.f;
    }

    for (int kb = 0; kb <= qb; kb++) {
        int k0 = kb * 64;
        __syncthreads();
        const float* kbase = qkv + (size_t)(b * T_ + k0) * (3 * C_) + h * (3 * HD_) + HD_;
        const float* vbase = kbase + HD_;
#pragma unroll
        for (int r = 0; r < 4; r++) {
            int idx = tid + r * 256;
            int tok = idx >> 4, d4 = (idx & 15) * 4;
            float4 vk = *(const float4*)(kbase + (size_t)tok * (3 * C_) + d4);
            Ks[(d4 + 0) * 65 + tok] = vk.x; Ks[(d4 + 1) * 65 + tok] = vk.y;
            Ks[(d4 + 2) * 65 + tok] = vk.z; Ks[(d4 + 3) * 65 + tok] = vk.w;
            float4 vv = *(const float4*)(vbase + (size_t)tok * (3 * C_) + d4);
            *(float4*)(Vs + tok * 68 + d4) = vv;
        }
        __syncthreads();

        float s[4][4];
#pragma unroll
        for (int i = 0; i < 4; i++)
#pragma unroll
            for (int j = 0; j < 4; j++) s[i][j] = 0.f;
#pragma unroll
        for (int d = 0; d < 64; d++) {
            float a[4], bb[4];
#pragma unroll
            for (int i = 0; i < 4; i++) a[i]  = Qs[d * 65 + ty * 4 + i];
#pragma unroll
            for (int j = 0; j < 4; j++) bb[j] = Ks[d * 65 + tx * 4 + j];
#pragma unroll
            for (int i = 0; i < 4; i++)
#pragma unroll
                for (int j = 0; j < 4; j++) s[i][j] += a[i] * bb[j];
        }
        bool diag = (kb == qb);
#pragma unroll
        for (int i = 0; i < 4; i++)
#pragma unroll
            for (int j = 0; j < 4; j++) {
                s[i][j] *= 0.125f;
                if (diag && (tx * 4 + j) > (ty * 4 + i)) s[i][j] = -1e30f;
            }

#pragma unroll
        for (int i = 0; i < 4; i++) {
            float rm = fmaxf(fmaxf(s[i][0], s[i][1]), fmaxf(s[i][2], s[i][3]));
#pragma unroll
            for (int off = 1; off < 16; off <<= 1)
                rm = fmaxf(rm, __shfl_xor_sync(0xffffffffu, rm, off));
            float mn = fmaxf(mrow[i], rm);
            float alpha = expf(mrow[i] - mn);
            float rs = 0.f;
#pragma unroll
            for (int j = 0; j < 4; j++) {
                float p = expf(s[i][j] - mn);
                Ps[(ty * 4 + i) * 68 + tx * 4 + j] = p;
                rs += p;
            }
#pragma unroll
            for (int off = 1; off < 16; off <<= 1)
                rs += __shfl_xor_sync(0xffffffffu, rs, off);
            lrow[i] = lrow[i] * alpha + rs;
            mrow[i] = mn;
#pragma unroll
            for (int d = 0; d < 4; d++) o[i][d] *= alpha;
        }
        __syncthreads();

#pragma unroll 4
        for (int kk = 0; kk < 64; kk++) {
            float a[4], v[4];
#pragma unroll
            for (int i = 0; i < 4; i++) a[i] = Ps[(ty * 4 + i) * 68 + kk];
#pragma unroll
            for (int d = 0; d < 4; d++) v[d] = Vs[kk * 68 + tx * 4 + d];
#pragma unroll
            for (int i = 0; i < 4; i++)
#pragma unroll
                for (int d = 0; d < 4; d++) o[i][d] += a[i] * v[d];
        }
    }

#pragma unroll
    for (int i = 0; i < 4; i++) {
        float linv = 1.0f / lrow[i];
        float4 v;
        v.x = o[i][0] * linv; v.y = o[i][1] * linv;
        v.z = o[i][2] * linv; v.w = o[i][3] * linv;
        *(float4*)(out + (size_t)(b * T_ + q0 + ty * 4 + i) * C_ + h * HD_ + tx * 4) = v;
    }
}

// ---------------- gating ----------------
__global__ void gate_kernel(const float* __restrict__ x, const float* __restrict__ gw,
                            float* __restrict__ gates, int* __restrict__ top) {
    int n = blockIdx.x;
    int lane = threadIdx.x & 31, w = threadIdx.x >> 5;
    const float* xr = x + (size_t)n * C_;
    float acc = 0.f;
    for (int c = lane; c < C_; c += 32) acc += xr[c] * gw[(size_t)c * E_ + w];
    acc = warp_sum(acc);
    __shared__ float sl[E_];
    if (!lane) sl[w] = acc;
    __syncthreads();
    if (threadIdx.x == 0) {
        float p[E_];
        float m = sl[0];
        for (int e = 1; e < E_; e++) m = fmaxf(m, sl[e]);
        float s = 0.f;
        for (int e = 0; e < E_; e++) { p[e] = expf(sl[e] - m); s += p[e]; }
        float inv = 1.0f / s;
        for (int e = 0; e < E_; e++) { p[e] *= inv; gates[(size_t)n * E_ + e] = p[e]; }
        int i0 = 0;
        for (int e = 1; e < E_; e++) if (p[e] > p[i0]) i0 = e;
        int i1 = -1;
        for (int e = 0; e < E_; e++) {
            if (e == i0) continue;
            if (i1 < 0 || p[e] > p[i1]) i1 = e;
        }
        top[2 * n] = i0; top[2 * n + 1] = i1;
    }
}

// ---------------- routing ----------------
__global__ void route_kernel(const int* __restrict__ top, int* __restrict__ slot) {
    int e = threadIdx.x;
    if (e >= E_) return;
    int cnt = 0;
    for (int n = 0; n < NTOK; n++) {
        if (top[2 * n] == e)     { slot[2 * n]     = (cnt < CAP) ? cnt : -1; cnt++; }
        if (top[2 * n + 1] == e) { slot[2 * n + 1] = (cnt < CAP) ? cnt : -1; cnt++; }
    }
}

// ---------------- scatter ----------------
__global__ void scatter_kernel(const float* __restrict__ ln, const int* __restrict__ top,
                               const int* __restrict__ slot, float* __restrict__ buf) {
    int n = blockIdx.x;
    const float4* src = (const float4*)(ln + (size_t)n * C_);
#pragma unroll
    for (int kk = 0; kk < 2; kk++) {
        int s = slot[2 * n + kk];
        if (s < 0) continue;
        int e = top[2 * n + kk];
        float4* dst = (float4*)(buf + ((size_t)e * CAP + s) * C_);
        for (int i = threadIdx.x; i < C_ / 4; i += 256) dst[i] = src[i];
    }
}

// ---------------- combine + residual ----------------
__global__ void combine_kernel(const float* __restrict__ y, const float* __restrict__ gates,
                               const int* __restrict__ top, const int* __restrict__ slot,
                               float* __restrict__ x) {
    int n = blockIdx.x;
    int e0 = top[2 * n], e1 = top[2 * n + 1];
    int s0 = slot[2 * n], s1 = slot[2 * n + 1];
    float w0 = (s0 >= 0) ? gates[(size_t)n * E_ + e0] : 0.f;
    float w1 = (s1 >= 0) ? gates[(size_t)n * E_ + e1] : 0.f;
    const float* y0 = y + ((size_t)e0 * CAP + (s0 >= 0 ? s0 : 0)) * C_;
    const float* y1 = y + ((size_t)e1 * CAP + (s1 >= 0 ? s1 : 0)) * C_;
    float* xr = x + (size_t)n * C_;
    for (int c = threadIdx.x; c < C_; c += 256)
        xr[c] += w0 * y0[c] + w1 * y1[c];
}

// ---------------- launch ----------------
extern "C" void kernel_launch(void* const* d_in, const int* in_sizes, int n_in,
                              void* d_out, int out_size) {
    const int*   idx     = (const int*)  d_in[0];
    const float* tok_emb = (const float*)d_in[1];
    const float* ln1_g   = (const float*)d_in[2];
    const float* ln1_b   = (const float*)d_in[3];
    const float* qkv_w   = (const float*)d_in[4];
    const float* proj_w  = (const float*)d_in[5];
    const float* ln2_g   = (const float*)d_in[6];
    const float* ln2_b   = (const float*)d_in[7];
    const float* gate_w  = (const float*)d_in[8];
    const float* w1      = (const float*)d_in[9];
    const float* b1      = (const float*)d_in[10];
    const float* w2      = (const float*)d_in[11];
    const float* b2      = (const float*)d_in[12];
    const float* lnf_g   = (const float*)d_in[13];
    const float* lnf_b   = (const float*)d_in[14];
    const float* lm_head = (const float*)d_in[15];
    float* out = (float*)d_out;

    float *x, *ln, *qkv, *attn, *gates, *buf, *hbuf, *ybuf;
    int *top, *slot;
    cudaGetSymbolAddress((void**)&x,     g_x);
    cudaGetSymbolAddress((void**)&ln,    g_ln);
    cudaGetSymbolAddress((void**)&qkv,   g_qkv);
    cudaGetSymbolAddress((void**)&attn,  g_attn);
    cudaGetSymbolAddress((void**)&gates, g_gates);
    cudaGetSymbolAddress((void**)&top,   g_top);
    cudaGetSymbolAddress((void**)&slot,  g_slot);
    cudaGetSymbolAddress((void**)&buf,   g_buf);
    cudaGetSymbolAddress((void**)&hbuf,  g_hbuf);
    cudaGetSymbolAddress((void**)&ybuf,  g_ybuf);

    cudaFuncSetAttribute((const void*)mm_mma_kernel<128, 1>, cudaFuncAttributeMaxDynamicSharedMemorySize, SM_128_BF);
    cudaFuncSetAttribute((const void*)mm_mma_kernel<128, 2>, cudaFuncAttributeMaxDynamicSharedMemorySize, SM_128_HF);
    cudaFuncSetAttribute((const void*)mm_mma_kernel<64, 1>,  cudaFuncAttributeMaxDynamicSharedMemorySize, SM_64_BF);
    cudaFuncSetAttribute((const void*)mm_mma_kernel<64, 2>,  cudaFuncAttributeMaxDynamicSharedMemorySize, SM_64_HF);
    cudaFuncSetAttribute((const void*)flash_attn_kernel, cudaFuncAttributeMaxDynamicSharedMemorySize, FA_SMEM);

    embed_kernel<<<NTOK * C_ / 256, 256>>>(idx, tok_emb, x);

    for (int l = 0; l < L_; l++) {
        // --- attention (routing-critical -> bf16x3) ---
        ln_kernel<<<NTOK, 256>>>(x, ln1_g + (size_t)l * C_, ln1_b + (size_t)l * C_, ln);
        mm_mma_kernel<128, 1><<<dim3(NTOK / 128, 3 * C_ / 128, 1), 256, SM_128_BF>>>(
            ln, qkv_w + (size_t)l * C_ * 3 * C_, qkv, nullptr,
            NTOK, 3 * C_, C_, 0, 0, 0, 0, 0, 3);
        rope_kernel<<<(NTOK * H_ * (HD_ / 2) + 255) / 256, 256>>>(qkv);
        flash_attn_kernel<<<dim3(T_ / 64, B_ * H_), 256, FA_SMEM>>>(qkv, attn);
        mm_mma_kernel<128, 1><<<dim3(NTOK / 128, C_ / 128, 1), 256, SM_128_BF>>>(
            attn, proj_w + (size_t)l * C_ * C_, x, nullptr,
            NTOK, C_, C_, 0, 0, 0, 0, 1, 3);  // += residual

        // --- MoE ---
        ln_kernel<<<NTOK, 256>>>(x, ln2_g + (size_t)l * C_, ln2_b + (size_t)l * C_, ln);
        gate_kernel<<<NTOK, 256>>>(ln, gate_w + (size_t)l * C_ * E_, gates, top);
        route_kernel<<<1, 32>>>(top, slot);
        scatter_kernel<<<NTOK, 256>>>(ln, top, slot, buf);
        if (l < L_ - 1) {
            // feeds next layer's routing -> bf16x3
            mm_mma_kernel<64, 1><<<dim3(CAP / 64, FF_ / 128, E_), 256, SM_64_BF>>>(
                buf, w1 + (size_t)l * E_ * C_ * FF_, hbuf, b1 + (size_t)l * E_ * FF_,
                CAP, FF_, C_, (long)CAP * C_, (long)C_ * FF_, (long)CAP * FF_, (long)FF_, 2, 3);
            mm_mma_kernel<64, 1><<<dim3(CAP / 64, C_ / 128, E_), 256, SM_64_BF>>>(
                hbuf, w2 + (size_t)l * E_ * FF_ * C_, ybuf, b2 + (size_t)l * E_ * C_,
                CAP, C_, FF_, (long)CAP * FF_, (long)FF_ * C_, (long)CAP * C_, (long)C_, 3, 3);
        } else {
            // only smooth ops downstream -> fp16 1-pass (same mantissa as tf32, half instr)
            mm_mma_kernel<64, 2><<<dim3(CAP / 64, FF_ / 128, E_), 256, SM_64_HF>>>(
                buf, w1 + (size_t)l * E_ * C_ * FF_, hbuf, b1 + (size_t)l * E_ * FF_,
                CAP, FF_, C_, (long)CAP * C_, (long)C_ * FF_, (long)CAP * FF_, (long)FF_, 2, 1);
            mm_mma_kernel<64, 2><<<dim3(CAP / 64, C_ / 128, E_), 256, SM_64_HF>>>(
                hbuf, w2 + (size_t)l * E_ * FF_ * C_, ybuf, b2 + (size_t)l * E_ * C_,
                CAP, C_, FF_, (long)CAP * FF_, (long)FF_ * C_, (long)CAP * C_, (long)C_, 3, 1);
        }
        combine_kernel<<<NTOK, 256>>>(ybuf, gates, top, slot, x);
    }

    ln_kernel<<<NTOK, 256>>>(x, lnf_g, lnf_b, ln);
    mm_mma_kernel<128, 2><<<dim3(NTOK / 128, V_ / 128, 1), 256, SM_128_HF>>>(
        ln, lm_head, out, nullptr, NTOK, V_, C_, 0, 0, 0, 0, 0, 1);
}

// round 12
// speedup vs baseline: 3.1359x; 1.1149x over previous
#include <cuda_runtime.h>
#include <cuda_bf16.h>
#include <cuda_fp16.h>
#include <math.h>
#include <stdint.h>

#define B_   2
#define T_   1024
#define C_   1024
#define H_   16
#define HD_  64
#define L_   2
#define E_   8
#define FF_  4096
#define V_   32000
#define NTOK (B_ * T_)
#define CAP  320   // ceil(1.25 * 2048 / 8); 320 = 5 * 64 -> exact 64-row tiling

// ---------------- scratch (static device globals; no allocations) ----------------
__device__ float g_x[NTOK * C_];
__device__ float g_ln[NTOK * C_];
__device__ float g_qkv[NTOK * 3 * C_];
__device__ float g_attn[NTOK * C_];
__device__ float g_gates[NTOK * E_];
__device__ int   g_top[NTOK * 2];
__device__ int   g_slot[NTOK * 2];
__device__ float g_buf [E_ * CAP * C_];
__device__ float g_hbuf[E_ * CAP * FF_];
__device__ float g_ybuf[E_ * CAP * C_];

// ---------------- helpers ----------------
__device__ __forceinline__ float warp_sum(float v) {
#pragma unroll
    for (int o = 16; o; o >>= 1) v += __shfl_xor_sync(0xffffffffu, v, o);
    return v;
}
__device__ __forceinline__ float gelu_exact(float v) {
    return 0.5f * v * (1.0f + erff(v * 0.70710678118654752f));
}
__device__ __forceinline__ float to_tf32(float v) {
    float o; asm("cvt.rna.tf32.f32 %0, %1;" : "=f"(o) : "f"(v)); return o;
}
__device__ __forceinline__ float bf_hi(float v) {
    return __bfloat162float(__float2bfloat16(v));
}
__device__ __forceinline__ uint32_t pack_bf2(float a, float b) {
    uint32_t r;
    asm("cvt.rn.bf16x2.f32 %0, %1, %2;" : "=r"(r) : "f"(b), "f"(a));
    return r;
}
__device__ __forceinline__ uint32_t pack_f16(float a, float b) {
    uint32_t r;
    asm("cvt.rn.f16x2.f32 %0, %1, %2;" : "=r"(r) : "f"(b), "f"(a));
    return r;
}
__device__ __forceinline__ void split_pack(float x0, float x1, uint32_t& hi, uint32_t& lo) {
    float h0 = bf_hi(x0), h1 = bf_hi(x1);
    hi = pack_bf2(h0, h1);
    lo = pack_bf2(x0 - h0, x1 - h1);
}

#define MMA_TF32(accp, a0, a1, a2, a3, b0, b1)                                  \
    asm volatile(                                                               \
        "mma.sync.aligned.m16n8k8.row.col.f32.tf32.tf32.f32 "                   \
        "{%0,%1,%2,%3}, {%4,%5,%6,%7}, {%8,%9}, {%0,%1,%2,%3};"                 \
        : "+f"((accp)[0]), "+f"((accp)[1]), "+f"((accp)[2]), "+f"((accp)[3])    \
        : "r"(a0), "r"(a1), "r"(a2), "r"(a3), "r"(b0), "r"(b1))

#define MMA_BF16(accp, a0, a1, a2, a3, b0, b1)                                  \
    asm volatile(                                                               \
        "mma.sync.aligned.m16n8k16.row.col.f32.bf16.bf16.f32 "                  \
        "{%0,%1,%2,%3}, {%4,%5,%6,%7}, {%8,%9}, {%0,%1,%2,%3};"                 \
        : "+f"((accp)[0]), "+f"((accp)[1]), "+f"((accp)[2]), "+f"((accp)[3])    \
        : "r"(a0), "r"(a1), "r"(a2), "r"(a3), "r"(b0), "r"(b1))

#define MMA_F16(accp, a0, a1, a2, a3, b0, b1)                                   \
    asm volatile(                                                               \
        "mma.sync.aligned.m16n8k16.row.col.f32.f16.f16.f32 "                    \
        "{%0,%1,%2,%3}, {%4,%5,%6,%7}, {%8,%9}, {%0,%1,%2,%3};"                 \
        : "+f"((accp)[0]), "+f"((accp)[1]), "+f"((accp)[2]), "+f"((accp)[3])    \
        : "r"(a0), "r"(a1), "r"(a2), "r"(a3), "r"(b0), "r"(b1))

// ======== tensor-core GEMM, templated on M-tile and numeric MODE ========
// MODE 0: tf32 (npass 1|3)  MODE 1: bf16x3 (routing-critical)  MODE 2: fp16 1-pass
template<int MT, int MODE>
__global__ void __launch_bounds__(256, MT == 64 ? 2 : 1)
mm_mma_kernel(const float* __restrict__ A, const float* __restrict__ B,
              float* __restrict__ C, const float* __restrict__ bias,
              int Mv, int N, int K,
              long sA, long sB, long sC, long sBias, int ep, int npass)
{
    constexpr int LDA = (MODE == 0) ? 36 : 40;
    constexpr int LDB = (MODE == 0) ? 136 : 132;
    constexpr int MTW  = MT / 32;
    constexpr int AIT  = MT / 32;
    constexpr int ABUF = MT * LDA;
    constexpr int BUFSZ = ABUF + 32 * LDB;
    extern __shared__ float sm[];
    int tid = threadIdx.x, lane = tid & 31, wid = tid >> 5;
    int wm = wid & 1, wn = wid >> 1;
    int r_lo = lane >> 2, c_lo = lane & 3;
    int z = blockIdx.z;
    A += (long)z * sA; B += (long)z * sB; C += (long)z * sC;
    const float* bp = bias ? bias + (long)z * sBias : nullptr;
    int m0 = blockIdx.x * MT, n0 = blockIdx.y * 128;

    float acc[MTW][4][4];
#pragma unroll
    for (int i = 0; i < MTW; i++)
#pragma unroll
        for (int j = 0; j < 4; j++)
#pragma unroll
            for (int k = 0; k < 4; k++) acc[i][j][k] = 0.f;

    float4 pa[AIT], pb[4];

    auto prefetch = [&](int i) {
        int k0 = i << 5;
#pragma unroll
        for (int it = 0; it < AIT; it++) {
            int idx = tid + it * 256;
            int m = idx >> 3, f4 = idx & 7;
            pa[it] = *(const float4*)(A + (size_t)(m0 + m) * K + k0 + f4 * 4);
        }
#pragma unroll
        for (int it = 0; it < 4; it++) {
            int idx = tid + it * 256;
            int k = idx >> 5, f4 = idx & 31;
            pb[it] = *(const float4*)(B + (size_t)(k0 + k) * N + n0 + f4 * 4);
        }
    };
    auto cstore = [&](int s) {
        float* smA = sm + s * BUFSZ;
        float* smB = smA + ABUF;
#pragma unroll
        for (int it = 0; it < AIT; it++) {
            int idx = tid + it * 256;
            int m = idx >> 3, f4 = idx & 7;
            *(float4*)(smA + m * LDA + f4 * 4) = pa[it];
        }
#pragma unroll
        for (int it = 0; it < 4; it++) {
            int idx = tid + it * 256;
            int k = idx >> 5, f4 = idx & 31;
            *(float4*)(smB + k * LDB + f4 * 4) = pb[it];
        }
    };

    int nch = K >> 5;
    prefetch(0);
    cstore(0);
    __syncthreads();
    for (int i = 0; i < nch; i++) {
        if (i + 1 < nch) prefetch(i + 1);
        {
            float* smA = sm + (i & 1) * BUFSZ;
            float* smB = smA + ABUF;
            if constexpr (MODE == 1) {
#pragma unroll
                for (int ks = 0; ks < 2; ks++) {
                    int kb = ks * 16 + 2 * c_lo;
                    uint32_t ah[MTW][4], al[MTW][4], bh[4][2], bl[4][2];
#pragma unroll
                    for (int mt = 0; mt < MTW; mt++) {
                        const float* ab = smA + (wm * (MT / 2) + mt * 16 + r_lo) * LDA + kb;
                        float2 p0 = *(const float2*)ab;
                        float2 p1 = *(const float2*)(ab + 8 * LDA);
                        float2 p2 = *(const float2*)(ab + 8);
                        float2 p3 = *(const float2*)(ab + 8 * LDA + 8);
                        split_pack(p0.x, p0.y, ah[mt][0], al[mt][0]);
                        split_pack(p1.x, p1.y, ah[mt][1], al[mt][1]);
                        split_pack(p2.x, p2.y, ah[mt][2], al[mt][2]);
                        split_pack(p3.x, p3.y, ah[mt][3], al[mt][3]);
                    }
#pragma unroll
                    for (int nt = 0; nt < 4; nt++) {
                        const float* bb = smB + kb * LDB + wn * 32 + nt * 8 + r_lo;
                        split_pack(bb[0],       bb[LDB],     bh[nt][0], bl[nt][0]);
                        split_pack(bb[8 * LDB], bb[9 * LDB], bh[nt][1], bl[nt][1]);
                    }
#pragma unroll
                    for (int mt = 0; mt < MTW; mt++)
#pragma unroll
                        for (int nt = 0; nt < 4; nt++) {
                            MMA_BF16(acc[mt][nt], ah[mt][0], ah[mt][1], ah[mt][2], ah[mt][3],
                                     bh[nt][0], bh[nt][1]);
                            MMA_BF16(acc[mt][nt], ah[mt][0], ah[mt][1], ah[mt][2], ah[mt][3],
                                     bl[nt][0], bl[nt][1]);
                            MMA_BF16(acc[mt][nt], al[mt][0], al[mt][1], al[mt][2], al[mt][3],
                                     bh[nt][0], bh[nt][1]);
                        }
                }
            } else if constexpr (MODE == 2) {
#pragma unroll
                for (int ks = 0; ks < 2; ks++) {
                    int kb = ks * 16 + 2 * c_lo;
                    uint32_t ah[MTW][4], bh[4][2];
#pragma unroll
                    for (int mt = 0; mt < MTW; mt++) {
                        const float* ab = smA + (wm * (MT / 2) + mt * 16 + r_lo) * LDA + kb;
                        float2 p0 = *(const float2*)ab;
                        float2 p1 = *(const float2*)(ab + 8 * LDA);
                        float2 p2 = *(const float2*)(ab + 8);
                        float2 p3 = *(const float2*)(ab + 8 * LDA + 8);
                        ah[mt][0] = pack_f16(p0.x, p0.y);
                        ah[mt][1] = pack_f16(p1.x, p1.y);
                        ah[mt][2] = pack_f16(p2.x, p2.y);
                        ah[mt][3] = pack_f16(p3.x, p3.y);
                    }
#pragma unroll
                    for (int nt = 0; nt < 4; nt++) {
                        const float* bb = smB + kb * LDB + wn * 32 + nt * 8 + r_lo;
                        bh[nt][0] = pack_f16(bb[0], bb[LDB]);
                        bh[nt][1] = pack_f16(bb[8 * LDB], bb[9 * LDB]);
                    }
#pragma unroll
                    for (int mt = 0; mt < MTW; mt++)
#pragma unroll
                        for (int nt = 0; nt < 4; nt++)
                            MMA_F16(acc[mt][nt], ah[mt][0], ah[mt][1], ah[mt][2], ah[mt][3],
                                    bh[nt][0], bh[nt][1]);
                }
            } else {
#pragma unroll
                for (int ks = 0; ks < 4; ks++) {
                    float ar[MTW][4], br[4][2];
                    uint32_t ah[MTW][4], bh[4][2];
#pragma unroll
                    for (int mt = 0; mt < MTW; mt++) {
                        const float* ab = smA + (wm * (MT / 2) + mt * 16 + r_lo) * LDA + ks * 8 + c_lo;
                        ar[mt][0] = ab[0];
                        ar[mt][1] = ab[8 * LDA];
                        ar[mt][2] = ab[4];
                        ar[mt][3] = ab[8 * LDA + 4];
#pragma unroll
                        for (int q = 0; q < 4; q++) ah[mt][q] = __float_as_uint(to_tf32(ar[mt][q]));
                    }
#pragma unroll
                    for (int nt = 0; nt < 4; nt++) {
                        const float* bb = smB + (ks * 8 + c_lo) * LDB + wn * 32 + nt * 8 + r_lo;
                        br[nt][0] = bb[0];
                        br[nt][1] = bb[4 * LDB];
                        bh[nt][0] = __float_as_uint(to_tf32(br[nt][0]));
                        bh[nt][1] = __float_as_uint(to_tf32(br[nt][1]));
                    }
#pragma unroll
                    for (int mt = 0; mt < MTW; mt++)
#pragma unroll
                        for (int nt = 0; nt < 4; nt++)
                            MMA_TF32(acc[mt][nt], ah[mt][0], ah[mt][1], ah[mt][2], ah[mt][3],
                                     bh[nt][0], bh[nt][1]);
                    if (npass == 3) {
#pragma unroll
                        for (int nt = 0; nt < 4; nt++) {
                            br[nt][0] = to_tf32(br[nt][0] - __uint_as_float(bh[nt][0]));
                            br[nt][1] = to_tf32(br[nt][1] - __uint_as_float(bh[nt][1]));
                        }
#pragma unroll
                        for (int mt = 0; mt < MTW; mt++)
#pragma unroll
                            for (int nt = 0; nt < 4; nt++)
                                MMA_TF32(acc[mt][nt], ah[mt][0], ah[mt][1], ah[mt][2], ah[mt][3],
                                         __float_as_uint(br[nt][0]), __float_as_uint(br[nt][1]));
#pragma unroll
                        for (int mt = 0; mt < MTW; mt++)
#pragma unroll
                            for (int q = 0; q < 4; q++)
                                ar[mt][q] = to_tf32(ar[mt][q] - __uint_as_float(ah[mt][q]));
#pragma unroll
                        for (int mt = 0; mt < MTW; mt++)
#pragma unroll
                            for (int nt = 0; nt < 4; nt++)
                                MMA_TF32(acc[mt][nt],
                                         __float_as_uint(ar[mt][0]), __float_as_uint(ar[mt][1]),
                                         __float_as_uint(ar[mt][2]), __float_as_uint(ar[mt][3]),
                                         bh[nt][0], bh[nt][1]);
                    }
                }
            }
        }
        __syncthreads();
        if (i + 1 < nch) {
            cstore((i + 1) & 1);
            __syncthreads();
        }
    }

    int rbase = m0 + wm * (MT / 2) + (lane >> 2);
    int cbase = n0 + wn * 32 + (lane & 3) * 2;
#pragma unroll
    for (int mt = 0; mt < MTW; mt++) {
#pragma unroll
        for (int half = 0; half < 2; half++) {
            int row = rbase + mt * 16 + half * 8;
            if (row >= Mv) continue;
#pragma unroll
            for (int nt = 0; nt < 4; nt++) {
                int col = cbase + nt * 8;
                float x0 = acc[mt][nt][half * 2 + 0];
                float x1 = acc[mt][nt][half * 2 + 1];
                if (ep == 2)      { x0 = gelu_exact(x0 + bp[col]); x1 = gelu_exact(x1 + bp[col + 1]); }
                else if (ep == 3) { x0 += bp[col]; x1 += bp[col + 1]; }
                float* cp = C + (size_t)row * N + col;
                if (ep == 1) { x0 += cp[0]; x1 += cp[1]; }
                float2 o; o.x = x0; o.y = x1;
                *(float2*)cp = o;
            }
        }
    }
}
#define MM_SMEM(MT, LDA, LDB) (2 * ((MT) * (LDA) + 32 * (LDB)) * 4)
#define SM_128_BF MM_SMEM(128, 40, 132)
#define SM_128_HF MM_SMEM(128, 40, 132)
#define SM_64_BF  MM_SMEM(64, 40, 132)
#define SM_64_HF  MM_SMEM(64, 40, 132)

// ---------------- embedding gather ----------------
__global__ void embed_kernel(const int* __restrict__ idx, const float* __restrict__ emb,
                             float* __restrict__ x) {
    int i = blockIdx.x * 256 + threadIdx.x;
    int n = i >> 10, c = i & 1023;
    x[i] = emb[(size_t)idx[n] * C_ + c];
}

// ---------------- layernorm ----------------
__global__ void ln_kernel(const float* __restrict__ x, const float* __restrict__ g,
                          const float* __restrict__ b, float* __restrict__ out) {
    int row = blockIdx.x;
    const float* xr = x + (size_t)row * C_;
    float s = 0.f, s2 = 0.f;
    for (int c = threadIdx.x; c < C_; c += 256) { float v = xr[c]; s += v; s2 += v * v; }
    __shared__ float sh1[8], sh2[8], shm[2];
    int lane = threadIdx.x & 31, w = threadIdx.x >> 5;
    s = warp_sum(s); s2 = warp_sum(s2);
    if (!lane) { sh1[w] = s; sh2[w] = s2; }
    __syncthreads();
    if (threadIdx.x == 0) {
        float S = 0.f, S2 = 0.f;
        for (int i = 0; i < 8; i++) { S += sh1[i]; S2 += sh2[i]; }
        float mean = S * (1.0f / C_);
        float var  = S2 * (1.0f / C_) - mean * mean;
        shm[0] = mean; shm[1] = rsqrtf(var + 1e-5f);
    }
    __syncthreads();
    float mean = shm[0], inv = shm[1];
    float* orow = out + (size_t)row * C_;
    for (int c = threadIdx.x; c < C_; c += 256)
        orow[c] = (xr[c] - mean) * inv * g[c] + b[c];
}

// ---------------- RoPE ----------------
__global__ void rope_kernel(float* __restrict__ qkv) {
    int i = blockIdx.x * 256 + threadIdx.x;
    if (i >= NTOK * H_ * (HD_ / 2)) return;
    int j = i & 31;
    int h = (i >> 5) & 15;
    int n = i >> 9;
    int t = n & (T_ - 1);
    float e = (float)(2 * j) / (float)HD_;
    float invf = 1.0f / powf(10000.0f, e);
    float ang = (float)t * invf;
    float s = sinf(ang), c = cosf(ang);
    float* base = qkv + (size_t)n * (3 * C_) + h * (3 * HD_);
    float q1 = base[j],      q2 = base[j + 32];
    base[j]      = q1 * c - q2 * s;
    base[j + 32] = q1 * s + q2 * c;
    float k1 = base[64 + j], k2 = base[64 + j + 32];
    base[64 + j]      = k1 * c - k2 * s;
    base[64 + j + 32] = k1 * s + k2 * c;
}

// ---------------- tensor-core flash attention (bf16x3 QK and PV) ----------------
// One CTA per (bh, 64-row q-block). 8 warps tiled 4(m) x 2(n) over 64x64 S/O.
// Online softmax in fragment registers; cross-warp row stats via smem.
#define FQ_P 72
#define FV_P 68
#define FP_P 72
#define FA_QS   0
#define FA_KS   (64 * FQ_P)
#define FA_VS   (FA_KS + 64 * FQ_P)
#define FA_PS   (FA_VS + 64 * FV_P)
#define FA_WMAX (FA_PS + 64 * FP_P)
#define FA_WSUM (FA_WMAX + 128)
#define FA_MROW (FA_WSUM + 128)
#define FA_LROW (FA_MROW + 64)
#define FA_AROW (FA_LROW + 64)
#define FA_SMEM ((FA_AROW + 64) * 4)

__global__ void __launch_bounds__(256, 1)
flash_attn_kernel(const float* __restrict__ qkv, float* __restrict__ out) {
    extern __shared__ float fs[];
    float* Qs = fs + FA_QS;     // [tok][72]
    float* Ks = fs + FA_KS;     // [tok][72]
    float* Vs = fs + FA_VS;     // [tok][68]
    float* Ps = fs + FA_PS;     // [row][72]
    float* Wmax = fs + FA_WMAX; // [2][64]
    float* Wsum = fs + FA_WSUM; // [2][64]
    float* Mrow = fs + FA_MROW;
    float* Lrow = fs + FA_LROW;
    float* Arow = fs + FA_AROW;
    int bh = blockIdx.y; int b = bh >> 4, h = bh & 15;
    int qb = (int)gridDim.x - 1 - (int)blockIdx.x;   // heavy blocks first
    int q0 = qb * 64;
    int tid = threadIdx.x, lane = tid & 31, wid = tid >> 5;
    int wm = wid & 3, wn = wid >> 2;
    int r_lo = lane >> 2, c_lo = lane & 3;
    int row0 = wm * 16 + r_lo;          // this thread's S/O rows: row0, row0+8

    const float* qbase = qkv + (size_t)(b * T_ + q0) * (3 * C_) + h * (3 * HD_);
#pragma unroll
    for (int r = 0; r < 4; r++) {
        int idx = tid + r * 256;
        int tok = idx >> 4, d4 = (idx & 15) * 4;
        *(float4*)(Qs + tok * FQ_P + d4) = *(const float4*)(qbase + (size_t)tok * (3 * C_) + d4);
    }
    if (tid < 64) { Mrow[tid] = -1e30f; Lrow[tid] = 0.f; }

    float oacc[4][4];
#pragma unroll
    for (int nt = 0; nt < 4; nt++)
#pragma unroll
        for (int q = 0; q < 4; q++) oacc[nt][q] = 0.f;

    for (int kb = 0; kb <= qb; kb++) {
        int k0 = kb * 64;
        __syncthreads();   // prior-iter Ks/Vs/Ps reads complete
        const float* kbase = qkv + (size_t)(b * T_ + k0) * (3 * C_) + h * (3 * HD_) + HD_;
        const float* vbase = kbase + HD_;
#pragma unroll
        for (int r = 0; r < 4; r++) {
            int idx = tid + r * 256;
            int tok = idx >> 4, d4 = (idx & 15) * 4;
            *(float4*)(Ks + tok * FQ_P + d4) = *(const float4*)(kbase + (size_t)tok * (3 * C_) + d4);
            *(float4*)(Vs + tok * FV_P + d4) = *(const float4*)(vbase + (size_t)tok * (3 * C_) + d4);
        }
        __syncthreads();

        // ---- S = Q @ K^T (bf16x3), warp tile 16x32 ----
        float sacc[4][4];
#pragma unroll
        for (int nt = 0; nt < 4; nt++)
#pragma unroll
            for (int q = 0; q < 4; q++) sacc[nt][q] = 0.f;
#pragma unroll
        for (int sl = 0; sl < 4; sl++) {
            int kb2 = sl * 16 + 2 * c_lo;
            uint32_t ah[4], al[4];
            const float* ab = Qs + (wm * 16 + r_lo) * FQ_P + kb2;
            split_pack(ab[0], ab[1], ah[0], al[0]);
            split_pack(ab[8 * FQ_P], ab[8 * FQ_P + 1], ah[1], al[1]);
            split_pack(ab[8], ab[9], ah[2], al[2]);
            split_pack(ab[8 * FQ_P + 8], ab[8 * FQ_P + 9], ah[3], al[3]);
#pragma unroll
            for (int nt = 0; nt < 4; nt++) {
                const float* bb = Ks + (wn * 32 + nt * 8 + r_lo) * FQ_P + kb2;
                uint32_t bh0, bl0, bh1, bl1;
                split_pack(bb[0], bb[1], bh0, bl0);
                split_pack(bb[8], bb[9], bh1, bl1);
                MMA_BF16(sacc[nt], ah[0], ah[1], ah[2], ah[3], bh0, bh1);
                MMA_BF16(sacc[nt], ah[0], ah[1], ah[2], ah[3], bl0, bl1);
                MMA_BF16(sacc[nt], al[0], al[1], al[2], al[3], bh0, bh1);
            }
        }
        // scale + causal mask (only needed on the diagonal block; k0==q0 there)
        bool diag = (kb == qb);
#pragma unroll
        for (int nt = 0; nt < 4; nt++)
#pragma unroll
            for (int q = 0; q < 4; q++) {
                int rloc = (q >= 2) ? row0 + 8 : row0;
                int cloc = wn * 32 + nt * 8 + 2 * c_lo + (q & 1);
                float v = sacc[nt][q] * 0.125f;
                if (diag && cloc > rloc) v = -1e30f;
                sacc[nt][q] = v;
            }
        // per-row max within warp (rows row0, row0+8; 8 cols per row per thread)
        float rm0 = -1e30f, rm1 = -1e30f;
#pragma unroll
        for (int nt = 0; nt < 4; nt++) {
            rm0 = fmaxf(rm0, fmaxf(sacc[nt][0], sacc[nt][1]));
            rm1 = fmaxf(rm1, fmaxf(sacc[nt][2], sacc[nt][3]));
        }
        rm0 = fmaxf(rm0, __shfl_xor_sync(0xffffffffu, rm0, 1));
        rm0 = fmaxf(rm0, __shfl_xor_sync(0xffffffffu, rm0, 2));
        rm1 = fmaxf(rm1, __shfl_xor_sync(0xffffffffu, rm1, 1));
        rm1 = fmaxf(rm1, __shfl_xor_sync(0xffffffffu, rm1, 2));
        if (c_lo == 0) {
            Wmax[wn * 64 + row0] = rm0;
            Wmax[wn * 64 + row0 + 8] = rm1;
        }
        __syncthreads();
        float mn0 = fmaxf(Mrow[row0],     fmaxf(Wmax[row0],     Wmax[64 + row0]));
        float mn1 = fmaxf(Mrow[row0 + 8], fmaxf(Wmax[row0 + 8], Wmax[64 + row0 + 8]));
        // P = exp(s - mnew); row sums; store P to Ps
        float rs0 = 0.f, rs1 = 0.f;
#pragma unroll
        for (int nt = 0; nt < 4; nt++) {
            float p0 = expf(sacc[nt][0] - mn0);
            float p1 = expf(sacc[nt][1] - mn0);
            float p2 = expf(sacc[nt][2] - mn1);
            float p3 = expf(sacc[nt][3] - mn1);
            rs0 += p0 + p1; rs1 += p2 + p3;
            int c = wn * 32 + nt * 8 + 2 * c_lo;
            float2 v0; v0.x = p0; v0.y = p1;
            float2 v1; v1.x = p2; v1.y = p3;
            *(float2*)(Ps + (wm * 16 + r_lo) * FP_P + c)       = v0;
            *(float2*)(Ps + (wm * 16 + r_lo + 8) * FP_P + c)   = v1;
        }
        rs0 += __shfl_xor_sync(0xffffffffu, rs0, 1);
        rs0 += __shfl_xor_sync(0xffffffffu, rs0, 2);
        rs1 += __shfl_xor_sync(0xffffffffu, rs1, 1);
        rs1 += __shfl_xor_sync(0xffffffffu, rs1, 2);
        if (c_lo == 0) {
            Wsum[wn * 64 + row0] = rs0;
            Wsum[wn * 64 + row0 + 8] = rs1;
        }
        __syncthreads();
        if (tid < 64) {
            int r = tid;
            float mold = Mrow[r];
            float mn = fmaxf(mold, fmaxf(Wmax[r], Wmax[64 + r]));
            float a = expf(mold - mn);
            Arow[r] = a;
            Lrow[r] = Lrow[r] * a + Wsum[r] + Wsum[64 + r];
            Mrow[r] = mn;
        }
        __syncthreads();
        // rescale O and accumulate O += P @ V (bf16x3)
        float a0 = Arow[row0], a1 = Arow[row0 + 8];
#pragma unroll
        for (int nt = 0; nt < 4; nt++) {
            oacc[nt][0] *= a0; oacc[nt][1] *= a0;
            oacc[nt][2] *= a1; oacc[nt][3] *= a1;
        }
#pragma unroll
        for (int sl = 0; sl < 4; sl++) {
            int kb2 = sl * 16 + 2 * c_lo;
            uint32_t ah[4], al[4];
            const float* ab = Ps + (wm * 16 + r_lo) * FP_P + kb2;
            split_pack(ab[0], ab[1], ah[0], al[0]);
            split_pack(ab[8 * FP_P], ab[8 * FP_P + 1], ah[1], al[1]);
            split_pack(ab[8], ab[9], ah[2], al[2]);
            split_pack(ab[8 * FP_P + 8], ab[8 * FP_P + 9], ah[3], al[3]);
#pragma unroll
            for (int nt = 0; nt < 4; nt++) {
                const float* bb = Vs + kb2 * FV_P + wn * 32 + nt * 8 + r_lo;
                uint32_t bh0, bl0, bh1, bl1;
                split_pack(bb[0],          bb[FV_P],     bh0, bl0);
                split_pack(bb[8 * FV_P],   bb[9 * FV_P], bh1, bl1);
                MMA_BF16(oacc[nt], ah[0], ah[1], ah[2], ah[3], bh0, bh1);
                MMA_BF16(oacc[nt], ah[0], ah[1], ah[2], ah[3], bl0, bl1);
                MMA_BF16(oacc[nt], al[0], al[1], al[2], al[3], bh0, bh1);
            }
        }
    }

    // write O / l
    float l0 = 1.0f / Lrow[row0], l1 = 1.0f / Lrow[row0 + 8];
#pragma unroll
    for (int nt = 0; nt < 4; nt++) {
        int col = wn * 32 + nt * 8 + 2 * c_lo;
        float2 v0; v0.x = oacc[nt][0] * l0; v0.y = oacc[nt][1] * l0;
        float2 v1; v1.x = oacc[nt][2] * l1; v1.y = oacc[nt][3] * l1;
        *(float2*)(out + (size_t)(b * T_ + q0 + row0) * C_ + h * HD_ + col)     = v0;
        *(float2*)(out + (size_t)(b * T_ + q0 + row0 + 8) * C_ + h * HD_ + col) = v1;
    }
}

// ---------------- gating ----------------
__global__ void gate_kernel(const float* __restrict__ x, const float* __restrict__ gw,
                            float* __restrict__ gates, int* __restrict__ top) {
    int n = blockIdx.x;
    int lane = threadIdx.x & 31, w = threadIdx.x >> 5;
    const float* xr = x + (size_t)n * C_;
    float acc = 0.f;
    for (int c = lane; c < C_; c += 32) acc += xr[c] * gw[(size_t)c * E_ + w];
    acc = warp_sum(acc);
    __shared__ float sl[E_];
    if (!lane) sl[w] = acc;
    __syncthreads();
    if (threadIdx.x == 0) {
        float p[E_];
        float m = sl[0];
        for (int e = 1; e < E_; e++) m = fmaxf(m, sl[e]);
        float s = 0.f;
        for (int e = 0; e < E_; e++) { p[e] = expf(sl[e] - m); s += p[e]; }
        float inv = 1.0f / s;
        for (int e = 0; e < E_; e++) { p[e] *= inv; gates[(size_t)n * E_ + e] = p[e]; }
        int i0 = 0;
        for (int e = 1; e < E_; e++) if (p[e] > p[i0]) i0 = e;
        int i1 = -1;
        for (int e = 0; e < E_; e++) {
            if (e == i0) continue;
            if (i1 < 0 || p[e] > p[i1]) i1 = e;
        }
        top[2 * n] = i0; top[2 * n + 1] = i1;
    }
}

// ---------------- routing: warp-parallel per-expert prefix (exact token order) ----
__global__ void route_kernel(const int* __restrict__ top, int* __restrict__ slot) {
    int e = threadIdx.x >> 5, lane = threadIdx.x & 31;   // 8 warps = 8 experts
    int cnt = 0;
    for (int base = 0; base < NTOK; base += 32) {
        int n = base + lane;
        int t0 = top[2 * n], t1 = top[2 * n + 1];
        bool m = (t0 == e) || (t1 == e);                 // top0 != top1 -> at most one
        unsigned ball = __ballot_sync(0xffffffffu, m);
        if (m) {
            int pos = cnt + __popc(ball & ((1u << lane) - 1));
            int s = (pos < CAP) ? pos : -1;
            if (t0 == e) slot[2 * n] = s; else slot[2 * n + 1] = s;
        }
        cnt += __popc(ball);
    }
}

// ---------------- scatter ----------------
__global__ void scatter_kernel(const float* __restrict__ ln, const int* __restrict__ top,
                               const int* __restrict__ slot, float* __restrict__ buf) {
    int n = blockIdx.x;
    const float4* src = (const float4*)(ln + (size_t)n * C_);
#pragma unroll
    for (int kk = 0; kk < 2; kk++) {
        int s = slot[2 * n + kk];
        if (s < 0) continue;
        int e = top[2 * n + kk];
        float4* dst = (float4*)(buf + ((size_t)e * CAP + s) * C_);
        for (int i = threadIdx.x; i < C_ / 4; i += 256) dst[i] = src[i];
    }
}

// ---------------- combine + residual ----------------
__global__ void combine_kernel(const float* __restrict__ y, const float* __restrict__ gates,
                               const int* __restrict__ top, const int* __restrict__ slot,
                               float* __restrict__ x) {
    int n = blockIdx.x;
    int e0 = top[2 * n], e1 = top[2 * n + 1];
    int s0 = slot[2 * n], s1 = slot[2 * n + 1];
    float w0 = (s0 >= 0) ? gates[(size_t)n * E_ + e0] : 0.f;
    float w1 = (s1 >= 0) ? gates[(size_t)n * E_ + e1] : 0.f;
    const float* y0 = y + ((size_t)e0 * CAP + (s0 >= 0 ? s0 : 0)) * C_;
    const float* y1 = y + ((size_t)e1 * CAP + (s1 >= 0 ? s1 : 0)) * C_;
    float* xr = x + (size_t)n * C_;
    for (int c = threadIdx.x; c < C_; c += 256)
        xr[c] += w0 * y0[c] + w1 * y1[c];
}

// ---------------- launch ----------------
extern "C" void kernel_launch(void* const* d_in, const int* in_sizes, int n_in,
                              void* d_out, int out_size) {
    const int*   idx     = (const int*)  d_in[0];
    const float* tok_emb = (const float*)d_in[1];
    const float* ln1_g   = (const float*)d_in[2];
    const float* ln1_b   = (const float*)d_in[3];
    const float* qkv_w   = (const float*)d_in[4];
    const float* proj_w  = (const float*)d_in[5];
    const float* ln2_g   = (const float*)d_in[6];
    const float* ln2_b   = (const float*)d_in[7];
    const float* gate_w  = (const float*)d_in[8];
    const float* w1      = (const float*)d_in[9];
    const float* b1      = (const float*)d_in[10];
    const float* w2      = (const float*)d_in[11];
    const float* b2      = (const float*)d_in[12];
    const float* lnf_g   = (const float*)d_in[13];
    const float* lnf_b   = (const float*)d_in[14];
    const float* lm_head = (const float*)d_in[15];
    float* out = (float*)d_out;

    float *x, *ln, *qkv, *attn, *gates, *buf, *hbuf, *ybuf;
    int *top, *slot;
    cudaGetSymbolAddress((void**)&x,     g_x);
    cudaGetSymbolAddress((void**)&ln,    g_ln);
    cudaGetSymbolAddress((void**)&qkv,   g_qkv);
    cudaGetSymbolAddress((void**)&attn,  g_attn);
    cudaGetSymbolAddress((void**)&gates, g_gates);
    cudaGetSymbolAddress((void**)&top,   g_top);
    cudaGetSymbolAddress((void**)&slot,  g_slot);
    cudaGetSymbolAddress((void**)&buf,   g_buf);
    cudaGetSymbolAddress((void**)&hbuf,  g_hbuf);
    cudaGetSymbolAddress((void**)&ybuf,  g_ybuf);

    cudaFuncSetAttribute((const void*)mm_mma_kernel<128, 1>, cudaFuncAttributeMaxDynamicSharedMemorySize, SM_128_BF);
    cudaFuncSetAttribute((const void*)mm_mma_kernel<128, 2>, cudaFuncAttributeMaxDynamicSharedMemorySize, SM_128_HF);
    cudaFuncSetAttribute((const void*)mm_mma_kernel<64, 1>,  cudaFuncAttributeMaxDynamicSharedMemorySize, SM_64_BF);
    cudaFuncSetAttribute((const void*)mm_mma_kernel<64, 2>,  cudaFuncAttributeMaxDynamicSharedMemorySize, SM_64_HF);
    cudaFuncSetAttribute((const void*)flash_attn_kernel, cudaFuncAttributeMaxDynamicSharedMemorySize, FA_SMEM);

    embed_kernel<<<NTOK * C_ / 256, 256>>>(idx, tok_emb, x);

    for (int l = 0; l < L_; l++) {
        // --- attention (routing-critical -> bf16x3) ---
        ln_kernel<<<NTOK, 256>>>(x, ln1_g + (size_t)l * C_, ln1_b + (size_t)l * C_, ln);
        mm_mma_kernel<128, 1><<<dim3(NTOK / 128, 3 * C_ / 128, 1), 256, SM_128_BF>>>(
            ln, qkv_w + (size_t)l * C_ * 3 * C_, qkv, nullptr,
            NTOK, 3 * C_, C_, 0, 0, 0, 0, 0, 3);
        rope_kernel<<<(NTOK * H_ * (HD_ / 2) + 255) / 256, 256>>>(qkv);
        flash_attn_kernel<<<dim3(T_ / 64, B_ * H_), 256, FA_SMEM>>>(qkv, attn);
        mm_mma_kernel<128, 1><<<dim3(NTOK / 128, C_ / 128, 1), 256, SM_128_BF>>>(
            attn, proj_w + (size_t)l * C_ * C_, x, nullptr,
            NTOK, C_, C_, 0, 0, 0, 0, 1, 3);  // += residual

        // --- MoE ---
        ln_kernel<<<NTOK, 256>>>(x, ln2_g + (size_t)l * C_, ln2_b + (size_t)l * C_, ln);
        gate_kernel<<<NTOK, 256>>>(ln, gate_w + (size_t)l * C_ * E_, gates, top);
        route_kernel<<<1, 256>>>(top, slot);
        scatter_kernel<<<NTOK, 256>>>(ln, top, slot, buf);
        if (l < L_ - 1) {
            mm_mma_kernel<64, 1><<<dim3(CAP / 64, FF_ / 128, E_), 256, SM_64_BF>>>(
                buf, w1 + (size_t)l * E_ * C_ * FF_, hbuf, b1 + (size_t)l * E_ * FF_,
                CAP, FF_, C_, (long)CAP * C_, (long)C_ * FF_, (long)CAP * FF_, (long)FF_, 2, 3);
            mm_mma_kernel<64, 1><<<dim3(CAP / 64, C_ / 128, E_), 256, SM_64_BF>>>(
                hbuf, w2 + (size_t)l * E_ * FF_ * C_, ybuf, b2 + (size_t)l * E_ * C_,
                CAP, C_, FF_, (long)CAP * FF_, (long)FF_ * C_, (long)CAP * C_, (long)C_, 3, 3);
        } else {
            mm_mma_kernel<64, 2><<<dim3(CAP / 64, FF_ / 128, E_), 256, SM_64_HF>>>(
                buf, w1 + (size_t)l * E_ * C_ * FF_, hbuf, b1 + (size_t)l * E_ * FF_,
                CAP, FF_, C_, (long)CAP * C_, (long)C_ * FF_, (long)CAP * FF_, (long)FF_, 2, 1);
            mm_mma_kernel<64, 2><<<dim3(CAP / 64, C_ / 128, E_), 256, SM_64_HF>>>(
                hbuf, w2 + (size_t)l * E_ * FF_ * C_, ybuf, b2 + (size_t)l * E_ * C_,
                CAP, C_, FF_, (long)CAP * FF_, (long)FF_ * C_, (long)CAP * C_, (long)C_, 3, 1);
        }
        combine_kernel<<<NTOK, 256>>>(ybuf, gates, top, slot, x);
    }

    ln_kernel<<<NTOK, 256>>>(x, lnf_g, lnf_b, ln);
    mm_mma_kernel<128, 2><<<dim3(NTOK / 128, V_ / 128, 1), 256, SM_128_HF>>>(
        ln, lm_head, out, nullptr, NTOK, V_, C_, 0, 0, 0, 0, 0, 1);
}